// round 1
// baseline (speedup 1.0000x reference)
#include <cuda_runtime.h>

// Problem constants
#define NB   64      // batch
#define SEQ  785     // tokens
#define CDIM 768     // channels
#define NH   12      // heads
#define HD   64      // head dim
#define NLOC 78      // num_local = int(0.1 * 784)

// ---------------- device scratch (static, no allocations) ----------------
__device__ float g_K[(size_t)NB * NH * SEQ * HD];     // [b][h][n][d]
__device__ float g_V[(size_t)NB * NH * SEQ * HD];     // [b][h][n][d]
__device__ float g_Q[(size_t)NB * NH * NLOC * HD];    // [b][h][j][d]
__device__ float g_att[(size_t)NB * NLOC * CDIM];     // [b*78][768]
__device__ int   g_idx[NB * NLOC];                    // gathered token index (1..784)

// ---------------- top-k by exact rank (matches jax.lax.top_k ties) -------
__global__ __launch_bounds__(256) void topk_kernel(const float* __restrict__ roll)
{
    int b = blockIdx.x;
    __shared__ float v[SEQ - 1];  // 784
    const float* src = roll + (size_t)b * SEQ * SEQ + 1;  // row 0, cols 1..784
    for (int i = threadIdx.x; i < SEQ - 1; i += 256) v[i] = src[i];
    __syncthreads();
    for (int i = threadIdx.x; i < SEQ - 1; i += 256) {
        float vi = v[i];
        int rank = 0;
        for (int j = 0; j < SEQ - 1; j++) {
            float vj = v[j];
            rank += (vj > vi) || (vj == vi && j < i);
        }
        if (rank < NLOC) g_idx[b * NLOC + rank] = i + 1;
    }
}

// ---------------- fp32 tiled GEMM, 128x128x8, 8x8 micro-tiles -------------
// MODE 0: A = x direct;        C -> split into g_K / g_V   ([b][h][n][d])
// MODE 1: A = x gathered rows; C -> g_Q                    ([b][h][j][d])
// MODE 2: A = g_att direct;    C -> scatter rows of d_out via g_idx
template <int MODE>
__global__ __launch_bounds__(256) void gemm_kernel(
    const float* __restrict__ A, const float* __restrict__ B,
    const float* __restrict__ bias, float* __restrict__ C,
    int M, int N, int K)
{
    const int BM = 128, BN = 128, BK = 8;
    __shared__ float As[BK][BM + 4];   // transposed, padded
    __shared__ float Bs[BK][BN];

    int tid = threadIdx.x;
    int bc = blockIdx.x, br = blockIdx.y;

    const float* Ap = A;
    if (MODE == 2) Ap = (const float*)g_att;

    // A loader: 2 threads per row, float4 each
    int arow_l = tid >> 1;                        // 0..127
    int acol   = (tid & 1) * 4;                   // 0 or 4
    int arow_g = br * BM + arow_l;
    int am = arow_g < M ? arow_g : M - 1;         // clamp loads
    const float* Arow;
    if (MODE == 1) {
        int bb = am / NLOC;
        int srcrow = bb * SEQ + g_idx[am];
        Arow = Ap + (size_t)srcrow * K + acol;
    } else {
        Arow = Ap + (size_t)am * K + acol;
    }

    // B loader: 8 rows x 32 col-groups of float4
    int brow  = tid >> 5;                         // 0..7
    int bcol0 = (tid & 31) * 4;
    const float* Bptr = B + (size_t)brow * N + bc * BN + bcol0;

    float4 aReg = *(const float4*)(Arow);
    float4 bReg = *(const float4*)(Bptr);

    float acc[8][8];
#pragma unroll
    for (int i = 0; i < 8; i++)
#pragma unroll
        for (int j = 0; j < 8; j++) acc[i][j] = 0.f;

    int tr = tid >> 4, tc = tid & 15;
    int nk = K / BK;

    for (int kt = 0; kt < nk; kt++) {
        As[acol + 0][arow_l] = aReg.x;
        As[acol + 1][arow_l] = aReg.y;
        As[acol + 2][arow_l] = aReg.z;
        As[acol + 3][arow_l] = aReg.w;
        *(float4*)&Bs[brow][bcol0] = bReg;
        __syncthreads();
        if (kt + 1 < nk) {
            aReg = *(const float4*)(Arow + (kt + 1) * BK);
            bReg = *(const float4*)(Bptr + (size_t)(kt + 1) * BK * N);
        }
#pragma unroll
        for (int k = 0; k < BK; k++) {
            float a[8], bb[8];
            float4 t0 = *(const float4*)&As[k][tr * 8];
            float4 t1 = *(const float4*)&As[k][tr * 8 + 4];
            float4 t2 = *(const float4*)&Bs[k][tc * 8];
            float4 t3 = *(const float4*)&Bs[k][tc * 8 + 4];
            a[0] = t0.x; a[1] = t0.y; a[2] = t0.z; a[3] = t0.w;
            a[4] = t1.x; a[5] = t1.y; a[6] = t1.z; a[7] = t1.w;
            bb[0] = t2.x; bb[1] = t2.y; bb[2] = t2.z; bb[3] = t2.w;
            bb[4] = t3.x; bb[5] = t3.y; bb[6] = t3.z; bb[7] = t3.w;
#pragma unroll
            for (int i = 0; i < 8; i++)
#pragma unroll
                for (int j = 0; j < 8; j++) acc[i][j] += a[i] * bb[j];
        }
        __syncthreads();
    }

    // epilogue
#pragma unroll
    for (int i = 0; i < 8; i++) {
        int m = br * BM + tr * 8 + i;
        if (m >= M) continue;
        if (MODE == 0) {
            int bb = m / SEQ, nn = m % SEQ;
#pragma unroll
            for (int j = 0; j < 8; j++) {
                int n = bc * BN + tc * 8 + j;
                float val = acc[i][j] + bias[n];
                int nc = (n < CDIM) ? n : n - CDIM;
                int h = nc >> 6, d = nc & 63;
                float* dst = (n < CDIM) ? g_K : g_V;
                dst[(((size_t)bb * NH + h) * SEQ + nn) * HD + d] = val;
            }
        } else if (MODE == 1) {
            int bb = m / NLOC, jj = m % NLOC;
#pragma unroll
            for (int j = 0; j < 8; j++) {
                int n = bc * BN + tc * 8 + j;
                float val = acc[i][j] + bias[n];
                int h = n >> 6, d = n & 63;
                g_Q[(((size_t)bb * NH + h) * NLOC + jj) * HD + d] = val;
            }
        } else {
            int bb = m / NLOC;
            int row = bb * SEQ + g_idx[m];
#pragma unroll
            for (int j = 0; j < 8; j++) {
                int n = bc * BN + tc * 8 + j;
                C[(size_t)row * CDIM + n] = acc[i][j] + bias[n];
            }
        }
    }
}

// ---------------- fused flash attention per (b,h) -------------------------
// block = 256 threads; thread owns rows {t/16 + 16*i, i<5} x 4 d-cols
__global__ __launch_bounds__(256) void attn_kernel()
{
    int bh = blockIdx.x;
    int b = bh / NH, h = bh % NH;

    __shared__ float Qs[80][65];
    __shared__ float Ks[32][65];
    __shared__ float Vs[32][64];
    __shared__ float S[80][33];
    __shared__ float s_m[80], s_l[80], s_factor[80];

    int t = threadIdx.x;
    int rowbase = t >> 4, dgrp = t & 15;

    const float* qsrc = g_Q + (size_t)bh * NLOC * HD;
    const float* ksrc = g_K + (size_t)bh * SEQ * HD;
    const float* vsrc = g_V + (size_t)bh * SEQ * HD;

    for (int l = t; l < 80 * 64; l += 256) {
        int r = l >> 6, d = l & 63;
        Qs[r][d] = (r < NLOC) ? qsrc[r * HD + d] : 0.f;
    }
    if (t < 80) { s_m[t] = -1e30f; s_l[t] = 0.f; }

    float acc[5][4];
#pragma unroll
    for (int i = 0; i < 5; i++)
#pragma unroll
        for (int c = 0; c < 4; c++) acc[i][c] = 0.f;

    const float scale = 0.125f;  // 64^-0.5
    __syncthreads();

    for (int n0 = 0; n0 < SEQ; n0 += 32) {
        // load K/V tile (clamped rows; masked later)
        for (int l = t; l < 32 * 64; l += 256) {
            int rr = l >> 6, d = l & 63;
            int src = n0 + rr; if (src > SEQ - 1) src = SEQ - 1;
            Ks[rr][d] = ksrc[src * HD + d];
            Vs[rr][d] = vsrc[src * HD + d];
        }
        __syncthreads();

        // S = Q K^T * scale ; each thread: 5 rows x 2 key cols
        {
            int kk0 = dgrp * 2;
            float s0[5], s1[5];
#pragma unroll
            for (int i = 0; i < 5; i++) { s0[i] = 0.f; s1[i] = 0.f; }
#pragma unroll 8
            for (int d = 0; d < 64; d++) {
                float ka = Ks[kk0][d], kb = Ks[kk0 + 1][d];
#pragma unroll
                for (int i = 0; i < 5; i++) {
                    float q = Qs[rowbase + 16 * i][d];
                    s0[i] += q * ka;
                    s1[i] += q * kb;
                }
            }
#pragma unroll
            for (int i = 0; i < 5; i++) {
                int r = rowbase + 16 * i;
                S[r][kk0]     = (n0 + kk0     < SEQ) ? s0[i] * scale : -1e30f;
                S[r][kk0 + 1] = (n0 + kk0 + 1 < SEQ) ? s1[i] * scale : -1e30f;
            }
        }
        __syncthreads();

        // per-row running max + rescale factor
        if (t < 80) {
            float mo = s_m[t], mx = mo;
#pragma unroll 8
            for (int kk = 0; kk < 32; kk++) mx = fmaxf(mx, S[t][kk]);
            s_factor[t] = __expf(mo - mx);
            s_m[t] = mx;
        }
        __syncthreads();

        // P = exp(S - m), non-redundant
        for (int l = t; l < 80 * 32; l += 256) {
            int r = l >> 5, kk = l & 31;
            S[r][kk] = __expf(S[r][kk] - s_m[r]);
        }
        __syncthreads();

        // accumulate O += P V ; dgrp==0 updates l
#pragma unroll
        for (int i = 0; i < 5; i++) {
            int r = rowbase + 16 * i;
            float f = s_factor[r];
            float a0 = acc[i][0] * f, a1 = acc[i][1] * f;
            float a2 = acc[i][2] * f, a3 = acc[i][3] * f;
            float sum = 0.f;
#pragma unroll 8
            for (int kk = 0; kk < 32; kk++) {
                float p = S[r][kk];
                float4 vv = *(const float4*)&Vs[kk][dgrp * 4];
                a0 += p * vv.x; a1 += p * vv.y;
                a2 += p * vv.z; a3 += p * vv.w;
                sum += p;
            }
            acc[i][0] = a0; acc[i][1] = a1; acc[i][2] = a2; acc[i][3] = a3;
            if (dgrp == 0) s_l[r] = s_l[r] * f + sum;
        }
        __syncthreads();
    }

    // writeout into g_att [b*78][768] at head column block
    float* dst = g_att + ((size_t)b * NLOC) * CDIM + h * HD + dgrp * 4;
#pragma unroll
    for (int i = 0; i < 5; i++) {
        int r = rowbase + 16 * i;
        if (r < NLOC) {
            float inv = 1.f / s_l[r];
            dst[(size_t)r * CDIM + 0] = acc[i][0] * inv;
            dst[(size_t)r * CDIM + 1] = acc[i][1] * inv;
            dst[(size_t)r * CDIM + 2] = acc[i][2] * inv;
            dst[(size_t)r * CDIM + 3] = acc[i][3] * inv;
        }
    }
}

// ---------------- launch ---------------------------------------------------
extern "C" void kernel_launch(void* const* d_in, const int* in_sizes, int n_in,
                              void* d_out, int out_size)
{
    const float* x    = (const float*)d_in[0];
    const float* roll = (const float*)d_in[1];
    const float* Wq   = (const float*)d_in[2];
    const float* bq   = (const float*)d_in[3];
    const float* Wkv  = (const float*)d_in[4];
    const float* bkv  = (const float*)d_in[5];
    const float* Wp   = (const float*)d_in[6];
    const float* bp   = (const float*)d_in[7];
    float* out = (float*)d_out;

    size_t xbytes = (size_t)NB * SEQ * CDIM * sizeof(float);

    // pass-through copy (scattered rows overwritten at the end)
    cudaMemcpyAsync(out, x, xbytes, cudaMemcpyDeviceToDevice);

    // top-k indices per batch
    topk_kernel<<<NB, 256>>>(roll);

    // KV projection: [50240,768] @ [768,1536] -> g_K/g_V
    {
        int M = NB * SEQ, N = 2 * CDIM, K = CDIM;
        dim3 grid(N / 128, (M + 127) / 128);
        gemm_kernel<0><<<grid, 256>>>(x, Wkv, bkv, nullptr, M, N, K);
    }
    // Q projection (gathered rows): [4992,768] @ [768,768] -> g_Q
    {
        int M = NB * NLOC, N = CDIM, K = CDIM;
        dim3 grid(N / 128, (M + 127) / 128);
        gemm_kernel<1><<<grid, 256>>>(x, Wq, bq, nullptr, M, N, K);
    }
    // fused attention -> g_att
    attn_kernel<<<NB * NH, 256>>>();

    // output projection + scatter into out
    {
        int M = NB * NLOC, N = CDIM, K = CDIM;
        dim3 grid(N / 128, (M + 127) / 128);
        gemm_kernel<2><<<grid, 256>>>(nullptr, Wp, bp, out, M, N, K);
    }
}

// round 2
// speedup vs baseline: 1.0004x; 1.0004x over previous
#include <cuda_runtime.h>

// Problem constants
#define NB   64      // batch
#define SEQ  785     // tokens
#define CDIM 768     // channels
#define NH   12      // heads
#define HD   64      // head dim
#define NLOC 78      // num_local = int(0.1 * 784)

// ---------------- device scratch (static, no allocations) ----------------
__device__ float g_K[(size_t)NB * NH * SEQ * HD];     // [b][h][n][d]
__device__ float g_V[(size_t)NB * NH * SEQ * HD];     // [b][h][n][d]
__device__ float g_Q[(size_t)NB * NH * NLOC * HD];    // [b][h][j][d]
__device__ float g_att[(size_t)NB * NLOC * CDIM];     // [b*78][768]
__device__ int   g_idx[NB * NLOC];                    // gathered token index (1..784)

// ---------------- top-k by exact rank (matches jax.lax.top_k ties) -------
__global__ __launch_bounds__(256) void topk_kernel(const float* __restrict__ roll)
{
    int b = blockIdx.x;
    __shared__ float v[SEQ - 1];  // 784
    const float* src = roll + (size_t)b * SEQ * SEQ + 1;  // row 0, cols 1..784
    for (int i = threadIdx.x; i < SEQ - 1; i += 256) v[i] = src[i];
    __syncthreads();
    for (int i = threadIdx.x; i < SEQ - 1; i += 256) {
        float vi = v[i];
        int rank = 0;
        for (int j = 0; j < SEQ - 1; j++) {
            float vj = v[j];
            rank += (vj > vi) || (vj == vi && j < i);
        }
        if (rank < NLOC) g_idx[b * NLOC + rank] = i + 1;
    }
}

// ---------------- fp32 tiled GEMM, 128x128x8, 8x8 micro-tiles -------------
// MODE 0: A = x direct;        C -> split into g_K / g_V   ([b][h][n][d])
// MODE 1: A = x gathered rows; C -> g_Q                    ([b][h][j][d])
// MODE 2: A = g_att direct;    C -> scatter rows of d_out via g_idx
template <int MODE>
__global__ __launch_bounds__(256) void gemm_kernel(
    const float* __restrict__ A, const float* __restrict__ B,
    const float* __restrict__ bias, float* __restrict__ C,
    int M, int N, int K)
{
    const int BM = 128, BN = 128, BK = 8;
    __shared__ float As[BK][BM + 4];   // transposed, padded
    __shared__ float Bs[BK][BN];

    int tid = threadIdx.x;
    int bc = blockIdx.x, br = blockIdx.y;

    const float* Ap = A;
    if (MODE == 2) Ap = (const float*)g_att;

    // A loader: 2 threads per row, float4 each
    int arow_l = tid >> 1;                        // 0..127
    int acol   = (tid & 1) * 4;                   // 0 or 4
    int arow_g = br * BM + arow_l;
    int am = arow_g < M ? arow_g : M - 1;         // clamp loads
    const float* Arow;
    if (MODE == 1) {
        int bb = am / NLOC;
        int srcrow = bb * SEQ + g_idx[am];
        Arow = Ap + (size_t)srcrow * K + acol;
    } else {
        Arow = Ap + (size_t)am * K + acol;
    }

    // B loader: 8 rows x 32 col-groups of float4
    int brow  = tid >> 5;                         // 0..7
    int bcol0 = (tid & 31) * 4;
    const float* Bptr = B + (size_t)brow * N + bc * BN + bcol0;

    float4 aReg = *(const float4*)(Arow);
    float4 bReg = *(const float4*)(Bptr);

    float acc[8][8];
#pragma unroll
    for (int i = 0; i < 8; i++)
#pragma unroll
        for (int j = 0; j < 8; j++) acc[i][j] = 0.f;

    int tr = tid >> 4, tc = tid & 15;
    int nk = K / BK;

    for (int kt = 0; kt < nk; kt++) {
        As[acol + 0][arow_l] = aReg.x;
        As[acol + 1][arow_l] = aReg.y;
        As[acol + 2][arow_l] = aReg.z;
        As[acol + 3][arow_l] = aReg.w;
        *(float4*)&Bs[brow][bcol0] = bReg;
        __syncthreads();
        if (kt + 1 < nk) {
            aReg = *(const float4*)(Arow + (kt + 1) * BK);
            bReg = *(const float4*)(Bptr + (size_t)(kt + 1) * BK * N);
        }
#pragma unroll
        for (int k = 0; k < BK; k++) {
            float a[8], bb[8];
            float4 t0 = *(const float4*)&As[k][tr * 8];
            float4 t1 = *(const float4*)&As[k][tr * 8 + 4];
            float4 t2 = *(const float4*)&Bs[k][tc * 8];
            float4 t3 = *(const float4*)&Bs[k][tc * 8 + 4];
            a[0] = t0.x; a[1] = t0.y; a[2] = t0.z; a[3] = t0.w;
            a[4] = t1.x; a[5] = t1.y; a[6] = t1.z; a[7] = t1.w;
            bb[0] = t2.x; bb[1] = t2.y; bb[2] = t2.z; bb[3] = t2.w;
            bb[4] = t3.x; bb[5] = t3.y; bb[6] = t3.z; bb[7] = t3.w;
#pragma unroll
            for (int i = 0; i < 8; i++)
#pragma unroll
                for (int j = 0; j < 8; j++) acc[i][j] += a[i] * bb[j];
        }
        __syncthreads();
    }

    // epilogue
#pragma unroll
    for (int i = 0; i < 8; i++) {
        int m = br * BM + tr * 8 + i;
        if (m >= M) continue;
        if (MODE == 0) {
            int bb = m / SEQ, nn = m % SEQ;
#pragma unroll
            for (int j = 0; j < 8; j++) {
                int n = bc * BN + tc * 8 + j;
                float val = acc[i][j] + bias[n];
                int nc = (n < CDIM) ? n : n - CDIM;
                int h = nc >> 6, d = nc & 63;
                float* dst = (n < CDIM) ? g_K : g_V;
                dst[(((size_t)bb * NH + h) * SEQ + nn) * HD + d] = val;
            }
        } else if (MODE == 1) {
            int bb = m / NLOC, jj = m % NLOC;
#pragma unroll
            for (int j = 0; j < 8; j++) {
                int n = bc * BN + tc * 8 + j;
                float val = acc[i][j] + bias[n];
                int h = n >> 6, d = n & 63;
                g_Q[(((size_t)bb * NH + h) * NLOC + jj) * HD + d] = val;
            }
        } else {
            int bb = m / NLOC;
            int row = bb * SEQ + g_idx[m];
#pragma unroll
            for (int j = 0; j < 8; j++) {
                int n = bc * BN + tc * 8 + j;
                C[(size_t)row * CDIM + n] = acc[i][j] + bias[n];
            }
        }
    }
}

// ---------------- fused flash attention per (b,h) -------------------------
// block = 256 threads; thread owns rows {t/16 + 16*i, i<5} x 4 d-cols
__global__ __launch_bounds__(256) void attn_kernel()
{
    int bh = blockIdx.x;
    int b = bh / NH, h = bh % NH;

    __shared__ float Qs[80][65];
    __shared__ float Ks[32][65];
    __shared__ float Vs[32][64];
    __shared__ float S[80][33];
    __shared__ float s_m[80], s_l[80], s_factor[80];

    int t = threadIdx.x;
    int rowbase = t >> 4, dgrp = t & 15;

    const float* qsrc = g_Q + (size_t)bh * NLOC * HD;
    const float* ksrc = g_K + (size_t)bh * SEQ * HD;
    const float* vsrc = g_V + (size_t)bh * SEQ * HD;

    for (int l = t; l < 80 * 64; l += 256) {
        int r = l >> 6, d = l & 63;
        Qs[r][d] = (r < NLOC) ? qsrc[r * HD + d] : 0.f;
    }
    if (t < 80) { s_m[t] = -1e30f; s_l[t] = 0.f; }

    float acc[5][4];
#pragma unroll
    for (int i = 0; i < 5; i++)
#pragma unroll
        for (int c = 0; c < 4; c++) acc[i][c] = 0.f;

    const float scale = 0.125f;  // 64^-0.5
    __syncthreads();

    for (int n0 = 0; n0 < SEQ; n0 += 32) {
        // load K/V tile (clamped rows; masked later)
        for (int l = t; l < 32 * 64; l += 256) {
            int rr = l >> 6, d = l & 63;
            int src = n0 + rr; if (src > SEQ - 1) src = SEQ - 1;
            Ks[rr][d] = ksrc[src * HD + d];
            Vs[rr][d] = vsrc[src * HD + d];
        }
        __syncthreads();

        // S = Q K^T * scale ; each thread: 5 rows x 2 key cols
        {
            int kk0 = dgrp * 2;
            float s0[5], s1[5];
#pragma unroll
            for (int i = 0; i < 5; i++) { s0[i] = 0.f; s1[i] = 0.f; }
#pragma unroll 8
            for (int d = 0; d < 64; d++) {
                float ka = Ks[kk0][d], kb = Ks[kk0 + 1][d];
#pragma unroll
                for (int i = 0; i < 5; i++) {
                    float q = Qs[rowbase + 16 * i][d];
                    s0[i] += q * ka;
                    s1[i] += q * kb;
                }
            }
#pragma unroll
            for (int i = 0; i < 5; i++) {
                int r = rowbase + 16 * i;
                S[r][kk0]     = (n0 + kk0     < SEQ) ? s0[i] * scale : -1e30f;
                S[r][kk0 + 1] = (n0 + kk0 + 1 < SEQ) ? s1[i] * scale : -1e30f;
            }
        }
        __syncthreads();

        // per-row running max + rescale factor
        if (t < 80) {
            float mo = s_m[t], mx = mo;
#pragma unroll 8
            for (int kk = 0; kk < 32; kk++) mx = fmaxf(mx, S[t][kk]);
            s_factor[t] = __expf(mo - mx);
            s_m[t] = mx;
        }
        __syncthreads();

        // P = exp(S - m), non-redundant
        for (int l = t; l < 80 * 32; l += 256) {
            int r = l >> 5, kk = l & 31;
            S[r][kk] = __expf(S[r][kk] - s_m[r]);
        }
        __syncthreads();

        // accumulate O += P V ; dgrp==0 updates l
#pragma unroll
        for (int i = 0; i < 5; i++) {
            int r = rowbase + 16 * i;
            float f = s_factor[r];
            float a0 = acc[i][0] * f, a1 = acc[i][1] * f;
            float a2 = acc[i][2] * f, a3 = acc[i][3] * f;
            float sum = 0.f;
#pragma unroll 8
            for (int kk = 0; kk < 32; kk++) {
                float p = S[r][kk];
                float4 vv = *(const float4*)&Vs[kk][dgrp * 4];
                a0 += p * vv.x; a1 += p * vv.y;
                a2 += p * vv.z; a3 += p * vv.w;
                sum += p;
            }
            acc[i][0] = a0; acc[i][1] = a1; acc[i][2] = a2; acc[i][3] = a3;
            if (dgrp == 0) s_l[r] = s_l[r] * f + sum;
        }
        __syncthreads();
    }

    // writeout into g_att [b*78][768] at head column block
    float* dst = g_att + ((size_t)b * NLOC) * CDIM + h * HD + dgrp * 4;
#pragma unroll
    for (int i = 0; i < 5; i++) {
        int r = rowbase + 16 * i;
        if (r < NLOC) {
            float inv = 1.f / s_l[r];
            dst[(size_t)r * CDIM + 0] = acc[i][0] * inv;
            dst[(size_t)r * CDIM + 1] = acc[i][1] * inv;
            dst[(size_t)r * CDIM + 2] = acc[i][2] * inv;
            dst[(size_t)r * CDIM + 3] = acc[i][3] * inv;
        }
    }
}

// ---------------- launch ---------------------------------------------------
extern "C" void kernel_launch(void* const* d_in, const int* in_sizes, int n_in,
                              void* d_out, int out_size)
{
    const float* x    = (const float*)d_in[0];
    const float* roll = (const float*)d_in[1];
    const float* Wq   = (const float*)d_in[2];
    const float* bq   = (const float*)d_in[3];
    const float* Wkv  = (const float*)d_in[4];
    const float* bkv  = (const float*)d_in[5];
    const float* Wp   = (const float*)d_in[6];
    const float* bp   = (const float*)d_in[7];
    float* out = (float*)d_out;

    size_t xbytes = (size_t)NB * SEQ * CDIM * sizeof(float);

    // pass-through copy (scattered rows overwritten at the end)
    cudaMemcpyAsync(out, x, xbytes, cudaMemcpyDeviceToDevice);

    // top-k indices per batch
    topk_kernel<<<NB, 256>>>(roll);

    // KV projection: [50240,768] @ [768,1536] -> g_K/g_V
    {
        int M = NB * SEQ, N = 2 * CDIM, K = CDIM;
        dim3 grid(N / 128, (M + 127) / 128);
        gemm_kernel<0><<<grid, 256>>>(x, Wkv, bkv, nullptr, M, N, K);
    }
    // Q projection (gathered rows): [4992,768] @ [768,768] -> g_Q
    {
        int M = NB * NLOC, N = CDIM, K = CDIM;
        dim3 grid(N / 128, (M + 127) / 128);
        gemm_kernel<1><<<grid, 256>>>(x, Wq, bq, nullptr, M, N, K);
    }
    // fused attention -> g_att
    attn_kernel<<<NB * NH, 256>>>();

    // output projection + scatter into out
    {
        int M = NB * NLOC, N = CDIM, K = CDIM;
        dim3 grid(N / 128, (M + 127) / 128);
        gemm_kernel<2><<<grid, 256>>>(nullptr, Wp, bp, out, M, N, K);
    }
}

// round 3
// speedup vs baseline: 1.8588x; 1.8580x over previous
#include <cuda_runtime.h>
#include <cstdint>

// Problem constants
#define NB   64      // batch
#define SEQ  785     // tokens
#define CDIM 768     // channels
#define NH   12      // heads
#define HD   64      // head dim
#define NLOC 78      // num_local = int(0.1 * 784)

// ---------------- device scratch (static, no allocations) ----------------
__device__ float g_K[(size_t)NB * NH * SEQ * HD];     // [b][h][n][d]
__device__ float g_V[(size_t)NB * NH * SEQ * HD];     // [b][h][n][d]
__device__ float g_Q[(size_t)NB * NH * NLOC * HD];    // [b][h][j][d]
__device__ float g_att[(size_t)NB * NLOC * CDIM];     // [b*78][768]
__device__ int   g_idx[NB * NLOC];                    // gathered token index (1..784)

// ---------------- top-k by exact rank (matches jax.lax.top_k ties) -------
__global__ __launch_bounds__(256) void topk_kernel(const float* __restrict__ roll)
{
    int b = blockIdx.x;
    __shared__ float v[SEQ - 1];  // 784
    const float* src = roll + (size_t)b * SEQ * SEQ + 1;  // row 0, cols 1..784
    for (int i = threadIdx.x; i < SEQ - 1; i += 256) v[i] = src[i];
    __syncthreads();
    for (int i = threadIdx.x; i < SEQ - 1; i += 256) {
        float vi = v[i];
        int rank = 0;
        for (int j = 0; j < SEQ - 1; j++) {
            float vj = v[j];
            rank += (vj > vi) || (vj == vi && j < i);
        }
        if (rank < NLOC) g_idx[b * NLOC + rank] = i + 1;
    }
}

// ---------------- TF32 helpers --------------------------------------------
__device__ __forceinline__ uint32_t f2tf32(float f) {
    uint32_t u;
    asm("cvt.rna.tf32.f32 %0, %1;" : "=r"(u) : "f"(f));
    return u;
}
__device__ __forceinline__ void st_tf32_4(float* dst, float4 v) {
    float4 o;
    o.x = __uint_as_float(f2tf32(v.x));
    o.y = __uint_as_float(f2tf32(v.y));
    o.z = __uint_as_float(f2tf32(v.z));
    o.w = __uint_as_float(f2tf32(v.w));
    *(float4*)dst = o;
}

#define MMA_TF32(C, A, B)                                                     \
    asm volatile(                                                             \
        "mma.sync.aligned.m16n8k8.row.col.f32.tf32.tf32.f32 "                 \
        "{%0,%1,%2,%3}, {%4,%5,%6,%7}, {%8,%9}, {%0,%1,%2,%3};"               \
        : "+f"((C)[0]), "+f"((C)[1]), "+f"((C)[2]), "+f"((C)[3])              \
        : "r"((A)[0]), "r"((A)[1]), "r"((A)[2]), "r"((A)[3]),                 \
          "r"((B)[0]), "r"((B)[1]))

// ---------------- TF32 tensor-core GEMM, 128x128x16 -----------------------
// 8 warps in 2x4 grid; warp computes 64x32 via 4x4 m16n8k8 fragments.
// MODE 0: A = x direct;        C -> split into g_K / g_V   ([b][h][n][d])
// MODE 1: A = x gathered rows; C -> g_Q                    ([b][h][j][d])
// MODE 2: A = g_att direct;    C -> scatter rows of d_out via g_idx
template <int MODE>
__global__ __launch_bounds__(256) void gemm_tf32(
    const float* __restrict__ A, const float* __restrict__ B,
    const float* __restrict__ bias, float* __restrict__ C,
    int M, int N, int K)
{
    const int BM = 128, BN = 128, BK = 16;
    __shared__ float As[BM][BK + 4];    // pad -> 20 floats/row (bank-clean)
    __shared__ float Bs[BK][BN + 8];    // pad -> 136 floats/row (bank-clean)

    int tid = threadIdx.x;
    int wid = tid >> 5, lane = tid & 31;
    int warp_m = wid & 1, warp_n = wid >> 1;   // 2 x 4
    int g = lane >> 2, tig = lane & 3;

    int bc = blockIdx.x, br = blockIdx.y;

    const float* Ap = (MODE == 2) ? (const float*)g_att : A;

    // A loader: rows tid>>2 and +64, cols (tid&3)*4
    int ar  = tid >> 2;            // 0..63
    int acl = (tid & 3) * 4;       // 0,4,8,12
    int am0 = br * BM + ar;
    int am1 = am0 + 64;
    int cm0 = am0 < M ? am0 : M - 1;
    int cm1 = am1 < M ? am1 : M - 1;
    const float *Arow0, *Arow1;
    if (MODE == 1) {
        int b0 = cm0 / NLOC;
        int b1 = cm1 / NLOC;
        Arow0 = Ap + ((size_t)(b0 * SEQ + g_idx[cm0])) * K + acl;
        Arow1 = Ap + ((size_t)(b1 * SEQ + g_idx[cm1])) * K + acl;
    } else {
        Arow0 = Ap + (size_t)cm0 * K + acl;
        Arow1 = Ap + (size_t)cm1 * K + acl;
    }

    // B loader: rows tid>>5 (0..7) and +8; cols (tid&31)*4
    int brw = tid >> 5;
    int bcl = (tid & 31) * 4;
    const float* Bp0 = B + (size_t)brw * N + bc * BN + bcl;
    const float* Bp1 = Bp0 + (size_t)8 * N;

    float4 ra0 = *(const float4*)Arow0;
    float4 ra1 = *(const float4*)Arow1;
    float4 rb0 = *(const float4*)Bp0;
    float4 rb1 = *(const float4*)Bp1;

    float acc[4][4][4];
#pragma unroll
    for (int i = 0; i < 4; i++)
#pragma unroll
        for (int j = 0; j < 4; j++)
#pragma unroll
            for (int c = 0; c < 4; c++) acc[i][j][c] = 0.f;

    int nk = K / BK;
    for (int kt = 0; kt < nk; kt++) {
        st_tf32_4(&As[ar][acl],      ra0);
        st_tf32_4(&As[ar + 64][acl], ra1);
        st_tf32_4(&Bs[brw][bcl],     rb0);
        st_tf32_4(&Bs[brw + 8][bcl], rb1);
        __syncthreads();
        if (kt + 1 < nk) {
            ra0 = *(const float4*)(Arow0 + (kt + 1) * BK);
            ra1 = *(const float4*)(Arow1 + (kt + 1) * BK);
            rb0 = *(const float4*)(Bp0 + (size_t)(kt + 1) * BK * N);
            rb1 = *(const float4*)(Bp1 + (size_t)(kt + 1) * BK * N);
        }
#pragma unroll
        for (int ks = 0; ks < 2; ks++) {
            int k0 = ks * 8;
            uint32_t af[4][4];
            uint32_t bf[4][2];
#pragma unroll
            for (int i = 0; i < 4; i++) {
                int r = warp_m * 64 + i * 16 + g;
                af[i][0] = __float_as_uint(As[r][k0 + tig]);
                af[i][1] = __float_as_uint(As[r + 8][k0 + tig]);
                af[i][2] = __float_as_uint(As[r][k0 + tig + 4]);
                af[i][3] = __float_as_uint(As[r + 8][k0 + tig + 4]);
            }
#pragma unroll
            for (int j = 0; j < 4; j++) {
                int cix = warp_n * 32 + j * 8 + g;
                bf[j][0] = __float_as_uint(Bs[k0 + tig][cix]);
                bf[j][1] = __float_as_uint(Bs[k0 + tig + 4][cix]);
            }
#pragma unroll
            for (int i = 0; i < 4; i++)
#pragma unroll
                for (int j = 0; j < 4; j++)
                    MMA_TF32(acc[i][j], af[i], bf[j]);
        }
        __syncthreads();
    }

    // ---------------- epilogue ----------------
#pragma unroll
    for (int i = 0; i < 4; i++) {
        int mbase = br * BM + warp_m * 64 + i * 16 + g;
#pragma unroll
        for (int half = 0; half < 2; half++) {
            int m = mbase + half * 8;
            if (m >= M) continue;
            if (MODE == 0) {
                int bb = m / SEQ, nn = m % SEQ;
#pragma unroll
                for (int j = 0; j < 4; j++) {
                    int n0 = bc * BN + warp_n * 32 + j * 8 + 2 * tig;
#pragma unroll
                    for (int e = 0; e < 2; e++) {
                        int n = n0 + e;
                        float val = acc[i][j][half * 2 + e] + bias[n];
                        int nc = (n < CDIM) ? n : n - CDIM;
                        int h = nc >> 6, d = nc & 63;
                        float* dst = (n < CDIM) ? g_K : g_V;
                        dst[(((size_t)bb * NH + h) * SEQ + nn) * HD + d] = val;
                    }
                }
            } else if (MODE == 1) {
                int bb = m / NLOC, jj = m % NLOC;
#pragma unroll
                for (int j = 0; j < 4; j++) {
                    int n0 = bc * BN + warp_n * 32 + j * 8 + 2 * tig;
#pragma unroll
                    for (int e = 0; e < 2; e++) {
                        int n = n0 + e;
                        float val = acc[i][j][half * 2 + e] + bias[n];
                        int h = n >> 6, d = n & 63;
                        g_Q[(((size_t)bb * NH + h) * NLOC + jj) * HD + d] = val;
                    }
                }
            } else {
                int bb = m / NLOC;
                int row = bb * SEQ + g_idx[m];
                float* crow = C + (size_t)row * CDIM;
#pragma unroll
                for (int j = 0; j < 4; j++) {
                    int n0 = bc * BN + warp_n * 32 + j * 8 + 2 * tig;
                    crow[n0]     = acc[i][j][half * 2 + 0] + bias[n0];
                    crow[n0 + 1] = acc[i][j][half * 2 + 1] + bias[n0 + 1];
                }
            }
        }
    }
}

// ---------------- fused flash attention per (b,h) -------------------------
// block = 256 threads; thread owns rows {t/16 + 16*i, i<5} x 4 d-cols
__global__ __launch_bounds__(256) void attn_kernel()
{
    int bh = blockIdx.x;
    int b = bh / NH, h = bh % NH;

    __shared__ float Qs[80][65];
    __shared__ float Ks[32][65];
    __shared__ float Vs[32][64];
    __shared__ float S[80][33];
    __shared__ float s_m[80], s_l[80], s_factor[80];

    int t = threadIdx.x;
    int rowbase = t >> 4, dgrp = t & 15;

    const float* qsrc = g_Q + (size_t)bh * NLOC * HD;
    const float* ksrc = g_K + (size_t)bh * SEQ * HD;
    const float* vsrc = g_V + (size_t)bh * SEQ * HD;

    for (int l = t; l < 80 * 64; l += 256) {
        int r = l >> 6, d = l & 63;
        Qs[r][d] = (r < NLOC) ? qsrc[r * HD + d] : 0.f;
    }
    if (t < 80) { s_m[t] = -1e30f; s_l[t] = 0.f; }

    float acc[5][4];
#pragma unroll
    for (int i = 0; i < 5; i++)
#pragma unroll
        for (int c = 0; c < 4; c++) acc[i][c] = 0.f;

    const float scale = 0.125f;  // 64^-0.5
    __syncthreads();

    for (int n0 = 0; n0 < SEQ; n0 += 32) {
        // load K/V tile (clamped rows; masked later)
        for (int l = t; l < 32 * 64; l += 256) {
            int rr = l >> 6, d = l & 63;
            int src = n0 + rr; if (src > SEQ - 1) src = SEQ - 1;
            Ks[rr][d] = ksrc[src * HD + d];
            Vs[rr][d] = vsrc[src * HD + d];
        }
        __syncthreads();

        // S = Q K^T * scale ; each thread: 5 rows x 2 key cols
        {
            int kk0 = dgrp * 2;
            float s0[5], s1[5];
#pragma unroll
            for (int i = 0; i < 5; i++) { s0[i] = 0.f; s1[i] = 0.f; }
#pragma unroll 8
            for (int d = 0; d < 64; d++) {
                float ka = Ks[kk0][d], kb = Ks[kk0 + 1][d];
#pragma unroll
                for (int i = 0; i < 5; i++) {
                    float q = Qs[rowbase + 16 * i][d];
                    s0[i] += q * ka;
                    s1[i] += q * kb;
                }
            }
#pragma unroll
            for (int i = 0; i < 5; i++) {
                int r = rowbase + 16 * i;
                S[r][kk0]     = (n0 + kk0     < SEQ) ? s0[i] * scale : -1e30f;
                S[r][kk0 + 1] = (n0 + kk0 + 1 < SEQ) ? s1[i] * scale : -1e30f;
            }
        }
        __syncthreads();

        // per-row running max + rescale factor
        if (t < 80) {
            float mo = s_m[t], mx = mo;
#pragma unroll 8
            for (int kk = 0; kk < 32; kk++) mx = fmaxf(mx, S[t][kk]);
            s_factor[t] = __expf(mo - mx);
            s_m[t] = mx;
        }
        __syncthreads();

        // P = exp(S - m), non-redundant
        for (int l = t; l < 80 * 32; l += 256) {
            int r = l >> 5, kk = l & 31;
            S[r][kk] = __expf(S[r][kk] - s_m[r]);
        }
        __syncthreads();

        // accumulate O += P V ; dgrp==0 updates l
#pragma unroll
        for (int i = 0; i < 5; i++) {
            int r = rowbase + 16 * i;
            float f = s_factor[r];
            float a0 = acc[i][0] * f, a1 = acc[i][1] * f;
            float a2 = acc[i][2] * f, a3 = acc[i][3] * f;
            float sum = 0.f;
#pragma unroll 8
            for (int kk = 0; kk < 32; kk++) {
                float p = S[r][kk];
                float4 vv = *(const float4*)&Vs[kk][dgrp * 4];
                a0 += p * vv.x; a1 += p * vv.y;
                a2 += p * vv.z; a3 += p * vv.w;
                sum += p;
            }
            acc[i][0] = a0; acc[i][1] = a1; acc[i][2] = a2; acc[i][3] = a3;
            if (dgrp == 0) s_l[r] = s_l[r] * f + sum;
        }
        __syncthreads();
    }

    // writeout into g_att [b*78][768] at head column block
    float* dst = g_att + ((size_t)b * NLOC) * CDIM + h * HD + dgrp * 4;
#pragma unroll
    for (int i = 0; i < 5; i++) {
        int r = rowbase + 16 * i;
        if (r < NLOC) {
            float inv = 1.f / s_l[r];
            dst[(size_t)r * CDIM + 0] = acc[i][0] * inv;
            dst[(size_t)r * CDIM + 1] = acc[i][1] * inv;
            dst[(size_t)r * CDIM + 2] = acc[i][2] * inv;
            dst[(size_t)r * CDIM + 3] = acc[i][3] * inv;
        }
    }
}

// ---------------- launch ---------------------------------------------------
extern "C" void kernel_launch(void* const* d_in, const int* in_sizes, int n_in,
                              void* d_out, int out_size)
{
    const float* x    = (const float*)d_in[0];
    const float* roll = (const float*)d_in[1];
    const float* Wq   = (const float*)d_in[2];
    const float* bq   = (const float*)d_in[3];
    const float* Wkv  = (const float*)d_in[4];
    const float* bkv  = (const float*)d_in[5];
    const float* Wp   = (const float*)d_in[6];
    const float* bp   = (const float*)d_in[7];
    float* out = (float*)d_out;

    size_t xbytes = (size_t)NB * SEQ * CDIM * sizeof(float);

    // pass-through copy (scattered rows overwritten at the end)
    cudaMemcpyAsync(out, x, xbytes, cudaMemcpyDeviceToDevice);

    // top-k indices per batch
    topk_kernel<<<NB, 256>>>(roll);

    // KV projection: [50240,768] @ [768,1536] -> g_K/g_V
    {
        int M = NB * SEQ, N = 2 * CDIM, K = CDIM;
        dim3 grid(N / 128, (M + 127) / 128);
        gemm_tf32<0><<<grid, 256>>>(x, Wkv, bkv, nullptr, M, N, K);
    }
    // Q projection (gathered rows): [4992,768] @ [768,768] -> g_Q
    {
        int M = NB * NLOC, N = CDIM, K = CDIM;
        dim3 grid(N / 128, (M + 127) / 128);
        gemm_tf32<1><<<grid, 256>>>(x, Wq, bq, nullptr, M, N, K);
    }
    // fused attention -> g_att
    attn_kernel<<<NB * NH, 256>>>();

    // output projection + scatter into out
    {
        int M = NB * NLOC, N = CDIM, K = CDIM;
        dim3 grid(N / 128, (M + 127) / 128);
        gemm_tf32<2><<<grid, 256>>>(nullptr, Wp, bp, out, M, N, K);
    }
}

// round 4
// speedup vs baseline: 2.6497x; 1.4255x over previous
#include <cuda_runtime.h>
#include <cstdint>

// Problem constants
#define NB   64      // batch
#define SEQ  785     // tokens
#define CDIM 768     // channels
#define NH   12      // heads
#define HD   64      // head dim
#define NLOC 78      // num_local = int(0.1 * 784)

// ---------------- device scratch (static, no allocations) ----------------
__device__ float g_K[(size_t)NB * NH * SEQ * HD];     // [b][h][n][d]
__device__ float g_V[(size_t)NB * NH * SEQ * HD];     // [b][h][n][d]
__device__ float g_Q[(size_t)NB * NH * NLOC * HD];    // [b][h][j][d]
__device__ float g_att[(size_t)NB * NLOC * CDIM];     // [b*78][768]
__device__ int   g_idx[NB * NLOC];                    // gathered token index (1..784)

// ---------------- top-k by exact rank (matches jax.lax.top_k ties) -------
__global__ __launch_bounds__(256) void topk_kernel(const float* __restrict__ roll)
{
    int b = blockIdx.x;
    __shared__ float v[SEQ - 1];  // 784
    const float* src = roll + (size_t)b * SEQ * SEQ + 1;  // row 0, cols 1..784
    for (int i = threadIdx.x; i < SEQ - 1; i += 256) v[i] = src[i];
    __syncthreads();
    for (int i = threadIdx.x; i < SEQ - 1; i += 256) {
        float vi = v[i];
        int rank = 0;
        for (int j = 0; j < SEQ - 1; j++) {
            float vj = v[j];
            rank += (vj > vi) || (vj == vi && j < i);
        }
        if (rank < NLOC) g_idx[b * NLOC + rank] = i + 1;
    }
}

// ---------------- TF32 helpers --------------------------------------------
__device__ __forceinline__ uint32_t f2tf32(float f) {
    uint32_t u;
    asm("cvt.rna.tf32.f32 %0, %1;" : "=r"(u) : "f"(f));
    return u;
}
__device__ __forceinline__ void st_tf32_4(float* dst, float4 v) {
    float4 o;
    o.x = __uint_as_float(f2tf32(v.x));
    o.y = __uint_as_float(f2tf32(v.y));
    o.z = __uint_as_float(f2tf32(v.z));
    o.w = __uint_as_float(f2tf32(v.w));
    *(float4*)dst = o;
}

#define MMA_TF32(C, A, B)                                                     \
    asm volatile(                                                             \
        "mma.sync.aligned.m16n8k8.row.col.f32.tf32.tf32.f32 "                 \
        "{%0,%1,%2,%3}, {%4,%5,%6,%7}, {%8,%9}, {%0,%1,%2,%3};"               \
        : "+f"((C)[0]), "+f"((C)[1]), "+f"((C)[2]), "+f"((C)[3])              \
        : "r"((A)[0]), "r"((A)[1]), "r"((A)[2]), "r"((A)[3]),                 \
          "r"((B)[0]), "r"((B)[1]))

// ---------------- TF32 tensor-core GEMM, 128x128x16 -----------------------
template <int MODE>
__global__ __launch_bounds__(256) void gemm_tf32(
    const float* __restrict__ A, const float* __restrict__ B,
    const float* __restrict__ bias, float* __restrict__ C,
    int M, int N, int K)
{
    const int BM = 128, BN = 128, BK = 16;
    __shared__ float As[BM][BK + 4];    // pad -> 20 floats/row (bank-clean)
    __shared__ float Bs[BK][BN + 8];    // pad -> 136 floats/row (bank-clean)

    int tid = threadIdx.x;
    int wid = tid >> 5, lane = tid & 31;
    int warp_m = wid & 1, warp_n = wid >> 1;   // 2 x 4
    int g = lane >> 2, tig = lane & 3;

    int bc = blockIdx.x, br = blockIdx.y;

    const float* Ap = (MODE == 2) ? (const float*)g_att : A;

    int ar  = tid >> 2;            // 0..63
    int acl = (tid & 3) * 4;       // 0,4,8,12
    int am0 = br * BM + ar;
    int am1 = am0 + 64;
    int cm0 = am0 < M ? am0 : M - 1;
    int cm1 = am1 < M ? am1 : M - 1;
    const float *Arow0, *Arow1;
    if (MODE == 1) {
        int b0 = cm0 / NLOC;
        int b1 = cm1 / NLOC;
        Arow0 = Ap + ((size_t)(b0 * SEQ + g_idx[cm0])) * K + acl;
        Arow1 = Ap + ((size_t)(b1 * SEQ + g_idx[cm1])) * K + acl;
    } else {
        Arow0 = Ap + (size_t)cm0 * K + acl;
        Arow1 = Ap + (size_t)cm1 * K + acl;
    }

    int brw = tid >> 5;
    int bcl = (tid & 31) * 4;
    const float* Bp0 = B + (size_t)brw * N + bc * BN + bcl;
    const float* Bp1 = Bp0 + (size_t)8 * N;

    float4 ra0 = *(const float4*)Arow0;
    float4 ra1 = *(const float4*)Arow1;
    float4 rb0 = *(const float4*)Bp0;
    float4 rb1 = *(const float4*)Bp1;

    float acc[4][4][4];
#pragma unroll
    for (int i = 0; i < 4; i++)
#pragma unroll
        for (int j = 0; j < 4; j++)
#pragma unroll
            for (int c = 0; c < 4; c++) acc[i][j][c] = 0.f;

    int nk = K / BK;
    for (int kt = 0; kt < nk; kt++) {
        st_tf32_4(&As[ar][acl],      ra0);
        st_tf32_4(&As[ar + 64][acl], ra1);
        st_tf32_4(&Bs[brw][bcl],     rb0);
        st_tf32_4(&Bs[brw + 8][bcl], rb1);
        __syncthreads();
        if (kt + 1 < nk) {
            ra0 = *(const float4*)(Arow0 + (kt + 1) * BK);
            ra1 = *(const float4*)(Arow1 + (kt + 1) * BK);
            rb0 = *(const float4*)(Bp0 + (size_t)(kt + 1) * BK * N);
            rb1 = *(const float4*)(Bp1 + (size_t)(kt + 1) * BK * N);
        }
#pragma unroll
        for (int ks = 0; ks < 2; ks++) {
            int k0 = ks * 8;
            uint32_t af[4][4];
            uint32_t bf[4][2];
#pragma unroll
            for (int i = 0; i < 4; i++) {
                int r = warp_m * 64 + i * 16 + g;
                af[i][0] = __float_as_uint(As[r][k0 + tig]);
                af[i][1] = __float_as_uint(As[r + 8][k0 + tig]);
                af[i][2] = __float_as_uint(As[r][k0 + tig + 4]);
                af[i][3] = __float_as_uint(As[r + 8][k0 + tig + 4]);
            }
#pragma unroll
            for (int j = 0; j < 4; j++) {
                int cix = warp_n * 32 + j * 8 + g;
                bf[j][0] = __float_as_uint(Bs[k0 + tig][cix]);
                bf[j][1] = __float_as_uint(Bs[k0 + tig + 4][cix]);
            }
#pragma unroll
            for (int i = 0; i < 4; i++)
#pragma unroll
                for (int j = 0; j < 4; j++)
                    MMA_TF32(acc[i][j], af[i], bf[j]);
        }
        __syncthreads();
    }

    // ---------------- epilogue ----------------
#pragma unroll
    for (int i = 0; i < 4; i++) {
        int mbase = br * BM + warp_m * 64 + i * 16 + g;
#pragma unroll
        for (int half = 0; half < 2; half++) {
            int m = mbase + half * 8;
            if (m >= M) continue;
            if (MODE == 0) {
                int bb = m / SEQ, nn = m % SEQ;
#pragma unroll
                for (int j = 0; j < 4; j++) {
                    int n0 = bc * BN + warp_n * 32 + j * 8 + 2 * tig;
#pragma unroll
                    for (int e = 0; e < 2; e++) {
                        int n = n0 + e;
                        float val = acc[i][j][half * 2 + e] + bias[n];
                        int nc = (n < CDIM) ? n : n - CDIM;
                        int h = nc >> 6, d = nc & 63;
                        float* dst = (n < CDIM) ? g_K : g_V;
                        dst[(((size_t)bb * NH + h) * SEQ + nn) * HD + d] = val;
                    }
                }
            } else if (MODE == 1) {
                int bb = m / NLOC, jj = m % NLOC;
#pragma unroll
                for (int j = 0; j < 4; j++) {
                    int n0 = bc * BN + warp_n * 32 + j * 8 + 2 * tig;
#pragma unroll
                    for (int e = 0; e < 2; e++) {
                        int n = n0 + e;
                        float val = acc[i][j][half * 2 + e] + bias[n];
                        int h = n >> 6, d = n & 63;
                        g_Q[(((size_t)bb * NH + h) * NLOC + jj) * HD + d] = val;
                    }
                }
            } else {
                int bb = m / NLOC;
                int row = bb * SEQ + g_idx[m];
                float* crow = C + (size_t)row * CDIM;
#pragma unroll
                for (int j = 0; j < 4; j++) {
                    int n0 = bc * BN + warp_n * 32 + j * 8 + 2 * tig;
                    crow[n0]     = acc[i][j][half * 2 + 0] + bias[n0];
                    crow[n0 + 1] = acc[i][j][half * 2 + 1] + bias[n0 + 1];
                }
            }
        }
    }
}

// ---------------- TF32 tensor-core flash attention per (b,h) --------------
// M=96 (78 valid), key tile KN=64, 8 warps in 2x4.
// S phase: warp computes 48x16 of S via 3x2 m16n8k8 frags, depth 64.
// PV phase: warp computes 48x16 of O via 3x2 frags, depth 64 (keys).
#define AT_M   96
#define AT_KN  64
#define QS_LD  68   // Qs row pitch (floats)
#define KS_LD  68   // Ks row pitch
#define VS_LD  65   // Vs row pitch (transposed [d][key])
#define SS_LD  68   // Ss row pitch

// dynamic smem offsets (floats)
#define OFF_Q   0
#define OFF_KV  (AT_M * QS_LD)                    // 6528
#define OFF_S   (OFF_KV + AT_KN * KS_LD)          // 6528 + 4352 = 10880
#define OFF_M   (OFF_S + AT_M * SS_LD)            // 10880 + 6528 = 17408
#define OFF_L   (OFF_M + AT_M)
#define OFF_F   (OFF_L + AT_M)
#define SMEM_FLOATS (OFF_F + AT_M)                // 17696 floats = 70784 B

__global__ __launch_bounds__(256, 2) void attn_kernel()
{
    extern __shared__ float sm[];
    float* Qs  = sm + OFF_Q;    // [96][68]
    float* Ks  = sm + OFF_KV;   // [64][68]  (K tile, also reused as Vs [64][65])
    float* Vs  = sm + OFF_KV;
    float* Ss  = sm + OFF_S;    // [96][68]
    float* s_m = sm + OFF_M;
    float* s_l = sm + OFF_L;
    float* s_f = sm + OFF_F;

    int bh = blockIdx.x;
    int b = bh / NH, h = bh % NH;
    int t = threadIdx.x;
    int wid = t >> 5, lane = t & 31;
    int warp_m = wid & 1, warp_n = wid >> 1;   // 2 x 4
    int g = lane >> 2, tig = lane & 3;

    const float* qsrc = g_Q + (size_t)bh * NLOC * HD;
    const float* ksrc = g_K + (size_t)bh * SEQ * HD;
    const float* vsrc = g_V + (size_t)bh * SEQ * HD;

    // load Q (tf32-converted), zero-pad rows 78..95 ; 96*16 float4 chunks
    for (int l = t; l < AT_M * 16; l += 256) {
        int r = l >> 4, c4 = (l & 15) * 4;
        float4 v = (r < NLOC) ? *(const float4*)(qsrc + r * HD + c4)
                              : make_float4(0.f, 0.f, 0.f, 0.f);
        st_tf32_4(&Qs[r * QS_LD + c4], v);
    }
    if (t < AT_M) { s_m[t] = -1e30f; s_l[t] = 0.f; }

    float acc_o[3][2][4];
#pragma unroll
    for (int i = 0; i < 3; i++)
#pragma unroll
        for (int j = 0; j < 2; j++)
#pragma unroll
            for (int c = 0; c < 4; c++) acc_o[i][j][c] = 0.f;

    const float scale = 0.125f;  // 64^-0.5

    for (int n0 = 0; n0 < SEQ; n0 += AT_KN) {
        // sync: protects Qs on first iter; Vs/P consumption on later iters
        __syncthreads();

        // ---- load K tile [64][64] tf32 (clamped rows; masked at S-write)
        for (int l = t; l < AT_KN * 16; l += 256) {
            int kk = l >> 4, c4 = (l & 15) * 4;
            int src = n0 + kk; if (src > SEQ - 1) src = SEQ - 1;
            st_tf32_4(&Ks[kk * KS_LD + c4], *(const float4*)(ksrc + src * HD + c4));
        }
        __syncthreads();

        // ---- S = Q K^T (warp 48x16, frags 3x2, 8 k-steps)
        float acc_s[3][2][4];
#pragma unroll
        for (int i = 0; i < 3; i++)
#pragma unroll
            for (int j = 0; j < 2; j++)
#pragma unroll
                for (int c = 0; c < 4; c++) acc_s[i][j][c] = 0.f;

#pragma unroll
        for (int ks = 0; ks < 8; ks++) {
            int k0 = ks * 8;
            uint32_t af[3][4], bf[2][2];
#pragma unroll
            for (int i = 0; i < 3; i++) {
                int r = warp_m * 48 + i * 16 + g;
                af[i][0] = __float_as_uint(Qs[r * QS_LD + k0 + tig]);
                af[i][1] = __float_as_uint(Qs[(r + 8) * QS_LD + k0 + tig]);
                af[i][2] = __float_as_uint(Qs[r * QS_LD + k0 + tig + 4]);
                af[i][3] = __float_as_uint(Qs[(r + 8) * QS_LD + k0 + tig + 4]);
            }
#pragma unroll
            for (int j = 0; j < 2; j++) {
                int cix = warp_n * 16 + j * 8 + g;   // key col
                bf[j][0] = __float_as_uint(Ks[cix * KS_LD + k0 + tig]);
                bf[j][1] = __float_as_uint(Ks[cix * KS_LD + k0 + tig + 4]);
            }
#pragma unroll
            for (int i = 0; i < 3; i++)
#pragma unroll
                for (int j = 0; j < 2; j++)
                    MMA_TF32(acc_s[i][j], af[i], bf[j]);
        }

        // ---- write S*scale to Ss with key mask
#pragma unroll
        for (int i = 0; i < 3; i++) {
            int r0 = warp_m * 48 + i * 16 + g;
#pragma unroll
            for (int j = 0; j < 2; j++) {
                int c0 = warp_n * 16 + j * 8 + 2 * tig;
                bool v0 = (n0 + c0) < SEQ, v1 = (n0 + c0 + 1) < SEQ;
                Ss[r0 * SS_LD + c0]           = v0 ? acc_s[i][j][0] * scale : -1e30f;
                Ss[r0 * SS_LD + c0 + 1]       = v1 ? acc_s[i][j][1] * scale : -1e30f;
                Ss[(r0 + 8) * SS_LD + c0]     = v0 ? acc_s[i][j][2] * scale : -1e30f;
                Ss[(r0 + 8) * SS_LD + c0 + 1] = v1 ? acc_s[i][j][3] * scale : -1e30f;
            }
        }
        __syncthreads();

        // ---- V tile load (transposed, into Ks buffer) + row-owner softmax
        // V: 4 passes of 16 keys; thread: d=(t&15)*4, key=t>>4
        {
            int d4 = (t & 15) * 4;
            int kk = t >> 4;
#pragma unroll
            for (int p = 0; p < 4; p++, kk += 16) {
                int src = n0 + kk; if (src > SEQ - 1) src = SEQ - 1;
                float4 v = *(const float4*)(vsrc + src * HD + d4);
                Vs[(d4 + 0) * VS_LD + kk] = __uint_as_float(f2tf32(v.x));
                Vs[(d4 + 1) * VS_LD + kk] = __uint_as_float(f2tf32(v.y));
                Vs[(d4 + 2) * VS_LD + kk] = __uint_as_float(f2tf32(v.z));
                Vs[(d4 + 3) * VS_LD + kk] = __uint_as_float(f2tf32(v.w));
            }
        }
        if (t < AT_M) {
            float* row = Ss + t * SS_LD;
            float mo = s_m[t], mx = mo;
#pragma unroll
            for (int c4 = 0; c4 < AT_KN; c4 += 4) {
                float4 v = *(float4*)(row + c4);
                mx = fmaxf(mx, fmaxf(fmaxf(v.x, v.y), fmaxf(v.z, v.w)));
            }
            float fac = __expf(mo - mx);
            s_f[t] = fac; s_m[t] = mx;
            float sum = 0.f;
#pragma unroll
            for (int c4 = 0; c4 < AT_KN; c4 += 4) {
                float4 v = *(float4*)(row + c4);
                v.x = __expf(v.x - mx); v.y = __expf(v.y - mx);
                v.z = __expf(v.z - mx); v.w = __expf(v.w - mx);
                sum += v.x + v.y + v.z + v.w;
                st_tf32_4(row + c4, v);
            }
            s_l[t] = s_l[t] * fac + sum;
        }
        __syncthreads();

        // ---- rescale O accumulators, then O += P V
#pragma unroll
        for (int i = 0; i < 3; i++) {
            int r0 = warp_m * 48 + i * 16 + g;
            float f0 = s_f[r0], f1 = s_f[r0 + 8];
#pragma unroll
            for (int j = 0; j < 2; j++) {
                acc_o[i][j][0] *= f0; acc_o[i][j][1] *= f0;
                acc_o[i][j][2] *= f1; acc_o[i][j][3] *= f1;
            }
        }
#pragma unroll
        for (int ks = 0; ks < 8; ks++) {
            int k0 = ks * 8;   // key depth
            uint32_t af[3][4], bf[2][2];
#pragma unroll
            for (int i = 0; i < 3; i++) {
                int r = warp_m * 48 + i * 16 + g;
                af[i][0] = __float_as_uint(Ss[r * SS_LD + k0 + tig]);
                af[i][1] = __float_as_uint(Ss[(r + 8) * SS_LD + k0 + tig]);
                af[i][2] = __float_as_uint(Ss[r * SS_LD + k0 + tig + 4]);
                af[i][3] = __float_as_uint(Ss[(r + 8) * SS_LD + k0 + tig + 4]);
            }
#pragma unroll
            for (int j = 0; j < 2; j++) {
                int cix = warp_n * 16 + j * 8 + g;   // output dim d
                bf[j][0] = __float_as_uint(Vs[cix * VS_LD + k0 + tig]);
                bf[j][1] = __float_as_uint(Vs[cix * VS_LD + k0 + tig + 4]);
            }
#pragma unroll
            for (int i = 0; i < 3; i++)
#pragma unroll
                for (int j = 0; j < 2; j++)
                    MMA_TF32(acc_o[i][j], af[i], bf[j]);
        }
    }
    __syncthreads();

    // ---- writeout: g_att[b*78 + r][h*64 + c] = O / l
#pragma unroll
    for (int i = 0; i < 3; i++) {
        int r0 = warp_m * 48 + i * 16 + g;
#pragma unroll
        for (int half = 0; half < 2; half++) {
            int r = r0 + half * 8;
            if (r >= NLOC) continue;
            float inv = 1.f / s_l[r];
            float* dst = g_att + ((size_t)(b * NLOC + r)) * CDIM + h * HD;
#pragma unroll
            for (int j = 0; j < 2; j++) {
                int c0 = warp_n * 16 + j * 8 + 2 * tig;
                float2 o;
                o.x = acc_o[i][j][half * 2 + 0] * inv;
                o.y = acc_o[i][j][half * 2 + 1] * inv;
                *(float2*)(dst + c0) = o;
            }
        }
    }
}

// ---------------- launch ---------------------------------------------------
extern "C" void kernel_launch(void* const* d_in, const int* in_sizes, int n_in,
                              void* d_out, int out_size)
{
    const float* x    = (const float*)d_in[0];
    const float* roll = (const float*)d_in[1];
    const float* Wq   = (const float*)d_in[2];
    const float* bq   = (const float*)d_in[3];
    const float* Wkv  = (const float*)d_in[4];
    const float* bkv  = (const float*)d_in[5];
    const float* Wp   = (const float*)d_in[6];
    const float* bp   = (const float*)d_in[7];
    float* out = (float*)d_out;

    size_t xbytes = (size_t)NB * SEQ * CDIM * sizeof(float);
    const int attn_smem = SMEM_FLOATS * sizeof(float);  // 70784 B

    static int s_attr_done = 0;
    if (!s_attr_done) {
        cudaFuncSetAttribute(attn_kernel,
                             cudaFuncAttributeMaxDynamicSharedMemorySize, attn_smem);
        s_attr_done = 1;
    }

    // pass-through copy (scattered rows overwritten at the end)
    cudaMemcpyAsync(out, x, xbytes, cudaMemcpyDeviceToDevice);

    // top-k indices per batch
    topk_kernel<<<NB, 256>>>(roll);

    // KV projection: [50240,768] @ [768,1536] -> g_K/g_V
    {
        int M = NB * SEQ, N = 2 * CDIM, K = CDIM;
        dim3 grid(N / 128, (M + 127) / 128);
        gemm_tf32<0><<<grid, 256>>>(x, Wkv, bkv, nullptr, M, N, K);
    }
    // Q projection (gathered rows): [4992,768] @ [768,768] -> g_Q
    {
        int M = NB * NLOC, N = CDIM, K = CDIM;
        dim3 grid(N / 128, (M + 127) / 128);
        gemm_tf32<1><<<grid, 256>>>(x, Wq, bq, nullptr, M, N, K);
    }
    // fused tensor-core attention -> g_att
    attn_kernel<<<NB * NH, 256, attn_smem>>>();

    // output projection + scatter into out
    {
        int M = NB * NLOC, N = CDIM, K = CDIM;
        dim3 grid(N / 128, (M + 127) / 128);
        gemm_tf32<2><<<grid, 256>>>(nullptr, Wp, bp, out, M, N, K);
    }
}

// round 5
// speedup vs baseline: 2.9858x; 1.1269x over previous
#include <cuda_runtime.h>
#include <cstdint>

// Problem constants
#define NB   64      // batch
#define SEQ  785     // tokens
#define CDIM 768     // channels
#define NH   12      // heads
#define HD   64      // head dim
#define NLOC 78      // num_local = int(0.1 * 784)

// ---------------- device scratch (static, no allocations) ----------------
__device__ float g_K[(size_t)NB * NH * SEQ * HD];     // [b][h][n][d]
__device__ float g_V[(size_t)NB * NH * SEQ * HD];     // [b][h][n][d]
__device__ float g_Q[(size_t)NB * NH * NLOC * HD];    // [b][h][j][d]
__device__ float g_att[(size_t)NB * NLOC * CDIM];     // [b*78][768]
__device__ int   g_idx[NB * NLOC];                    // gathered token index (1..784)

// ---------------- top-k by exact rank (matches jax.lax.top_k ties) -------
__global__ __launch_bounds__(256) void topk_kernel(const float* __restrict__ roll)
{
    int b = blockIdx.x;
    __shared__ float v[SEQ - 1];  // 784
    const float* src = roll + (size_t)b * SEQ * SEQ + 1;  // row 0, cols 1..784
    for (int i = threadIdx.x; i < SEQ - 1; i += 256) v[i] = src[i];
    __syncthreads();
    for (int i = threadIdx.x; i < SEQ - 1; i += 256) {
        float vi = v[i];
        int rank = 0;
        for (int j = 0; j < SEQ - 1; j++) {
            float vj = v[j];
            rank += (vj > vi) || (vj == vi && j < i);
        }
        if (rank < NLOC) g_idx[b * NLOC + rank] = i + 1;
    }
}

// ---------------- TF32 helpers --------------------------------------------
__device__ __forceinline__ uint32_t f2tf32(float f) {
    uint32_t u;
    asm("cvt.rna.tf32.f32 %0, %1;" : "=r"(u) : "f"(f));
    return u;
}
__device__ __forceinline__ void st_tf32_4(float* dst, float4 v) {
    float4 o;
    o.x = __uint_as_float(f2tf32(v.x));
    o.y = __uint_as_float(f2tf32(v.y));
    o.z = __uint_as_float(f2tf32(v.z));
    o.w = __uint_as_float(f2tf32(v.w));
    *(float4*)dst = o;
}

#define MMA_TF32(C, A, B)                                                     \
    asm volatile(                                                             \
        "mma.sync.aligned.m16n8k8.row.col.f32.tf32.tf32.f32 "                 \
        "{%0,%1,%2,%3}, {%4,%5,%6,%7}, {%8,%9}, {%0,%1,%2,%3};"               \
        : "+f"((C)[0]), "+f"((C)[1]), "+f"((C)[2]), "+f"((C)[3])              \
        : "r"((A)[0]), "r"((A)[1]), "r"((A)[2]), "r"((A)[3]),                 \
          "r"((B)[0]), "r"((B)[1]))

__device__ __forceinline__ void cp16(uint32_t s, const void* g) {
    asm volatile("cp.async.cg.shared.global [%0], [%1], 16;" :: "r"(s), "l"(g));
}
#define CP_COMMIT()  asm volatile("cp.async.commit_group;")
#define CP_WAIT(n)   asm volatile("cp.async.wait_group %0;" :: "n"(n))

// ---------------- TF32 GEMM, 128x128x16, 3-stage cp.async pipeline --------
// fp32 bits fed directly to tf32 MMA (HW truncates mantissa).
#define G_APAD 20                 // As row pitch (floats)
#define G_BPAD 136                // Bs row pitch (floats)
#define G_AFL  (128 * G_APAD)     // 2560
#define G_BFL  (16 * G_BPAD)      // 2176
#define G_STG  (G_AFL + G_BFL)    // 4736 floats per stage
#define G_ST   3
#define G_SMEM_BYTES (G_ST * G_STG * 4)   // 56832

template <int MODE>
__global__ __launch_bounds__(256, 2) void gemm_tf32(
    const float* __restrict__ A, const float* __restrict__ B,
    const float* __restrict__ bias, float* __restrict__ C,
    int M, int N, int K)
{
    const int BM = 128, BN = 128, BK = 16;
    extern __shared__ float sm[];
    uint32_t smem_u32 = (uint32_t)__cvta_generic_to_shared(sm);

    int tid = threadIdx.x;
    int wid = tid >> 5, lane = tid & 31;
    int warp_m = wid & 1, warp_n = wid >> 1;   // 2 x 4
    int g = lane >> 2, tig = lane & 3;

    int bc = blockIdx.x, br = blockIdx.y;

    const float* Ap = (MODE == 2) ? (const float*)g_att : A;

    // A loader: rows ar, ar+64; col acl (4 floats = 16B)
    int ar  = tid >> 2;
    int acl = (tid & 3) * 4;
    int am0 = br * BM + ar;
    int am1 = am0 + 64;
    int cm0 = am0 < M ? am0 : M - 1;
    int cm1 = am1 < M ? am1 : M - 1;
    const float *Arow0, *Arow1;
    if (MODE == 1) {
        int b0 = cm0 / NLOC;
        int b1 = cm1 / NLOC;
        Arow0 = Ap + ((size_t)(b0 * SEQ + g_idx[cm0])) * K + acl;
        Arow1 = Ap + ((size_t)(b1 * SEQ + g_idx[cm1])) * K + acl;
    } else {
        Arow0 = Ap + (size_t)cm0 * K + acl;
        Arow1 = Ap + (size_t)cm1 * K + acl;
    }

    // B loader: rows brw, brw+8; col bcl
    int brw = tid >> 5;
    int bcl = (tid & 31) * 4;
    const float* Bp0 = B + (size_t)brw * N + bc * BN + bcl;
    const float* Bp1 = Bp0 + (size_t)8 * N;

    // per-thread shared store offsets (bytes)
    uint32_t sA = smem_u32 + (uint32_t)(ar * G_APAD + acl) * 4;
    uint32_t sB = smem_u32 + (uint32_t)(G_AFL + brw * G_BPAD + bcl) * 4;

    int nk = K / BK;

    // prologue: stages 0..ST-2
#pragma unroll
    for (int p = 0; p < G_ST - 1; p++) {
        uint32_t so = (uint32_t)(p * G_STG) * 4;
        cp16(sA + so, Arow0 + p * BK);
        cp16(sA + so + 64 * G_APAD * 4, Arow1 + p * BK);
        cp16(sB + so, Bp0 + (size_t)p * BK * N);
        cp16(sB + so + 8 * G_BPAD * 4, Bp1 + (size_t)p * BK * N);
        CP_COMMIT();
    }

    float acc[4][4][4];
#pragma unroll
    for (int i = 0; i < 4; i++)
#pragma unroll
        for (int j = 0; j < 4; j++)
#pragma unroll
            for (int c = 0; c < 4; c++) acc[i][j][c] = 0.f;

    int st = 0;
    for (int kt = 0; kt < nk; kt++) {
        CP_WAIT(G_ST - 2);
        __syncthreads();

        // issue loads for stage kt+ST-1 (overwrites buffer st-1, safe post-sync)
        int nxt = kt + G_ST - 1;
        if (nxt < nk) {
            int stn = nxt % G_ST;
            uint32_t so = (uint32_t)(stn * G_STG) * 4;
            cp16(sA + so, Arow0 + nxt * BK);
            cp16(sA + so + 64 * G_APAD * 4, Arow1 + nxt * BK);
            cp16(sB + so, Bp0 + (size_t)nxt * BK * N);
            cp16(sB + so + 8 * G_BPAD * 4, Bp1 + (size_t)nxt * BK * N);
        }
        CP_COMMIT();

        const float* As = sm + st * G_STG;
        const float* Bs = As + G_AFL;

#pragma unroll
        for (int ks = 0; ks < 2; ks++) {
            int k0 = ks * 8;
            uint32_t af[4][4];
            uint32_t bf[4][2];
#pragma unroll
            for (int i = 0; i < 4; i++) {
                int r = warp_m * 64 + i * 16 + g;
                af[i][0] = __float_as_uint(As[r * G_APAD + k0 + tig]);
                af[i][1] = __float_as_uint(As[(r + 8) * G_APAD + k0 + tig]);
                af[i][2] = __float_as_uint(As[r * G_APAD + k0 + tig + 4]);
                af[i][3] = __float_as_uint(As[(r + 8) * G_APAD + k0 + tig + 4]);
            }
#pragma unroll
            for (int j = 0; j < 4; j++) {
                int cix = warp_n * 32 + j * 8 + g;
                bf[j][0] = __float_as_uint(Bs[(k0 + tig) * G_BPAD + cix]);
                bf[j][1] = __float_as_uint(Bs[(k0 + tig + 4) * G_BPAD + cix]);
            }
#pragma unroll
            for (int i = 0; i < 4; i++)
#pragma unroll
                for (int j = 0; j < 4; j++)
                    MMA_TF32(acc[i][j], af[i], bf[j]);
        }
        st = (st + 1 == G_ST) ? 0 : st + 1;
    }

    // ---------------- epilogue ----------------
#pragma unroll
    for (int i = 0; i < 4; i++) {
        int mbase = br * BM + warp_m * 64 + i * 16 + g;
#pragma unroll
        for (int half = 0; half < 2; half++) {
            int m = mbase + half * 8;
            if (m >= M) continue;
            if (MODE == 0) {
                int bb = m / SEQ, nn = m % SEQ;
#pragma unroll
                for (int j = 0; j < 4; j++) {
                    int n0 = bc * BN + warp_n * 32 + j * 8 + 2 * tig;
#pragma unroll
                    for (int e = 0; e < 2; e++) {
                        int n = n0 + e;
                        float val = acc[i][j][half * 2 + e] + bias[n];
                        int nc = (n < CDIM) ? n : n - CDIM;
                        int h = nc >> 6, d = nc & 63;
                        float* dst = (n < CDIM) ? g_K : g_V;
                        dst[(((size_t)bb * NH + h) * SEQ + nn) * HD + d] = val;
                    }
                }
            } else if (MODE == 1) {
                int bb = m / NLOC, jj = m % NLOC;
#pragma unroll
                for (int j = 0; j < 4; j++) {
                    int n0 = bc * BN + warp_n * 32 + j * 8 + 2 * tig;
#pragma unroll
                    for (int e = 0; e < 2; e++) {
                        int n = n0 + e;
                        float val = acc[i][j][half * 2 + e] + bias[n];
                        int h = n >> 6, d = n & 63;
                        g_Q[(((size_t)bb * NH + h) * NLOC + jj) * HD + d] = val;
                    }
                }
            } else {
                int bb = m / NLOC;
                int row = bb * SEQ + g_idx[m];
                float* crow = C + (size_t)row * CDIM;
#pragma unroll
                for (int j = 0; j < 4; j++) {
                    int n0 = bc * BN + warp_n * 32 + j * 8 + 2 * tig;
                    crow[n0]     = acc[i][j][half * 2 + 0] + bias[n0];
                    crow[n0 + 1] = acc[i][j][half * 2 + 1] + bias[n0 + 1];
                }
            }
        }
    }
}

// ---------------- TF32 tensor-core flash attention per (b,h) --------------
#define AT_M   96
#define AT_KN  64
#define QS_LD  68
#define KS_LD  68
#define VS_LD  65
#define SS_LD  68

#define OFF_Q   0
#define OFF_KV  (AT_M * QS_LD)
#define OFF_S   (OFF_KV + AT_KN * KS_LD)
#define OFF_M   (OFF_S + AT_M * SS_LD)
#define OFF_L   (OFF_M + AT_M)
#define OFF_F   (OFF_L + AT_M)
#define SMEM_FLOATS (OFF_F + AT_M)

__global__ __launch_bounds__(256, 2) void attn_kernel()
{
    extern __shared__ float sm[];
    float* Qs  = sm + OFF_Q;    // [96][68]
    float* Ks  = sm + OFF_KV;   // [64][68]  (K tile, reused as Vs [64][65])
    float* Vs  = sm + OFF_KV;
    float* Ss  = sm + OFF_S;    // [96][68]
    float* s_m = sm + OFF_M;
    float* s_l = sm + OFF_L;
    float* s_f = sm + OFF_F;

    int bh = blockIdx.x;
    int b = bh / NH, h = bh % NH;
    int t = threadIdx.x;
    int wid = t >> 5, lane = t & 31;
    int warp_m = wid & 1, warp_n = wid >> 1;   // 2 x 4
    int g = lane >> 2, tig = lane & 3;

    const float* qsrc = g_Q + (size_t)bh * NLOC * HD;
    const float* ksrc = g_K + (size_t)bh * SEQ * HD;
    const float* vsrc = g_V + (size_t)bh * SEQ * HD;

    for (int l = t; l < AT_M * 16; l += 256) {
        int r = l >> 4, c4 = (l & 15) * 4;
        float4 v = (r < NLOC) ? *(const float4*)(qsrc + r * HD + c4)
                              : make_float4(0.f, 0.f, 0.f, 0.f);
        st_tf32_4(&Qs[r * QS_LD + c4], v);
    }
    if (t < AT_M) { s_m[t] = -1e30f; s_l[t] = 0.f; }

    float acc_o[3][2][4];
#pragma unroll
    for (int i = 0; i < 3; i++)
#pragma unroll
        for (int j = 0; j < 2; j++)
#pragma unroll
            for (int c = 0; c < 4; c++) acc_o[i][j][c] = 0.f;

    const float scale = 0.125f;

    for (int n0 = 0; n0 < SEQ; n0 += AT_KN) {
        __syncthreads();

        for (int l = t; l < AT_KN * 16; l += 256) {
            int kk = l >> 4, c4 = (l & 15) * 4;
            int src = n0 + kk; if (src > SEQ - 1) src = SEQ - 1;
            st_tf32_4(&Ks[kk * KS_LD + c4], *(const float4*)(ksrc + src * HD + c4));
        }
        __syncthreads();

        float acc_s[3][2][4];
#pragma unroll
        for (int i = 0; i < 3; i++)
#pragma unroll
            for (int j = 0; j < 2; j++)
#pragma unroll
                for (int c = 0; c < 4; c++) acc_s[i][j][c] = 0.f;

#pragma unroll
        for (int ks = 0; ks < 8; ks++) {
            int k0 = ks * 8;
            uint32_t af[3][4], bf[2][2];
#pragma unroll
            for (int i = 0; i < 3; i++) {
                int r = warp_m * 48 + i * 16 + g;
                af[i][0] = __float_as_uint(Qs[r * QS_LD + k0 + tig]);
                af[i][1] = __float_as_uint(Qs[(r + 8) * QS_LD + k0 + tig]);
                af[i][2] = __float_as_uint(Qs[r * QS_LD + k0 + tig + 4]);
                af[i][3] = __float_as_uint(Qs[(r + 8) * QS_LD + k0 + tig + 4]);
            }
#pragma unroll
            for (int j = 0; j < 2; j++) {
                int cix = warp_n * 16 + j * 8 + g;
                bf[j][0] = __float_as_uint(Ks[cix * KS_LD + k0 + tig]);
                bf[j][1] = __float_as_uint(Ks[cix * KS_LD + k0 + tig + 4]);
            }
#pragma unroll
            for (int i = 0; i < 3; i++)
#pragma unroll
                for (int j = 0; j < 2; j++)
                    MMA_TF32(acc_s[i][j], af[i], bf[j]);
        }

#pragma unroll
        for (int i = 0; i < 3; i++) {
            int r0 = warp_m * 48 + i * 16 + g;
#pragma unroll
            for (int j = 0; j < 2; j++) {
                int c0 = warp_n * 16 + j * 8 + 2 * tig;
                bool v0 = (n0 + c0) < SEQ, v1 = (n0 + c0 + 1) < SEQ;
                Ss[r0 * SS_LD + c0]           = v0 ? acc_s[i][j][0] * scale : -1e30f;
                Ss[r0 * SS_LD + c0 + 1]       = v1 ? acc_s[i][j][1] * scale : -1e30f;
                Ss[(r0 + 8) * SS_LD + c0]     = v0 ? acc_s[i][j][2] * scale : -1e30f;
                Ss[(r0 + 8) * SS_LD + c0 + 1] = v1 ? acc_s[i][j][3] * scale : -1e30f;
            }
        }
        __syncthreads();

        {
            int d4 = (t & 15) * 4;
            int kk = t >> 4;
#pragma unroll
            for (int p = 0; p < 4; p++, kk += 16) {
                int src = n0 + kk; if (src > SEQ - 1) src = SEQ - 1;
                float4 v = *(const float4*)(vsrc + src * HD + d4);
                Vs[(d4 + 0) * VS_LD + kk] = __uint_as_float(f2tf32(v.x));
                Vs[(d4 + 1) * VS_LD + kk] = __uint_as_float(f2tf32(v.y));
                Vs[(d4 + 2) * VS_LD + kk] = __uint_as_float(f2tf32(v.z));
                Vs[(d4 + 3) * VS_LD + kk] = __uint_as_float(f2tf32(v.w));
            }
        }
        if (t < AT_M) {
            float* row = Ss + t * SS_LD;
            float mo = s_m[t], mx = mo;
#pragma unroll
            for (int c4 = 0; c4 < AT_KN; c4 += 4) {
                float4 v = *(float4*)(row + c4);
                mx = fmaxf(mx, fmaxf(fmaxf(v.x, v.y), fmaxf(v.z, v.w)));
            }
            float fac = __expf(mo - mx);
            s_f[t] = fac; s_m[t] = mx;
            float sum = 0.f;
#pragma unroll
            for (int c4 = 0; c4 < AT_KN; c4 += 4) {
                float4 v = *(float4*)(row + c4);
                v.x = __expf(v.x - mx); v.y = __expf(v.y - mx);
                v.z = __expf(v.z - mx); v.w = __expf(v.w - mx);
                sum += v.x + v.y + v.z + v.w;
                st_tf32_4(row + c4, v);
            }
            s_l[t] = s_l[t] * fac + sum;
        }
        __syncthreads();

#pragma unroll
        for (int i = 0; i < 3; i++) {
            int r0 = warp_m * 48 + i * 16 + g;
            float f0 = s_f[r0], f1 = s_f[r0 + 8];
#pragma unroll
            for (int j = 0; j < 2; j++) {
                acc_o[i][j][0] *= f0; acc_o[i][j][1] *= f0;
                acc_o[i][j][2] *= f1; acc_o[i][j][3] *= f1;
            }
        }
#pragma unroll
        for (int ks = 0; ks < 8; ks++) {
            int k0 = ks * 8;
            uint32_t af[3][4], bf[2][2];
#pragma unroll
            for (int i = 0; i < 3; i++) {
                int r = warp_m * 48 + i * 16 + g;
                af[i][0] = __float_as_uint(Ss[r * SS_LD + k0 + tig]);
                af[i][1] = __float_as_uint(Ss[(r + 8) * SS_LD + k0 + tig]);
                af[i][2] = __float_as_uint(Ss[r * SS_LD + k0 + tig + 4]);
                af[i][3] = __float_as_uint(Ss[(r + 8) * SS_LD + k0 + tig + 4]);
            }
#pragma unroll
            for (int j = 0; j < 2; j++) {
                int cix = warp_n * 16 + j * 8 + g;
                bf[j][0] = __float_as_uint(Vs[cix * VS_LD + k0 + tig]);
                bf[j][1] = __float_as_uint(Vs[cix * VS_LD + k0 + tig + 4]);
            }
#pragma unroll
            for (int i = 0; i < 3; i++)
#pragma unroll
                for (int j = 0; j < 2; j++)
                    MMA_TF32(acc_o[i][j], af[i], bf[j]);
        }
    }
    __syncthreads();

#pragma unroll
    for (int i = 0; i < 3; i++) {
        int r0 = warp_m * 48 + i * 16 + g;
#pragma unroll
        for (int half = 0; half < 2; half++) {
            int r = r0 + half * 8;
            if (r >= NLOC) continue;
            float inv = 1.f / s_l[r];
            float* dst = g_att + ((size_t)(b * NLOC + r)) * CDIM + h * HD;
#pragma unroll
            for (int j = 0; j < 2; j++) {
                int c0 = warp_n * 16 + j * 8 + 2 * tig;
                float2 o;
                o.x = acc_o[i][j][half * 2 + 0] * inv;
                o.y = acc_o[i][j][half * 2 + 1] * inv;
                *(float2*)(dst + c0) = o;
            }
        }
    }
}

// ---------------- launch ---------------------------------------------------
extern "C" void kernel_launch(void* const* d_in, const int* in_sizes, int n_in,
                              void* d_out, int out_size)
{
    const float* x    = (const float*)d_in[0];
    const float* roll = (const float*)d_in[1];
    const float* Wq   = (const float*)d_in[2];
    const float* bq   = (const float*)d_in[3];
    const float* Wkv  = (const float*)d_in[4];
    const float* bkv  = (const float*)d_in[5];
    const float* Wp   = (const float*)d_in[6];
    const float* bp   = (const float*)d_in[7];
    float* out = (float*)d_out;

    size_t xbytes = (size_t)NB * SEQ * CDIM * sizeof(float);
    const int attn_smem = SMEM_FLOATS * sizeof(float);

    static int s_attr_done = 0;
    if (!s_attr_done) {
        cudaFuncSetAttribute(attn_kernel,
                             cudaFuncAttributeMaxDynamicSharedMemorySize, attn_smem);
        cudaFuncSetAttribute(gemm_tf32<0>,
                             cudaFuncAttributeMaxDynamicSharedMemorySize, G_SMEM_BYTES);
        cudaFuncSetAttribute(gemm_tf32<1>,
                             cudaFuncAttributeMaxDynamicSharedMemorySize, G_SMEM_BYTES);
        cudaFuncSetAttribute(gemm_tf32<2>,
                             cudaFuncAttributeMaxDynamicSharedMemorySize, G_SMEM_BYTES);
        s_attr_done = 1;
    }

    // pass-through copy (scattered rows overwritten at the end)
    cudaMemcpyAsync(out, x, xbytes, cudaMemcpyDeviceToDevice);

    // top-k indices per batch
    topk_kernel<<<NB, 256>>>(roll);

    // KV projection: [50240,768] @ [768,1536] -> g_K/g_V
    {
        int M = NB * SEQ, N = 2 * CDIM, K = CDIM;
        dim3 grid(N / 128, (M + 127) / 128);
        gemm_tf32<0><<<grid, 256, G_SMEM_BYTES>>>(x, Wkv, bkv, nullptr, M, N, K);
    }
    // Q projection (gathered rows): [4992,768] @ [768,768] -> g_Q
    {
        int M = NB * NLOC, N = CDIM, K = CDIM;
        dim3 grid(N / 128, (M + 127) / 128);
        gemm_tf32<1><<<grid, 256, G_SMEM_BYTES>>>(x, Wq, bq, nullptr, M, N, K);
    }
    // fused tensor-core attention -> g_att
    attn_kernel<<<NB * NH, 256, attn_smem>>>();

    // output projection + scatter into out
    {
        int M = NB * NLOC, N = CDIM, K = CDIM;
        dim3 grid(N / 128, (M + 127) / 128);
        gemm_tf32<2><<<grid, 256, G_SMEM_BYTES>>>(nullptr, Wp, bp, out, M, N, K);
    }
}

// round 7
// speedup vs baseline: 3.7276x; 1.2484x over previous
#include <cuda_runtime.h>
#include <cuda_bf16.h>
#include <cstdint>

// Problem constants
#define NB   64      // batch
#define SEQ  785     // tokens
#define CDIM 768     // channels
#define NH   12      // heads
#define HD   64      // head dim
#define NLOC 78      // num_local = int(0.1 * 784)

// ---------------- device scratch (static, no allocations) ----------------
__device__ float g_K[(size_t)NB * NH * SEQ * HD];     // [b][h][n][d]
__device__ float g_V[(size_t)NB * NH * SEQ * HD];     // [b][h][n][d]
__device__ float g_Q[(size_t)NB * NH * NLOC * HD];    // [b][h][j][d]
__device__ float g_att[(size_t)NB * NLOC * CDIM];     // [b*78][768]
__device__ int   g_idx[NB * NLOC];                    // gathered token index (1..784)
__device__ __nv_bfloat16 g_x_bf[(size_t)NB * SEQ * CDIM];     // x in bf16
__device__ __nv_bfloat16 g_Wkv_bt[2 * CDIM * CDIM];           // Wkv^T [1536][768] bf16

// ---------------- top-k by exact rank (matches jax.lax.top_k ties) -------
__global__ __launch_bounds__(256) void topk_kernel(const float* __restrict__ roll)
{
    int b = blockIdx.x;
    __shared__ float v[SEQ - 1];  // 784
    const float* src = roll + (size_t)b * SEQ * SEQ + 1;  // row 0, cols 1..784
    for (int i = threadIdx.x; i < SEQ - 1; i += 256) v[i] = src[i];
    __syncthreads();
    for (int i = threadIdx.x; i < SEQ - 1; i += 256) {
        float vi = v[i];
        int rank = 0;
        for (int j = 0; j < SEQ - 1; j++) {
            float vj = v[j];
            rank += (vj > vi) || (vj == vi && j < i);
        }
        if (rank < NLOC) g_idx[b * NLOC + rank] = i + 1;
    }
}

// ---------------- fp32 -> bf16 convert (x) --------------------------------
__global__ __launch_bounds__(256) void conv_x_kernel(const float* __restrict__ src)
{
    size_t n4 = (size_t)NB * SEQ * CDIM / 4;
    size_t stride = (size_t)gridDim.x * blockDim.x;
    for (size_t i = (size_t)blockIdx.x * blockDim.x + threadIdx.x; i < n4; i += stride) {
        float4 v = *(const float4*)(src + i * 4);
        __nv_bfloat16 o[4];
        o[0] = __float2bfloat16_rn(v.x);
        o[1] = __float2bfloat16_rn(v.y);
        o[2] = __float2bfloat16_rn(v.z);
        o[3] = __float2bfloat16_rn(v.w);
        *(uint2*)(g_x_bf + i * 4) = *(uint2*)o;
    }
}

// ---------------- transpose + convert: Wkv [768][1536] -> bf16 [1536][768]
__global__ void convt_wkv_kernel(const float* __restrict__ src)
{
    __shared__ float t[32][33];
    const int R = CDIM, C = 2 * CDIM;
    int c0 = blockIdx.x * 32, r0 = blockIdx.y * 32;
    int x = threadIdx.x, y = threadIdx.y;   // 32 x 8
    for (int i = y; i < 32; i += 8) t[i][x] = src[(size_t)(r0 + i) * C + c0 + x];
    __syncthreads();
    for (int i = y; i < 32; i += 8)
        g_Wkv_bt[(size_t)(c0 + i) * R + r0 + x] = __float2bfloat16_rn(t[x][i]);
}

// ---------------- TF32 helpers --------------------------------------------
__device__ __forceinline__ uint32_t f2tf32(float f) {
    uint32_t u;
    asm("cvt.rna.tf32.f32 %0, %1;" : "=r"(u) : "f"(f));
    return u;
}
__device__ __forceinline__ void st_tf32_4(float* dst, float4 v) {
    float4 o;
    o.x = __uint_as_float(f2tf32(v.x));
    o.y = __uint_as_float(f2tf32(v.y));
    o.z = __uint_as_float(f2tf32(v.z));
    o.w = __uint_as_float(f2tf32(v.w));
    *(float4*)dst = o;
}

#define MMA_TF32(C, A, B)                                                     \
    asm volatile(                                                             \
        "mma.sync.aligned.m16n8k8.row.col.f32.tf32.tf32.f32 "                 \
        "{%0,%1,%2,%3}, {%4,%5,%6,%7}, {%8,%9}, {%0,%1,%2,%3};"               \
        : "+f"((C)[0]), "+f"((C)[1]), "+f"((C)[2]), "+f"((C)[3])              \
        : "r"((A)[0]), "r"((A)[1]), "r"((A)[2]), "r"((A)[3]),                 \
          "r"((B)[0]), "r"((B)[1]))

#define MMA_BF16(C, A, B)                                                     \
    asm volatile(                                                             \
        "mma.sync.aligned.m16n8k16.row.col.f32.bf16.bf16.f32 "                \
        "{%0,%1,%2,%3}, {%4,%5,%6,%7}, {%8,%9}, {%0,%1,%2,%3};"               \
        : "+f"((C)[0]), "+f"((C)[1]), "+f"((C)[2]), "+f"((C)[3])              \
        : "r"((A)[0]), "r"((A)[1]), "r"((A)[2]), "r"((A)[3]),                 \
          "r"((B)[0]), "r"((B)[1]))

__device__ __forceinline__ void cp16(uint32_t s, const void* g) {
    asm volatile("cp.async.cg.shared.global [%0], [%1], 16;" :: "r"(s), "l"(g));
}
#define CP_COMMIT()  asm volatile("cp.async.commit_group;")
#define CP_WAIT(n)   asm volatile("cp.async.wait_group %0;" :: "n"(n))

// ---------------- bf16 GEMM (KV projection), 128x128x32, 3-stage ----------
// A = g_x_bf [50240][768], B = g_Wkv_bt [1536][768] (n-major, k contiguous)
// C -> split into g_K / g_V
#define BF_PITCH 40                       // bf16 per smem row (32 + 8 pad)
#define BF_AROWS 128
#define BF_STAGE (2 * BF_AROWS * BF_PITCH)        // bf16 elems per stage (A+B)
#define BF_ST    3
#define BF_SMEM_BYTES (BF_ST * BF_STAGE * 2)      // 61440

__global__ __launch_bounds__(256, 2) void gemm_bf16_kv(const float* __restrict__ bias)
{
    const int M = NB * SEQ, K = CDIM;
    const int BK = 32;
    extern __shared__ __nv_bfloat16 smb[];
    uint32_t smem_u32 = (uint32_t)__cvta_generic_to_shared(smb);

    int t = threadIdx.x;
    int wid = t >> 5, lane = t & 31;
    int warp_m = wid & 1, warp_n = wid >> 1;   // 2 x 4
    int g = lane >> 2, tig = lane & 3;
    int bc = blockIdx.x, br = blockIdx.y;

    // loaders: 2 tasks each for A and B; task = p*256+t -> row (0..127), chunk (0..3)
    const __nv_bfloat16* arow[2];
    const __nv_bfloat16* brow[2];
    uint32_t soff[2];
#pragma unroll
    for (int p = 0; p < 2; p++) {
        int task = p * 256 + t;
        int r = task >> 2, ch = task & 3;
        int am = br * BF_AROWS + r;
        int cm = am < M ? am : M - 1;
        arow[p] = g_x_bf + (size_t)cm * K + ch * 8;
        int bn = bc * 128 + r;
        brow[p] = g_Wkv_bt + (size_t)bn * K + ch * 8;
        soff[p] = (uint32_t)(r * BF_PITCH + ch * 8) * 2;  // bytes
    }
    const uint32_t BOFF = BF_AROWS * BF_PITCH * 2;        // B area offset in stage

    // prologue: stages 0,1
#pragma unroll
    for (int s = 0; s < 2; s++) {
        uint32_t sb = smem_u32 + s * BF_STAGE * 2;
#pragma unroll
        for (int p = 0; p < 2; p++) {
            cp16(sb + soff[p], arow[p] + s * BK);
            cp16(sb + BOFF + soff[p], brow[p] + s * BK);
        }
        CP_COMMIT();
    }

    float acc[4][4][4];
#pragma unroll
    for (int i = 0; i < 4; i++)
#pragma unroll
        for (int j = 0; j < 4; j++)
#pragma unroll
            for (int c = 0; c < 4; c++) acc[i][j][c] = 0.f;

    const int nk = K / BK;   // 24
    int st = 0;
    for (int kt = 0; kt < nk; kt++) {
        CP_WAIT(1);
        __syncthreads();

        int nxt = kt + 2;
        if (nxt < nk) {
            uint32_t sb = smem_u32 + (nxt % BF_ST) * BF_STAGE * 2;
#pragma unroll
            for (int p = 0; p < 2; p++) {
                cp16(sb + soff[p], arow[p] + nxt * BK);
                cp16(sb + BOFF + soff[p], brow[p] + nxt * BK);
            }
        }
        CP_COMMIT();

        const uint32_t* As32 = (const uint32_t*)(smb + st * BF_STAGE);
        const uint32_t* Bs32 = As32 + BF_AROWS * BF_PITCH / 2;
        const int PW = BF_PITCH / 2;   // 20 words per row

#pragma unroll
        for (int ks = 0; ks < 2; ks++) {    // two k16 steps per BK=32
            int kb = ks * 8;                // word base
            uint32_t af[4][4], bf[4][2];
#pragma unroll
            for (int i = 0; i < 4; i++) {
                int r = warp_m * 64 + i * 16 + g;
                af[i][0] = As32[r * PW + kb + tig];
                af[i][1] = As32[(r + 8) * PW + kb + tig];
                af[i][2] = As32[r * PW + kb + 4 + tig];
                af[i][3] = As32[(r + 8) * PW + kb + 4 + tig];
            }
#pragma unroll
            for (int j = 0; j < 4; j++) {
                int cix = warp_n * 32 + j * 8 + g;
                bf[j][0] = Bs32[cix * PW + kb + tig];
                bf[j][1] = Bs32[cix * PW + kb + 4 + tig];
            }
#pragma unroll
            for (int i = 0; i < 4; i++)
#pragma unroll
                for (int j = 0; j < 4; j++)
                    MMA_BF16(acc[i][j], af[i], bf[j]);
        }
        st = (st + 1 == BF_ST) ? 0 : st + 1;
        __syncthreads();
    }

    // epilogue: split into g_K / g_V
#pragma unroll
    for (int i = 0; i < 4; i++) {
        int mbase = br * BF_AROWS + warp_m * 64 + i * 16 + g;
#pragma unroll
        for (int half = 0; half < 2; half++) {
            int m = mbase + half * 8;
            if (m >= M) continue;
            int bb = m / SEQ, nn = m % SEQ;
#pragma unroll
            for (int j = 0; j < 4; j++) {
                int n0 = bc * 128 + warp_n * 32 + j * 8 + 2 * tig;
#pragma unroll
                for (int e = 0; e < 2; e++) {
                    int n = n0 + e;
                    float val = acc[i][j][half * 2 + e] + bias[n];
                    int nc = (n < CDIM) ? n : n - CDIM;
                    float* dst = (n < CDIM) ? g_K : g_V;
                    dst[(((size_t)bb * NH + (nc >> 6)) * SEQ + nn) * HD + (nc & 63)] = val;
                }
            }
        }
    }
}

// ---------------- TF32 GEMM, 128x128x16, 3-stage cp.async pipeline --------
// MODE 1: A = x gathered rows; C -> g_Q
// MODE 2: A = g_att direct;    C -> scatter rows of d_out via g_idx
#define G_APAD 20
#define G_BPAD 136
#define G_AFL  (128 * G_APAD)
#define G_BFL  (16 * G_BPAD)
#define G_STG  (G_AFL + G_BFL)
#define G_ST   3
#define G_SMEM_BYTES (G_ST * G_STG * 4)

template <int MODE>
__global__ __launch_bounds__(256, 2) void gemm_tf32(
    const float* __restrict__ A, const float* __restrict__ B,
    const float* __restrict__ bias, float* __restrict__ C,
    int M, int N, int K)
{
    const int BM = 128, BN = 128, BK = 16;
    extern __shared__ float sm[];
    uint32_t smem_u32 = (uint32_t)__cvta_generic_to_shared(sm);

    int tid = threadIdx.x;
    int wid = tid >> 5, lane = tid & 31;
    int warp_m = wid & 1, warp_n = wid >> 1;
    int g = lane >> 2, tig = lane & 3;

    int bc = blockIdx.x, br = blockIdx.y;

    const float* Ap = (MODE == 2) ? (const float*)g_att : A;

    int ar  = tid >> 2;
    int acl = (tid & 3) * 4;
    int am0 = br * BM + ar;
    int am1 = am0 + 64;
    int cm0 = am0 < M ? am0 : M - 1;
    int cm1 = am1 < M ? am1 : M - 1;
    const float *Arow0, *Arow1;
    if (MODE == 1) {
        int b0 = cm0 / NLOC;
        int b1 = cm1 / NLOC;
        Arow0 = Ap + ((size_t)(b0 * SEQ + g_idx[cm0])) * K + acl;
        Arow1 = Ap + ((size_t)(b1 * SEQ + g_idx[cm1])) * K + acl;
    } else {
        Arow0 = Ap + (size_t)cm0 * K + acl;
        Arow1 = Ap + (size_t)cm1 * K + acl;
    }

    int brw = tid >> 5;
    int bcl = (tid & 31) * 4;
    const float* Bp0 = B + (size_t)brw * N + bc * BN + bcl;
    const float* Bp1 = Bp0 + (size_t)8 * N;

    uint32_t sA = smem_u32 + (uint32_t)(ar * G_APAD + acl) * 4;
    uint32_t sB = smem_u32 + (uint32_t)(G_AFL + brw * G_BPAD + bcl) * 4;

    int nk = K / BK;

#pragma unroll
    for (int p = 0; p < G_ST - 1; p++) {
        uint32_t so = (uint32_t)(p * G_STG) * 4;
        cp16(sA + so, Arow0 + p * BK);
        cp16(sA + so + 64 * G_APAD * 4, Arow1 + p * BK);
        cp16(sB + so, Bp0 + (size_t)p * BK * N);
        cp16(sB + so + 8 * G_BPAD * 4, Bp1 + (size_t)p * BK * N);
        CP_COMMIT();
    }

    float acc[4][4][4];
#pragma unroll
    for (int i = 0; i < 4; i++)
#pragma unroll
        for (int j = 0; j < 4; j++)
#pragma unroll
            for (int c = 0; c < 4; c++) acc[i][j][c] = 0.f;

    int st = 0;
    for (int kt = 0; kt < nk; kt++) {
        CP_WAIT(G_ST - 2);
        __syncthreads();

        int nxt = kt + G_ST - 1;
        if (nxt < nk) {
            int stn = nxt % G_ST;
            uint32_t so = (uint32_t)(stn * G_STG) * 4;
            cp16(sA + so, Arow0 + nxt * BK);
            cp16(sA + so + 64 * G_APAD * 4, Arow1 + nxt * BK);
            cp16(sB + so, Bp0 + (size_t)nxt * BK * N);
            cp16(sB + so + 8 * G_BPAD * 4, Bp1 + (size_t)nxt * BK * N);
        }
        CP_COMMIT();

        const float* As = sm + st * G_STG;
        const float* Bs = As + G_AFL;

#pragma unroll
        for (int ks = 0; ks < 2; ks++) {
            int k0 = ks * 8;
            uint32_t af[4][4];
            uint32_t bf[4][2];
#pragma unroll
            for (int i = 0; i < 4; i++) {
                int r = warp_m * 64 + i * 16 + g;
                af[i][0] = __float_as_uint(As[r * G_APAD + k0 + tig]);
                af[i][1] = __float_as_uint(As[(r + 8) * G_APAD + k0 + tig]);
                af[i][2] = __float_as_uint(As[r * G_APAD + k0 + tig + 4]);
                af[i][3] = __float_as_uint(As[(r + 8) * G_APAD + k0 + tig + 4]);
            }
#pragma unroll
            for (int j = 0; j < 4; j++) {
                int cix = warp_n * 32 + j * 8 + g;
                bf[j][0] = __float_as_uint(Bs[(k0 + tig) * G_BPAD + cix]);
                bf[j][1] = __float_as_uint(Bs[(k0 + tig + 4) * G_BPAD + cix]);
            }
#pragma unroll
            for (int i = 0; i < 4; i++)
#pragma unroll
                for (int j = 0; j < 4; j++)
                    MMA_TF32(acc[i][j], af[i], bf[j]);
        }
        st = (st + 1 == G_ST) ? 0 : st + 1;
    }

    // epilogue
#pragma unroll
    for (int i = 0; i < 4; i++) {
        int mbase = br * BM + warp_m * 64 + i * 16 + g;
#pragma unroll
        for (int half = 0; half < 2; half++) {
            int m = mbase + half * 8;
            if (m >= M) continue;
            if (MODE == 1) {
                int bb = m / NLOC, jj = m % NLOC;
#pragma unroll
                for (int j = 0; j < 4; j++) {
                    int n0 = bc * BN + warp_n * 32 + j * 8 + 2 * tig;
#pragma unroll
                    for (int e = 0; e < 2; e++) {
                        int n = n0 + e;
                        float val = acc[i][j][half * 2 + e] + bias[n];
                        g_Q[(((size_t)bb * NH + (n >> 6)) * NLOC + jj) * HD + (n & 63)] = val;
                    }
                }
            } else {
                int bb = m / NLOC;
                int row = bb * SEQ + g_idx[m];
                float* crow = C + (size_t)row * CDIM;
#pragma unroll
                for (int j = 0; j < 4; j++) {
                    int n0 = bc * BN + warp_n * 32 + j * 8 + 2 * tig;
                    crow[n0]     = acc[i][j][half * 2 + 0] + bias[n0];
                    crow[n0 + 1] = acc[i][j][half * 2 + 1] + bias[n0 + 1];
                }
            }
        }
    }
}

// ---------------- TF32 tensor-core flash attention per (b,h) --------------
#define AT_M   96
#define AT_KN  64
#define QS_LD  68
#define KS_LD  68
#define VS_LD  65
#define SS_LD  68

#define OFF_Q   0
#define OFF_KV  (AT_M * QS_LD)
#define OFF_S   (OFF_KV + AT_KN * KS_LD)
#define OFF_M   (OFF_S + AT_M * SS_LD)
#define OFF_L   (OFF_M + AT_M)
#define OFF_F   (OFF_L + AT_M)
#define SMEM_FLOATS (OFF_F + AT_M)

__global__ __launch_bounds__(256, 2) void attn_kernel()
{
    extern __shared__ float sm[];
    float* Qs  = sm + OFF_Q;
    float* Ks  = sm + OFF_KV;
    float* Vs  = sm + OFF_KV;
    float* Ss  = sm + OFF_S;
    float* s_m = sm + OFF_M;
    float* s_l = sm + OFF_L;
    float* s_f = sm + OFF_F;

    int bh = blockIdx.x;
    int b = bh / NH, h = bh % NH;
    int t = threadIdx.x;
    int wid = t >> 5, lane = t & 31;
    int warp_m = wid & 1, warp_n = wid >> 1;
    int g = lane >> 2, tig = lane & 3;

    const float* qsrc = g_Q + (size_t)bh * NLOC * HD;
    const float* ksrc = g_K + (size_t)bh * SEQ * HD;
    const float* vsrc = g_V + (size_t)bh * SEQ * HD;

    for (int l = t; l < AT_M * 16; l += 256) {
        int r = l >> 4, c4 = (l & 15) * 4;
        float4 v = (r < NLOC) ? *(const float4*)(qsrc + r * HD + c4)
                              : make_float4(0.f, 0.f, 0.f, 0.f);
        st_tf32_4(&Qs[r * QS_LD + c4], v);
    }
    if (t < AT_M) { s_m[t] = -1e30f; s_l[t] = 0.f; }

    float acc_o[3][2][4];
#pragma unroll
    for (int i = 0; i < 3; i++)
#pragma unroll
        for (int j = 0; j < 2; j++)
#pragma unroll
            for (int c = 0; c < 4; c++) acc_o[i][j][c] = 0.f;

    const float scale = 0.125f;

    for (int n0 = 0; n0 < SEQ; n0 += AT_KN) {
        __syncthreads();

        for (int l = t; l < AT_KN * 16; l += 256) {
            int kk = l >> 4, c4 = (l & 15) * 4;
            int src = n0 + kk; if (src > SEQ - 1) src = SEQ - 1;
            st_tf32_4(&Ks[kk * KS_LD + c4], *(const float4*)(ksrc + src * HD + c4));
        }
        __syncthreads();

        float acc_s[3][2][4];
#pragma unroll
        for (int i = 0; i < 3; i++)
#pragma unroll
            for (int j = 0; j < 2; j++)
#pragma unroll
                for (int c = 0; c < 4; c++) acc_s[i][j][c] = 0.f;

#pragma unroll
        for (int ks = 0; ks < 8; ks++) {
            int k0 = ks * 8;
            uint32_t af[3][4], bf[2][2];
#pragma unroll
            for (int i = 0; i < 3; i++) {
                int r = warp_m * 48 + i * 16 + g;
                af[i][0] = __float_as_uint(Qs[r * QS_LD + k0 + tig]);
                af[i][1] = __float_as_uint(Qs[(r + 8) * QS_LD + k0 + tig]);
                af[i][2] = __float_as_uint(Qs[r * QS_LD + k0 + tig + 4]);
                af[i][3] = __float_as_uint(Qs[(r + 8) * QS_LD + k0 + tig + 4]);
            }
#pragma unroll
            for (int j = 0; j < 2; j++) {
                int cix = warp_n * 16 + j * 8 + g;
                bf[j][0] = __float_as_uint(Ks[cix * KS_LD + k0 + tig]);
                bf[j][1] = __float_as_uint(Ks[cix * KS_LD + k0 + tig + 4]);
            }
#pragma unroll
            for (int i = 0; i < 3; i++)
#pragma unroll
                for (int j = 0; j < 2; j++)
                    MMA_TF32(acc_s[i][j], af[i], bf[j]);
        }

#pragma unroll
        for (int i = 0; i < 3; i++) {
            int r0 = warp_m * 48 + i * 16 + g;
#pragma unroll
            for (int j = 0; j < 2; j++) {
                int c0 = warp_n * 16 + j * 8 + 2 * tig;
                bool v0 = (n0 + c0) < SEQ, v1 = (n0 + c0 + 1) < SEQ;
                Ss[r0 * SS_LD + c0]           = v0 ? acc_s[i][j][0] * scale : -1e30f;
                Ss[r0 * SS_LD + c0 + 1]       = v1 ? acc_s[i][j][1] * scale : -1e30f;
                Ss[(r0 + 8) * SS_LD + c0]     = v0 ? acc_s[i][j][2] * scale : -1e30f;
                Ss[(r0 + 8) * SS_LD + c0 + 1] = v1 ? acc_s[i][j][3] * scale : -1e30f;
            }
        }
        __syncthreads();

        {
            int d4 = (t & 15) * 4;
            int kk = t >> 4;
#pragma unroll
            for (int p = 0; p < 4; p++, kk += 16) {
                int src = n0 + kk; if (src > SEQ - 1) src = SEQ - 1;
                float4 v = *(const float4*)(vsrc + src * HD + d4);
                Vs[(d4 + 0) * VS_LD + kk] = __uint_as_float(f2tf32(v.x));
                Vs[(d4 + 1) * VS_LD + kk] = __uint_as_float(f2tf32(v.y));
                Vs[(d4 + 2) * VS_LD + kk] = __uint_as_float(f2tf32(v.z));
                Vs[(d4 + 3) * VS_LD + kk] = __uint_as_float(f2tf32(v.w));
            }
        }
        if (t < AT_M) {
            float* row = Ss + t * SS_LD;
            float mo = s_m[t], mx = mo;
#pragma unroll
            for (int c4 = 0; c4 < AT_KN; c4 += 4) {
                float4 v = *(float4*)(row + c4);
                mx = fmaxf(mx, fmaxf(fmaxf(v.x, v.y), fmaxf(v.z, v.w)));
            }
            float fac = __expf(mo - mx);
            s_f[t] = fac; s_m[t] = mx;
            float sum = 0.f;
#pragma unroll
            for (int c4 = 0; c4 < AT_KN; c4 += 4) {
                float4 v = *(float4*)(row + c4);
                v.x = __expf(v.x - mx); v.y = __expf(v.y - mx);
                v.z = __expf(v.z - mx); v.w = __expf(v.w - mx);
                sum += v.x + v.y + v.z + v.w;
                st_tf32_4(row + c4, v);
            }
            s_l[t] = s_l[t] * fac + sum;
        }
        __syncthreads();

#pragma unroll
        for (int i = 0; i < 3; i++) {
            int r0 = warp_m * 48 + i * 16 + g;
            float f0 = s_f[r0], f1 = s_f[r0 + 8];
#pragma unroll
            for (int j = 0; j < 2; j++) {
                acc_o[i][j][0] *= f0; acc_o[i][j][1] *= f0;
                acc_o[i][j][2] *= f1; acc_o[i][j][3] *= f1;
            }
        }
#pragma unroll
        for (int ks = 0; ks < 8; ks++) {
            int k0 = ks * 8;
            uint32_t af[3][4], bf[2][2];
#pragma unroll
            for (int i = 0; i < 3; i++) {
                int r = warp_m * 48 + i * 16 + g;
                af[i][0] = __float_as_uint(Ss[r * SS_LD + k0 + tig]);
                af[i][1] = __float_as_uint(Ss[(r + 8) * SS_LD + k0 + tig]);
                af[i][2] = __float_as_uint(Ss[r * SS_LD + k0 + tig + 4]);
                af[i][3] = __float_as_uint(Ss[(r + 8) * SS_LD + k0 + tig + 4]);
            }
#pragma unroll
            for (int j = 0; j < 2; j++) {
                int cix = warp_n * 16 + j * 8 + g;
                bf[j][0] = __float_as_uint(Vs[cix * VS_LD + k0 + tig]);
                bf[j][1] = __float_as_uint(Vs[cix * VS_LD + k0 + tig + 4]);
            }
#pragma unroll
            for (int i = 0; i < 3; i++)
#pragma unroll
                for (int j = 0; j < 2; j++)
                    MMA_TF32(acc_o[i][j], af[i], bf[j]);
        }
    }
    __syncthreads();

#pragma unroll
    for (int i = 0; i < 3; i++) {
        int r0 = warp_m * 48 + i * 16 + g;
#pragma unroll
        for (int half = 0; half < 2; half++) {
            int r = r0 + half * 8;
            if (r >= NLOC) continue;
            float inv = 1.f / s_l[r];
            float* dst = g_att + ((size_t)(b * NLOC + r)) * CDIM + h * HD;
#pragma unroll
            for (int j = 0; j < 2; j++) {
                int c0 = warp_n * 16 + j * 8 + 2 * tig;
                float2 o;
                o.x = acc_o[i][j][half * 2 + 0] * inv;
                o.y = acc_o[i][j][half * 2 + 1] * inv;
                *(float2*)(dst + c0) = o;
            }
        }
    }
}

// ---------------- launch ---------------------------------------------------
extern "C" void kernel_launch(void* const* d_in, const int* in_sizes, int n_in,
                              void* d_out, int out_size)
{
    const float* x    = (const float*)d_in[0];
    const float* roll = (const float*)d_in[1];
    const float* Wq   = (const float*)d_in[2];
    const float* bq   = (const float*)d_in[3];
    const float* Wkv  = (const float*)d_in[4];
    const float* bkv  = (const float*)d_in[5];
    const float* Wp   = (const float*)d_in[6];
    const float* bp   = (const float*)d_in[7];
    float* out = (float*)d_out;

    size_t xbytes = (size_t)NB * SEQ * CDIM * sizeof(float);
    const int attn_smem = SMEM_FLOATS * sizeof(float);

    static int s_attr_done = 0;
    if (!s_attr_done) {
        cudaFuncSetAttribute(attn_kernel,
                             cudaFuncAttributeMaxDynamicSharedMemorySize, attn_smem);
        cudaFuncSetAttribute(gemm_bf16_kv,
                             cudaFuncAttributeMaxDynamicSharedMemorySize, BF_SMEM_BYTES);
        cudaFuncSetAttribute(gemm_tf32<1>,
                             cudaFuncAttributeMaxDynamicSharedMemorySize, G_SMEM_BYTES);
        cudaFuncSetAttribute(gemm_tf32<2>,
                             cudaFuncAttributeMaxDynamicSharedMemorySize, G_SMEM_BYTES);
        s_attr_done = 1;
    }

    // pass-through copy (scattered rows overwritten at the end)
    cudaMemcpyAsync(out, x, xbytes, cudaMemcpyDeviceToDevice);

    // conversions for the bf16 KV GEMM
    conv_x_kernel<<<512, 256>>>(x);
    convt_wkv_kernel<<<dim3(2 * CDIM / 32, CDIM / 32), dim3(32, 8)>>>(Wkv);

    // top-k indices per batch
    topk_kernel<<<NB, 256>>>(roll);

    // KV projection (bf16): [50240,768] @ [768,1536] -> g_K/g_V
    {
        int M = NB * SEQ;
        dim3 grid((2 * CDIM) / 128, (M + 127) / 128);
        gemm_bf16_kv<<<grid, 256, BF_SMEM_BYTES>>>(bkv);
    }
    // Q projection (tf32, gathered rows): [4992,768] @ [768,768] -> g_Q
    {
        int M = NB * NLOC, N = CDIM, K = CDIM;
        dim3 grid(N / 128, (M + 127) / 128);
        gemm_tf32<1><<<grid, 256, G_SMEM_BYTES>>>(x, Wq, bq, nullptr, M, N, K);
    }
    // fused tensor-core attention -> g_att
    attn_kernel<<<NB * NH, 256, attn_smem>>>();

    // output projection + scatter into out (tf32)
    {
        int M = NB * NLOC, N = CDIM, K = CDIM;
        dim3 grid(N / 128, (M + 127) / 128);
        gemm_tf32<2><<<grid, 256, G_SMEM_BYTES>>>(nullptr, Wp, bp, out, M, N, K);
    }
}

// round 8
// speedup vs baseline: 3.7324x; 1.0013x over previous
#include <cuda_runtime.h>
#include <cuda_bf16.h>
#include <cstdint>

// Problem constants
#define NB   64      // batch
#define SEQ  785     // tokens
#define CDIM 768     // channels
#define NH   12      // heads
#define HD   64      // head dim
#define NLOC 78      // num_local = int(0.1 * 784)

// ---------------- device scratch (static, no allocations) ----------------
__device__ float g_K[(size_t)NB * NH * SEQ * HD];     // [b][h][n][d]
__device__ float g_V[(size_t)NB * NH * SEQ * HD];     // [b][h][n][d]
__device__ float g_Q[(size_t)NB * NH * NLOC * HD];    // [b][h][j][d]
__device__ float g_att[(size_t)NB * NLOC * CDIM];     // [b*78][768]
__device__ int   g_idx[NB * NLOC];                    // gathered token index (1..784)
__device__ __nv_bfloat16 g_x_bf[(size_t)NB * SEQ * CDIM];     // x in bf16
__device__ __nv_bfloat16 g_Wkv_bt[2 * CDIM * CDIM];           // Wkv^T [1536][768] bf16

// ---------------- top-k by exact rank (matches jax.lax.top_k ties) -------
__global__ __launch_bounds__(256) void topk_kernel(const float* __restrict__ roll)
{
    int b = blockIdx.x;
    __shared__ float v[SEQ - 1];  // 784
    const float* src = roll + (size_t)b * SEQ * SEQ + 1;  // row 0, cols 1..784
    for (int i = threadIdx.x; i < SEQ - 1; i += 256) v[i] = src[i];
    __syncthreads();
    for (int i = threadIdx.x; i < SEQ - 1; i += 256) {
        float vi = v[i];
        int rank = 0;
        for (int j = 0; j < SEQ - 1; j++) {
            float vj = v[j];
            rank += (vj > vi) || (vj == vi && j < i);
        }
        if (rank < NLOC) g_idx[b * NLOC + rank] = i + 1;
    }
}

// ---------------- fp32 -> bf16 convert (x) --------------------------------
__global__ __launch_bounds__(256) void conv_x_kernel(const float* __restrict__ src)
{
    size_t n4 = (size_t)NB * SEQ * CDIM / 4;
    size_t stride = (size_t)gridDim.x * blockDim.x;
    for (size_t i = (size_t)blockIdx.x * blockDim.x + threadIdx.x; i < n4; i += stride) {
        float4 v = *(const float4*)(src + i * 4);
        __nv_bfloat16 o[4];
        o[0] = __float2bfloat16_rn(v.x);
        o[1] = __float2bfloat16_rn(v.y);
        o[2] = __float2bfloat16_rn(v.z);
        o[3] = __float2bfloat16_rn(v.w);
        *(uint2*)(g_x_bf + i * 4) = *(uint2*)o;
    }
}

// ---------------- transpose + convert: Wkv [768][1536] -> bf16 [1536][768]
__global__ void convt_wkv_kernel(const float* __restrict__ src)
{
    __shared__ float t[32][33];
    const int R = CDIM, C = 2 * CDIM;
    int c0 = blockIdx.x * 32, r0 = blockIdx.y * 32;
    int x = threadIdx.x, y = threadIdx.y;   // 32 x 8
    for (int i = y; i < 32; i += 8) t[i][x] = src[(size_t)(r0 + i) * C + c0 + x];
    __syncthreads();
    for (int i = y; i < 32; i += 8)
        g_Wkv_bt[(size_t)(c0 + i) * R + r0 + x] = __float2bfloat16_rn(t[x][i]);
}

// ---------------- TF32 helpers --------------------------------------------
__device__ __forceinline__ uint32_t f2tf32(float f) {
    uint32_t u;
    asm("cvt.rna.tf32.f32 %0, %1;" : "=r"(u) : "f"(f));
    return u;
}
__device__ __forceinline__ void st_tf32_4(float* dst, float4 v) {
    float4 o;
    o.x = __uint_as_float(f2tf32(v.x));
    o.y = __uint_as_float(f2tf32(v.y));
    o.z = __uint_as_float(f2tf32(v.z));
    o.w = __uint_as_float(f2tf32(v.w));
    *(float4*)dst = o;
}

#define MMA_TF32(C, A, B)                                                     \
    asm volatile(                                                             \
        "mma.sync.aligned.m16n8k8.row.col.f32.tf32.tf32.f32 "                 \
        "{%0,%1,%2,%3}, {%4,%5,%6,%7}, {%8,%9}, {%0,%1,%2,%3};"               \
        : "+f"((C)[0]), "+f"((C)[1]), "+f"((C)[2]), "+f"((C)[3])              \
        : "r"((A)[0]), "r"((A)[1]), "r"((A)[2]), "r"((A)[3]),                 \
          "r"((B)[0]), "r"((B)[1]))

#define MMA_BF16(C, A, B)                                                     \
    asm volatile(                                                             \
        "mma.sync.aligned.m16n8k16.row.col.f32.bf16.bf16.f32 "                \
        "{%0,%1,%2,%3}, {%4,%5,%6,%7}, {%8,%9}, {%0,%1,%2,%3};"               \
        : "+f"((C)[0]), "+f"((C)[1]), "+f"((C)[2]), "+f"((C)[3])              \
        : "r"((A)[0]), "r"((A)[1]), "r"((A)[2]), "r"((A)[3]),                 \
          "r"((B)[0]), "r"((B)[1]))

__device__ __forceinline__ void cp16(uint32_t s, const void* g) {
    asm volatile("cp.async.cg.shared.global [%0], [%1], 16;" :: "r"(s), "l"(g));
}
#define CP_COMMIT()  asm volatile("cp.async.commit_group;")
#define CP_WAIT(n)   asm volatile("cp.async.wait_group %0;" :: "n"(n))

// ---------------- bf16 GEMM (KV projection), 128x128x32, 3-stage ----------
// A = g_x_bf [50240][768], B = g_Wkv_bt [1536][768] (n-major, k contiguous)
// C -> split into g_K / g_V
#define BF_PITCH 40                       // bf16 per smem row (32 + 8 pad)
#define BF_AROWS 128
#define BF_STAGE (2 * BF_AROWS * BF_PITCH)        // bf16 elems per stage (A+B)
#define BF_ST    3
#define BF_SMEM_BYTES (BF_ST * BF_STAGE * 2)      // 61440

__global__ __launch_bounds__(256, 2) void gemm_bf16_kv(const float* __restrict__ bias)
{
    const int M = NB * SEQ, K = CDIM;
    const int BK = 32;
    extern __shared__ __nv_bfloat16 smb[];
    uint32_t smem_u32 = (uint32_t)__cvta_generic_to_shared(smb);

    int t = threadIdx.x;
    int wid = t >> 5, lane = t & 31;
    int warp_m = wid & 1, warp_n = wid >> 1;   // 2 x 4
    int g = lane >> 2, tig = lane & 3;
    int bc = blockIdx.x, br = blockIdx.y;

    // loaders: 2 tasks each for A and B; task = p*256+t -> row (0..127), chunk (0..3)
    const __nv_bfloat16* arow[2];
    const __nv_bfloat16* brow[2];
    uint32_t soff[2];
#pragma unroll
    for (int p = 0; p < 2; p++) {
        int task = p * 256 + t;
        int r = task >> 2, ch = task & 3;
        int am = br * BF_AROWS + r;
        int cm = am < M ? am : M - 1;
        arow[p] = g_x_bf + (size_t)cm * K + ch * 8;
        int bn = bc * 128 + r;
        brow[p] = g_Wkv_bt + (size_t)bn * K + ch * 8;
        soff[p] = (uint32_t)(r * BF_PITCH + ch * 8) * 2;  // bytes
    }
    const uint32_t BOFF = BF_AROWS * BF_PITCH * 2;        // B area offset in stage

    // prologue: stages 0,1
#pragma unroll
    for (int s = 0; s < 2; s++) {
        uint32_t sb = smem_u32 + s * BF_STAGE * 2;
#pragma unroll
        for (int p = 0; p < 2; p++) {
            cp16(sb + soff[p], arow[p] + s * BK);
            cp16(sb + BOFF + soff[p], brow[p] + s * BK);
        }
        CP_COMMIT();
    }

    float acc[4][4][4];
#pragma unroll
    for (int i = 0; i < 4; i++)
#pragma unroll
        for (int j = 0; j < 4; j++)
#pragma unroll
            for (int c = 0; c < 4; c++) acc[i][j][c] = 0.f;

    const int nk = K / BK;   // 24
    int st = 0;
    for (int kt = 0; kt < nk; kt++) {
        CP_WAIT(1);
        __syncthreads();

        int nxt = kt + 2;
        if (nxt < nk) {
            uint32_t sb = smem_u32 + (nxt % BF_ST) * BF_STAGE * 2;
#pragma unroll
            for (int p = 0; p < 2; p++) {
                cp16(sb + soff[p], arow[p] + nxt * BK);
                cp16(sb + BOFF + soff[p], brow[p] + nxt * BK);
            }
        }
        CP_COMMIT();

        const uint32_t* As32 = (const uint32_t*)(smb + st * BF_STAGE);
        const uint32_t* Bs32 = As32 + BF_AROWS * BF_PITCH / 2;
        const int PW = BF_PITCH / 2;   // 20 words per row

#pragma unroll
        for (int ks = 0; ks < 2; ks++) {    // two k16 steps per BK=32
            int kb = ks * 8;                // word base
            uint32_t af[4][4], bf[4][2];
#pragma unroll
            for (int i = 0; i < 4; i++) {
                int r = warp_m * 64 + i * 16 + g;
                af[i][0] = As32[r * PW + kb + tig];
                af[i][1] = As32[(r + 8) * PW + kb + tig];
                af[i][2] = As32[r * PW + kb + 4 + tig];
                af[i][3] = As32[(r + 8) * PW + kb + 4 + tig];
            }
#pragma unroll
            for (int j = 0; j < 4; j++) {
                int cix = warp_n * 32 + j * 8 + g;
                bf[j][0] = Bs32[cix * PW + kb + tig];
                bf[j][1] = Bs32[cix * PW + kb + 4 + tig];
            }
#pragma unroll
            for (int i = 0; i < 4; i++)
#pragma unroll
                for (int j = 0; j < 4; j++)
                    MMA_BF16(acc[i][j], af[i], bf[j]);
        }
        st = (st + 1 == BF_ST) ? 0 : st + 1;
        __syncthreads();
    }

    // epilogue: split into g_K / g_V
#pragma unroll
    for (int i = 0; i < 4; i++) {
        int mbase = br * BF_AROWS + warp_m * 64 + i * 16 + g;
#pragma unroll
        for (int half = 0; half < 2; half++) {
            int m = mbase + half * 8;
            if (m >= M) continue;
            int bb = m / SEQ, nn = m % SEQ;
#pragma unroll
            for (int j = 0; j < 4; j++) {
                int n0 = bc * 128 + warp_n * 32 + j * 8 + 2 * tig;
#pragma unroll
                for (int e = 0; e < 2; e++) {
                    int n = n0 + e;
                    float val = acc[i][j][half * 2 + e] + bias[n];
                    int nc = (n < CDIM) ? n : n - CDIM;
                    float* dst = (n < CDIM) ? g_K : g_V;
                    dst[(((size_t)bb * NH + (nc >> 6)) * SEQ + nn) * HD + (nc & 63)] = val;
                }
            }
        }
    }
}

// ---------------- TF32 GEMM, 128x128x16, 3-stage cp.async pipeline --------
// MODE 1: A = x gathered rows; C -> g_Q
// MODE 2: A = g_att direct;    C -> scatter rows of d_out via g_idx
#define G_APAD 20
#define G_BPAD 136
#define G_AFL  (128 * G_APAD)
#define G_BFL  (16 * G_BPAD)
#define G_STG  (G_AFL + G_BFL)
#define G_ST   3
#define G_SMEM_BYTES (G_ST * G_STG * 4)

template <int MODE>
__global__ __launch_bounds__(256, 2) void gemm_tf32(
    const float* __restrict__ A, const float* __restrict__ B,
    const float* __restrict__ bias, float* __restrict__ C,
    int M, int N, int K)
{
    const int BM = 128, BN = 128, BK = 16;
    extern __shared__ float sm[];
    uint32_t smem_u32 = (uint32_t)__cvta_generic_to_shared(sm);

    int tid = threadIdx.x;
    int wid = tid >> 5, lane = tid & 31;
    int warp_m = wid & 1, warp_n = wid >> 1;
    int g = lane >> 2, tig = lane & 3;

    int bc = blockIdx.x, br = blockIdx.y;

    const float* Ap = (MODE == 2) ? (const float*)g_att : A;

    int ar  = tid >> 2;
    int acl = (tid & 3) * 4;
    int am0 = br * BM + ar;
    int am1 = am0 + 64;
    int cm0 = am0 < M ? am0 : M - 1;
    int cm1 = am1 < M ? am1 : M - 1;
    const float *Arow0, *Arow1;
    if (MODE == 1) {
        int b0 = cm0 / NLOC;
        int b1 = cm1 / NLOC;
        Arow0 = Ap + ((size_t)(b0 * SEQ + g_idx[cm0])) * K + acl;
        Arow1 = Ap + ((size_t)(b1 * SEQ + g_idx[cm1])) * K + acl;
    } else {
        Arow0 = Ap + (size_t)cm0 * K + acl;
        Arow1 = Ap + (size_t)cm1 * K + acl;
    }

    int brw = tid >> 5;
    int bcl = (tid & 31) * 4;
    const float* Bp0 = B + (size_t)brw * N + bc * BN + bcl;
    const float* Bp1 = Bp0 + (size_t)8 * N;

    uint32_t sA = smem_u32 + (uint32_t)(ar * G_APAD + acl) * 4;
    uint32_t sB = smem_u32 + (uint32_t)(G_AFL + brw * G_BPAD + bcl) * 4;

    int nk = K / BK;

#pragma unroll
    for (int p = 0; p < G_ST - 1; p++) {
        uint32_t so = (uint32_t)(p * G_STG) * 4;
        cp16(sA + so, Arow0 + p * BK);
        cp16(sA + so + 64 * G_APAD * 4, Arow1 + p * BK);
        cp16(sB + so, Bp0 + (size_t)p * BK * N);
        cp16(sB + so + 8 * G_BPAD * 4, Bp1 + (size_t)p * BK * N);
        CP_COMMIT();
    }

    float acc[4][4][4];
#pragma unroll
    for (int i = 0; i < 4; i++)
#pragma unroll
        for (int j = 0; j < 4; j++)
#pragma unroll
            for (int c = 0; c < 4; c++) acc[i][j][c] = 0.f;

    int st = 0;
    for (int kt = 0; kt < nk; kt++) {
        CP_WAIT(G_ST - 2);
        __syncthreads();

        int nxt = kt + G_ST - 1;
        if (nxt < nk) {
            int stn = nxt % G_ST;
            uint32_t so = (uint32_t)(stn * G_STG) * 4;
            cp16(sA + so, Arow0 + nxt * BK);
            cp16(sA + so + 64 * G_APAD * 4, Arow1 + nxt * BK);
            cp16(sB + so, Bp0 + (size_t)nxt * BK * N);
            cp16(sB + so + 8 * G_BPAD * 4, Bp1 + (size_t)nxt * BK * N);
        }
        CP_COMMIT();

        const float* As = sm + st * G_STG;
        const float* Bs = As + G_AFL;

#pragma unroll
        for (int ks = 0; ks < 2; ks++) {
            int k0 = ks * 8;
            uint32_t af[4][4];
            uint32_t bf[4][2];
#pragma unroll
            for (int i = 0; i < 4; i++) {
                int r = warp_m * 64 + i * 16 + g;
                af[i][0] = __float_as_uint(As[r * G_APAD + k0 + tig]);
                af[i][1] = __float_as_uint(As[(r + 8) * G_APAD + k0 + tig]);
                af[i][2] = __float_as_uint(As[r * G_APAD + k0 + tig + 4]);
                af[i][3] = __float_as_uint(As[(r + 8) * G_APAD + k0 + tig + 4]);
            }
#pragma unroll
            for (int j = 0; j < 4; j++) {
                int cix = warp_n * 32 + j * 8 + g;
                bf[j][0] = __float_as_uint(Bs[(k0 + tig) * G_BPAD + cix]);
                bf[j][1] = __float_as_uint(Bs[(k0 + tig + 4) * G_BPAD + cix]);
            }
#pragma unroll
            for (int i = 0; i < 4; i++)
#pragma unroll
                for (int j = 0; j < 4; j++)
                    MMA_TF32(acc[i][j], af[i], bf[j]);
        }
        st = (st + 1 == G_ST) ? 0 : st + 1;
    }

    // epilogue
#pragma unroll
    for (int i = 0; i < 4; i++) {
        int mbase = br * BM + warp_m * 64 + i * 16 + g;
#pragma unroll
        for (int half = 0; half < 2; half++) {
            int m = mbase + half * 8;
            if (m >= M) continue;
            if (MODE == 1) {
                int bb = m / NLOC, jj = m % NLOC;
#pragma unroll
                for (int j = 0; j < 4; j++) {
                    int n0 = bc * BN + warp_n * 32 + j * 8 + 2 * tig;
#pragma unroll
                    for (int e = 0; e < 2; e++) {
                        int n = n0 + e;
                        float val = acc[i][j][half * 2 + e] + bias[n];
                        g_Q[(((size_t)bb * NH + (n >> 6)) * NLOC + jj) * HD + (n & 63)] = val;
                    }
                }
            } else {
                int bb = m / NLOC;
                int row = bb * SEQ + g_idx[m];
                float* crow = C + (size_t)row * CDIM;
#pragma unroll
                for (int j = 0; j < 4; j++) {
                    int n0 = bc * BN + warp_n * 32 + j * 8 + 2 * tig;
                    crow[n0]     = acc[i][j][half * 2 + 0] + bias[n0];
                    crow[n0 + 1] = acc[i][j][half * 2 + 1] + bias[n0 + 1];
                }
            }
        }
    }
}

// ---------------- TF32 tensor-core flash attention per (b,h) --------------
#define AT_M   96
#define AT_KN  64
#define QS_LD  68
#define KS_LD  68
#define VS_LD  65
#define SS_LD  68

#define OFF_Q   0
#define OFF_KV  (AT_M * QS_LD)
#define OFF_S   (OFF_KV + AT_KN * KS_LD)
#define OFF_M   (OFF_S + AT_M * SS_LD)
#define OFF_L   (OFF_M + AT_M)
#define OFF_F   (OFF_L + AT_M)
#define SMEM_FLOATS (OFF_F + AT_M)

__global__ __launch_bounds__(256, 2) void attn_kernel()
{
    extern __shared__ float sm[];
    float* Qs  = sm + OFF_Q;
    float* Ks  = sm + OFF_KV;
    float* Vs  = sm + OFF_KV;
    float* Ss  = sm + OFF_S;
    float* s_m = sm + OFF_M;
    float* s_l = sm + OFF_L;
    float* s_f = sm + OFF_F;

    int bh = blockIdx.x;
    int b = bh / NH, h = bh % NH;
    int t = threadIdx.x;
    int wid = t >> 5, lane = t & 31;
    int warp_m = wid & 1, warp_n = wid >> 1;
    int g = lane >> 2, tig = lane & 3;

    const float* qsrc = g_Q + (size_t)bh * NLOC * HD;
    const float* ksrc = g_K + (size_t)bh * SEQ * HD;
    const float* vsrc = g_V + (size_t)bh * SEQ * HD;

    for (int l = t; l < AT_M * 16; l += 256) {
        int r = l >> 4, c4 = (l & 15) * 4;
        float4 v = (r < NLOC) ? *(const float4*)(qsrc + r * HD + c4)
                              : make_float4(0.f, 0.f, 0.f, 0.f);
        st_tf32_4(&Qs[r * QS_LD + c4], v);
    }
    if (t < AT_M) { s_m[t] = -1e30f; s_l[t] = 0.f; }

    float acc_o[3][2][4];
#pragma unroll
    for (int i = 0; i < 3; i++)
#pragma unroll
        for (int j = 0; j < 2; j++)
#pragma unroll
            for (int c = 0; c < 4; c++) acc_o[i][j][c] = 0.f;

    const float scale = 0.125f;

    for (int n0 = 0; n0 < SEQ; n0 += AT_KN) {
        __syncthreads();

        for (int l = t; l < AT_KN * 16; l += 256) {
            int kk = l >> 4, c4 = (l & 15) * 4;
            int src = n0 + kk; if (src > SEQ - 1) src = SEQ - 1;
            st_tf32_4(&Ks[kk * KS_LD + c4], *(const float4*)(ksrc + src * HD + c4));
        }
        __syncthreads();

        float acc_s[3][2][4];
#pragma unroll
        for (int i = 0; i < 3; i++)
#pragma unroll
            for (int j = 0; j < 2; j++)
#pragma unroll
                for (int c = 0; c < 4; c++) acc_s[i][j][c] = 0.f;

#pragma unroll
        for (int ks = 0; ks < 8; ks++) {
            int k0 = ks * 8;
            uint32_t af[3][4], bf[2][2];
#pragma unroll
            for (int i = 0; i < 3; i++) {
                int r = warp_m * 48 + i * 16 + g;
                af[i][0] = __float_as_uint(Qs[r * QS_LD + k0 + tig]);
                af[i][1] = __float_as_uint(Qs[(r + 8) * QS_LD + k0 + tig]);
                af[i][2] = __float_as_uint(Qs[r * QS_LD + k0 + tig + 4]);
                af[i][3] = __float_as_uint(Qs[(r + 8) * QS_LD + k0 + tig + 4]);
            }
#pragma unroll
            for (int j = 0; j < 2; j++) {
                int cix = warp_n * 16 + j * 8 + g;
                bf[j][0] = __float_as_uint(Ks[cix * KS_LD + k0 + tig]);
                bf[j][1] = __float_as_uint(Ks[cix * KS_LD + k0 + tig + 4]);
            }
#pragma unroll
            for (int i = 0; i < 3; i++)
#pragma unroll
                for (int j = 0; j < 2; j++)
                    MMA_TF32(acc_s[i][j], af[i], bf[j]);
        }

#pragma unroll
        for (int i = 0; i < 3; i++) {
            int r0 = warp_m * 48 + i * 16 + g;
#pragma unroll
            for (int j = 0; j < 2; j++) {
                int c0 = warp_n * 16 + j * 8 + 2 * tig;
                bool v0 = (n0 + c0) < SEQ, v1 = (n0 + c0 + 1) < SEQ;
                Ss[r0 * SS_LD + c0]           = v0 ? acc_s[i][j][0] * scale : -1e30f;
                Ss[r0 * SS_LD + c0 + 1]       = v1 ? acc_s[i][j][1] * scale : -1e30f;
                Ss[(r0 + 8) * SS_LD + c0]     = v0 ? acc_s[i][j][2] * scale : -1e30f;
                Ss[(r0 + 8) * SS_LD + c0 + 1] = v1 ? acc_s[i][j][3] * scale : -1e30f;
            }
        }
        __syncthreads();

        {
            int d4 = (t & 15) * 4;
            int kk = t >> 4;
#pragma unroll
            for (int p = 0; p < 4; p++, kk += 16) {
                int src = n0 + kk; if (src > SEQ - 1) src = SEQ - 1;
                float4 v = *(const float4*)(vsrc + src * HD + d4);
                Vs[(d4 + 0) * VS_LD + kk] = __uint_as_float(f2tf32(v.x));
                Vs[(d4 + 1) * VS_LD + kk] = __uint_as_float(f2tf32(v.y));
                Vs[(d4 + 2) * VS_LD + kk] = __uint_as_float(f2tf32(v.z));
                Vs[(d4 + 3) * VS_LD + kk] = __uint_as_float(f2tf32(v.w));
            }
        }
        if (t < AT_M) {
            float* row = Ss + t * SS_LD;
            float mo = s_m[t], mx = mo;
#pragma unroll
            for (int c4 = 0; c4 < AT_KN; c4 += 4) {
                float4 v = *(float4*)(row + c4);
                mx = fmaxf(mx, fmaxf(fmaxf(v.x, v.y), fmaxf(v.z, v.w)));
            }
            float fac = __expf(mo - mx);
            s_f[t] = fac; s_m[t] = mx;
            float sum = 0.f;
#pragma unroll
            for (int c4 = 0; c4 < AT_KN; c4 += 4) {
                float4 v = *(float4*)(row + c4);
                v.x = __expf(v.x - mx); v.y = __expf(v.y - mx);
                v.z = __expf(v.z - mx); v.w = __expf(v.w - mx);
                sum += v.x + v.y + v.z + v.w;
                st_tf32_4(row + c4, v);
            }
            s_l[t] = s_l[t] * fac + sum;
        }
        __syncthreads();

#pragma unroll
        for (int i = 0; i < 3; i++) {
            int r0 = warp_m * 48 + i * 16 + g;
            float f0 = s_f[r0], f1 = s_f[r0 + 8];
#pragma unroll
            for (int j = 0; j < 2; j++) {
                acc_o[i][j][0] *= f0; acc_o[i][j][1] *= f0;
                acc_o[i][j][2] *= f1; acc_o[i][j][3] *= f1;
            }
        }
#pragma unroll
        for (int ks = 0; ks < 8; ks++) {
            int k0 = ks * 8;
            uint32_t af[3][4], bf[2][2];
#pragma unroll
            for (int i = 0; i < 3; i++) {
                int r = warp_m * 48 + i * 16 + g;
                af[i][0] = __float_as_uint(Ss[r * SS_LD + k0 + tig]);
                af[i][1] = __float_as_uint(Ss[(r + 8) * SS_LD + k0 + tig]);
                af[i][2] = __float_as_uint(Ss[r * SS_LD + k0 + tig + 4]);
                af[i][3] = __float_as_uint(Ss[(r + 8) * SS_LD + k0 + tig + 4]);
            }
#pragma unroll
            for (int j = 0; j < 2; j++) {
                int cix = warp_n * 16 + j * 8 + g;
                bf[j][0] = __float_as_uint(Vs[cix * VS_LD + k0 + tig]);
                bf[j][1] = __float_as_uint(Vs[cix * VS_LD + k0 + tig + 4]);
            }
#pragma unroll
            for (int i = 0; i < 3; i++)
#pragma unroll
                for (int j = 0; j < 2; j++)
                    MMA_TF32(acc_o[i][j], af[i], bf[j]);
        }
    }
    __syncthreads();

#pragma unroll
    for (int i = 0; i < 3; i++) {
        int r0 = warp_m * 48 + i * 16 + g;
#pragma unroll
        for (int half = 0; half < 2; half++) {
            int r = r0 + half * 8;
            if (r >= NLOC) continue;
            float inv = 1.f / s_l[r];
            float* dst = g_att + ((size_t)(b * NLOC + r)) * CDIM + h * HD;
#pragma unroll
            for (int j = 0; j < 2; j++) {
                int c0 = warp_n * 16 + j * 8 + 2 * tig;
                float2 o;
                o.x = acc_o[i][j][half * 2 + 0] * inv;
                o.y = acc_o[i][j][half * 2 + 1] * inv;
                *(float2*)(dst + c0) = o;
            }
        }
    }
}

// ---------------- launch ---------------------------------------------------
extern "C" void kernel_launch(void* const* d_in, const int* in_sizes, int n_in,
                              void* d_out, int out_size)
{
    const float* x    = (const float*)d_in[0];
    const float* roll = (const float*)d_in[1];
    const float* Wq   = (const float*)d_in[2];
    const float* bq   = (const float*)d_in[3];
    const float* Wkv  = (const float*)d_in[4];
    const float* bkv  = (const float*)d_in[5];
    const float* Wp   = (const float*)d_in[6];
    const float* bp   = (const float*)d_in[7];
    float* out = (float*)d_out;

    size_t xbytes = (size_t)NB * SEQ * CDIM * sizeof(float);
    const int attn_smem = SMEM_FLOATS * sizeof(float);

    static int s_attr_done = 0;
    if (!s_attr_done) {
        cudaFuncSetAttribute(attn_kernel,
                             cudaFuncAttributeMaxDynamicSharedMemorySize, attn_smem);
        cudaFuncSetAttribute(gemm_bf16_kv,
                             cudaFuncAttributeMaxDynamicSharedMemorySize, BF_SMEM_BYTES);
        cudaFuncSetAttribute(gemm_tf32<1>,
                             cudaFuncAttributeMaxDynamicSharedMemorySize, G_SMEM_BYTES);
        cudaFuncSetAttribute(gemm_tf32<2>,
                             cudaFuncAttributeMaxDynamicSharedMemorySize, G_SMEM_BYTES);
        s_attr_done = 1;
    }

    // pass-through copy (scattered rows overwritten at the end)
    cudaMemcpyAsync(out, x, xbytes, cudaMemcpyDeviceToDevice);

    // conversions for the bf16 KV GEMM
    conv_x_kernel<<<512, 256>>>(x);
    convt_wkv_kernel<<<dim3(2 * CDIM / 32, CDIM / 32), dim3(32, 8)>>>(Wkv);

    // top-k indices per batch
    topk_kernel<<<NB, 256>>>(roll);

    // KV projection (bf16): [50240,768] @ [768,1536] -> g_K/g_V
    {
        int M = NB * SEQ;
        dim3 grid((2 * CDIM) / 128, (M + 127) / 128);
        gemm_bf16_kv<<<grid, 256, BF_SMEM_BYTES>>>(bkv);
    }
    // Q projection (tf32, gathered rows): [4992,768] @ [768,768] -> g_Q
    {
        int M = NB * NLOC, N = CDIM, K = CDIM;
        dim3 grid(N / 128, (M + 127) / 128);
        gemm_tf32<1><<<grid, 256, G_SMEM_BYTES>>>(x, Wq, bq, nullptr, M, N, K);
    }
    // fused tensor-core attention -> g_att
    attn_kernel<<<NB * NH, 256, attn_smem>>>();

    // output projection + scatter into out (tf32)
    {
        int M = NB * NLOC, N = CDIM, K = CDIM;
        dim3 grid(N / 128, (M + 127) / 128);
        gemm_tf32<2><<<grid, 256, G_SMEM_BYTES>>>(nullptr, Wp, bp, out, M, N, K);
    }
}

// round 15
// speedup vs baseline: 4.2215x; 1.1310x over previous
#include <cuda_runtime.h>
#include <cuda_bf16.h>
#include <cstdint>

// Problem constants
#define NB   64      // batch
#define SEQ  785     // tokens
#define CDIM 768     // channels
#define NH   12      // heads
#define HD   64      // head dim
#define NLOC 78      // num_local = int(0.1 * 784)

// ---------------- device scratch (static, no allocations) ----------------
__device__ float g_K[(size_t)NB * NH * SEQ * HD];     // [b][h][n][d]
__device__ float g_V[(size_t)NB * NH * SEQ * HD];     // [b][h][n][d]
__device__ float g_Q[(size_t)NB * NH * NLOC * HD];    // [b][h][j][d]
__device__ float g_att[(size_t)NB * NLOC * CDIM];     // [b*78][768]
__device__ int   g_idx[NB * NLOC];                    // gathered token index (1..784)
__device__ __nv_bfloat16 g_x_bf[(size_t)NB * SEQ * CDIM];     // x in bf16
__device__ __nv_bfloat16 g_Wkv_bt[2 * CDIM * CDIM];           // Wkv^T [1536][768] bf16
__device__ __nv_bfloat16 g_Wq_bt[CDIM * CDIM];                // Wq^T  [768][768] bf16

// ---------------- top-k by exact rank (matches jax.lax.top_k ties) -------
__global__ __launch_bounds__(256) void topk_kernel(const float* __restrict__ roll)
{
    int b = blockIdx.x;
    __shared__ float v[SEQ - 1];  // 784
    const float* src = roll + (size_t)b * SEQ * SEQ + 1;  // row 0, cols 1..784
    for (int i = threadIdx.x; i < SEQ - 1; i += 256) v[i] = src[i];
    __syncthreads();
    for (int i = threadIdx.x; i < SEQ - 1; i += 256) {
        float vi = v[i];
        int rank = 0;
        for (int j = 0; j < SEQ - 1; j++) {
            float vj = v[j];
            rank += (vj > vi) || (vj == vi && j < i);
        }
        if (rank < NLOC) g_idx[b * NLOC + rank] = i + 1;
    }
}

// ---------------- fp32 -> bf16 convert (x) --------------------------------
__global__ __launch_bounds__(256) void conv_x_kernel(const float* __restrict__ src)
{
    size_t n4 = (size_t)NB * SEQ * CDIM / 4;
    size_t stride = (size_t)gridDim.x * blockDim.x;
    for (size_t i = (size_t)blockIdx.x * blockDim.x + threadIdx.x; i < n4; i += stride) {
        float4 v = *(const float4*)(src + i * 4);
        __nv_bfloat16 o[4];
        o[0] = __float2bfloat16_rn(v.x);
        o[1] = __float2bfloat16_rn(v.y);
        o[2] = __float2bfloat16_rn(v.z);
        o[3] = __float2bfloat16_rn(v.w);
        *(uint2*)(g_x_bf + i * 4) = *(uint2*)o;
    }
}

// ---------------- transpose+convert: src fp32 [R][C] -> dst bf16 [C][R] ---
__global__ void convt_kernel(const float* __restrict__ src,
                             __nv_bfloat16* __restrict__ dst, int R, int C)
{
    __shared__ float t[32][33];
    int c0 = blockIdx.x * 32, r0 = blockIdx.y * 32;
    int x = threadIdx.x, y = threadIdx.y;   // 32 x 8
    for (int i = y; i < 32; i += 8) t[i][x] = src[(size_t)(r0 + i) * C + c0 + x];
    __syncthreads();
    for (int i = y; i < 32; i += 8)
        dst[(size_t)(c0 + i) * R + r0 + x] = __float2bfloat16_rn(t[x][i]);
}

// ---------------- helpers --------------------------------------------------
__device__ __forceinline__ uint32_t f2tf32(float f) {
    uint32_t u;
    asm("cvt.rna.tf32.f32 %0, %1;" : "=r"(u) : "f"(f));
    return u;
}
__device__ __forceinline__ uint32_t packbf(float lo, float hi) {
    uint32_t u;
    asm("cvt.rn.bf16x2.f32 %0, %1, %2;" : "=r"(u) : "f"(hi), "f"(lo));
    return u;
}

#define MMA_TF32(C, A, B)                                                     \
    asm volatile(                                                             \
        "mma.sync.aligned.m16n8k8.row.col.f32.tf32.tf32.f32 "                 \
        "{%0,%1,%2,%3}, {%4,%5,%6,%7}, {%8,%9}, {%0,%1,%2,%3};"               \
        : "+f"((C)[0]), "+f"((C)[1]), "+f"((C)[2]), "+f"((C)[3])              \
        : "r"((A)[0]), "r"((A)[1]), "r"((A)[2]), "r"((A)[3]),                 \
          "r"((B)[0]), "r"((B)[1]))

#define MMA_BF16(C, A, B)                                                     \
    asm volatile(                                                             \
        "mma.sync.aligned.m16n8k16.row.col.f32.bf16.bf16.f32 "                \
        "{%0,%1,%2,%3}, {%4,%5,%6,%7}, {%8,%9}, {%0,%1,%2,%3};"               \
        : "+f"((C)[0]), "+f"((C)[1]), "+f"((C)[2]), "+f"((C)[3])              \
        : "r"((A)[0]), "r"((A)[1]), "r"((A)[2]), "r"((A)[3]),                 \
          "r"((B)[0]), "r"((B)[1]))

#define LDSM_X4(r, a)                                                         \
    asm volatile("ldmatrix.sync.aligned.m8n8.x4.shared.b16 {%0,%1,%2,%3}, [%4];" \
        : "=r"((r)[0]), "=r"((r)[1]), "=r"((r)[2]), "=r"((r)[3]) : "r"(a))

__device__ __forceinline__ void cp16(uint32_t s, const void* g) {
    asm volatile("cp.async.cg.shared.global [%0], [%1], 16;" :: "r"(s), "l"(g));
}
#define CP_COMMIT()  asm volatile("cp.async.commit_group;")
#define CP_WAIT(n)   asm volatile("cp.async.wait_group %0;" :: "n"(n))

// ---------------- unified bf16 GEMM, 128x128x32, ldmatrix, 3-stage --------
// MODE 0: A = g_x_bf direct, B = g_Wkv_bt, epilogue split -> g_K/g_V (N=1536)
// MODE 1: A = g_x_bf gathered rows, B = g_Wq_bt, epilogue -> g_Q     (N=768)
#define BF_ROWB  80                               // bytes per smem row (32bf16+pad)
#define BF_AREA  (128 * BF_ROWB)                  // 10240 bytes
#define BF_STAGEB (2 * BF_AREA)                   // 20480 bytes per stage
#define BF_ST    3
#define BF_SMEM_BYTES (BF_ST * BF_STAGEB)         // 61440

template <int MODE>
__global__ __launch_bounds__(256, 2) void gemm_bf16(const float* __restrict__ bias)
{
    const int M = (MODE == 0) ? NB * SEQ : NB * NLOC;
    const int K = CDIM;
    const int BK = 32;
    extern __shared__ __nv_bfloat16 smb[];
    uint32_t smem_u32 = (uint32_t)__cvta_generic_to_shared(smb);

    int t = threadIdx.x;
    int wid = t >> 5, lane = t & 31;
    int warp_m = wid & 1, warp_n = wid >> 1;   // 2 x 4
    int g = lane >> 2, tig = lane & 3;
    int sel = lane >> 3, lrow = lane & 7;
    int bc = blockIdx.x, br = blockIdx.y;

    const __nv_bfloat16* Wsrc = (MODE == 0) ? g_Wkv_bt : g_Wq_bt;

    // loaders: 2 (row,chunk) tasks each for A and B
    const __nv_bfloat16* arow[2];
    const __nv_bfloat16* brow[2];
    uint32_t soff[2];
#pragma unroll
    for (int p = 0; p < 2; p++) {
        int task = p * 256 + t;
        int r = task >> 2, ch = task & 3;
        int am = br * 128 + r;
        int cm = am < M ? am : M - 1;
        if (MODE == 1) {
            int bb2 = cm / NLOC;
            arow[p] = g_x_bf + ((size_t)(bb2 * SEQ + g_idx[cm])) * K + ch * 8;
        } else {
            arow[p] = g_x_bf + (size_t)cm * K + ch * 8;
        }
        int bn = bc * 128 + r;
        brow[p] = Wsrc + (size_t)bn * K + ch * 8;
        soff[p] = (uint32_t)(r * BF_ROWB + ch * 16);
    }

    // prologue: stages 0,1
#pragma unroll
    for (int s = 0; s < 2; s++) {
        uint32_t sb = smem_u32 + s * BF_STAGEB;
#pragma unroll
        for (int p = 0; p < 2; p++) {
            cp16(sb + soff[p], arow[p] + s * BK);
            cp16(sb + BF_AREA + soff[p], brow[p] + s * BK);
        }
        CP_COMMIT();
    }

    float acc[4][4][4];
#pragma unroll
    for (int i = 0; i < 4; i++)
#pragma unroll
        for (int j = 0; j < 4; j++)
#pragma unroll
            for (int c = 0; c < 4; c++) acc[i][j][c] = 0.f;

    // per-thread ldmatrix base offsets (within stage)
    uint32_t a_off = (uint32_t)((warp_m * 64 + (sel & 1) * 8 + lrow) * BF_ROWB
                                + (sel >> 1) * 16);
    uint32_t b_off = (uint32_t)(BF_AREA
                                + (warp_n * 32 + (sel >> 1) * 8 + lrow) * BF_ROWB
                                + (sel & 1) * 16);

    const int nk = K / BK;   // 24
    int st = 0;
    for (int kt = 0; kt < nk; kt++) {
        CP_WAIT(1);
        __syncthreads();

        int nxt = kt + 2;
        if (nxt < nk) {
            uint32_t sb = smem_u32 + (nxt % BF_ST) * BF_STAGEB;
#pragma unroll
            for (int p = 0; p < 2; p++) {
                cp16(sb + soff[p], arow[p] + nxt * BK);
                cp16(sb + BF_AREA + soff[p], brow[p] + nxt * BK);
            }
        }
        CP_COMMIT();

        uint32_t sb = smem_u32 + st * BF_STAGEB;
        uint32_t ab = sb + a_off;
        uint32_t bb = sb + b_off;

#pragma unroll
        for (int ks = 0; ks < 2; ks++) {    // two k16 steps
            uint32_t af[4][4], bf[4][2];
#pragma unroll
            for (int i = 0; i < 4; i++)
                LDSM_X4(af[i], ab + i * (16 * BF_ROWB) + ks * 32);
#pragma unroll
            for (int jp = 0; jp < 2; jp++) {
                uint32_t bt[4];
                LDSM_X4(bt, bb + jp * (16 * BF_ROWB) + ks * 32);
                bf[2 * jp][0] = bt[0]; bf[2 * jp][1] = bt[1];
                bf[2 * jp + 1][0] = bt[2]; bf[2 * jp + 1][1] = bt[3];
            }
#pragma unroll
            for (int i = 0; i < 4; i++)
#pragma unroll
                for (int j = 0; j < 4; j++)
                    MMA_BF16(acc[i][j], af[i], bf[j]);
        }
        st = (st + 1 == BF_ST) ? 0 : st + 1;
    }

    // epilogue
#pragma unroll
    for (int i = 0; i < 4; i++) {
        int mbase = br * 128 + warp_m * 64 + i * 16 + g;
#pragma unroll
        for (int half = 0; half < 2; half++) {
            int m = mbase + half * 8;
            if (m >= M) continue;
            if (MODE == 0) {
                int bb2 = m / SEQ, nn = m % SEQ;
#pragma unroll
                for (int j = 0; j < 4; j++) {
                    int n0 = bc * 128 + warp_n * 32 + j * 8 + 2 * tig;
#pragma unroll
                    for (int e = 0; e < 2; e++) {
                        int n = n0 + e;
                        float val = acc[i][j][half * 2 + e] + bias[n];
                        int nc = (n < CDIM) ? n : n - CDIM;
                        float* dst = (n < CDIM) ? g_K : g_V;
                        dst[(((size_t)bb2 * NH + (nc >> 6)) * SEQ + nn) * HD + (nc & 63)] = val;
                    }
                }
            } else {
                int bb2 = m / NLOC, jj = m % NLOC;
#pragma unroll
                for (int j = 0; j < 4; j++) {
                    int n0 = bc * 128 + warp_n * 32 + j * 8 + 2 * tig;
#pragma unroll
                    for (int e = 0; e < 2; e++) {
                        int n = n0 + e;
                        float val = acc[i][j][half * 2 + e] + bias[n];
                        g_Q[(((size_t)bb2 * NH + (n >> 6)) * NLOC + jj) * HD + (n & 63)] = val;
                    }
                }
            }
        }
    }
}

// ---------------- TF32 GEMM (out projection only), 128x128x16 -------------
#define G_APAD 20
#define G_BPAD 136
#define G_AFL  (128 * G_APAD)
#define G_BFL  (16 * G_BPAD)
#define G_STG  (G_AFL + G_BFL)
#define G_ST   3
#define G_SMEM_BYTES (G_ST * G_STG * 4)

__global__ __launch_bounds__(256, 2) void gemm_tf32_out(
    const float* __restrict__ B, const float* __restrict__ bias,
    float* __restrict__ C)
{
    const int M = NB * NLOC, N = CDIM, K = CDIM;
    const int BM = 128, BN = 128, BK = 16;
    extern __shared__ float sm[];
    uint32_t smem_u32 = (uint32_t)__cvta_generic_to_shared(sm);

    int tid = threadIdx.x;
    int wid = tid >> 5, lane = tid & 31;
    int warp_m = wid & 1, warp_n = wid >> 1;
    int g = lane >> 2, tig = lane & 3;

    int bc = blockIdx.x, br = blockIdx.y;

    const float* Ap = (const float*)g_att;

    int ar  = tid >> 2;
    int acl = (tid & 3) * 4;
    int am0 = br * BM + ar;
    int am1 = am0 + 64;
    int cm0 = am0 < M ? am0 : M - 1;
    int cm1 = am1 < M ? am1 : M - 1;
    const float* Arow0 = Ap + (size_t)cm0 * K + acl;
    const float* Arow1 = Ap + (size_t)cm1 * K + acl;

    int brw = tid >> 5;
    int bcl = (tid & 31) * 4;
    const float* Bp0 = B + (size_t)brw * N + bc * BN + bcl;
    const float* Bp1 = Bp0 + (size_t)8 * N;

    uint32_t sA = smem_u32 + (uint32_t)(ar * G_APAD + acl) * 4;
    uint32_t sB = smem_u32 + (uint32_t)(G_AFL + brw * G_BPAD + bcl) * 4;

    int nk = K / BK;

#pragma unroll
    for (int p = 0; p < G_ST - 1; p++) {
        uint32_t so = (uint32_t)(p * G_STG) * 4;
        cp16(sA + so, Arow0 + p * BK);
        cp16(sA + so + 64 * G_APAD * 4, Arow1 + p * BK);
        cp16(sB + so, Bp0 + (size_t)p * BK * N);
        cp16(sB + so + 8 * G_BPAD * 4, Bp1 + (size_t)p * BK * N);
        CP_COMMIT();
    }

    float acc[4][4][4];
#pragma unroll
    for (int i = 0; i < 4; i++)
#pragma unroll
        for (int j = 0; j < 4; j++)
#pragma unroll
            for (int c = 0; c < 4; c++) acc[i][j][c] = 0.f;

    int st = 0;
    for (int kt = 0; kt < nk; kt++) {
        CP_WAIT(G_ST - 2);
        __syncthreads();

        int nxt = kt + G_ST - 1;
        if (nxt < nk) {
            int stn = nxt % G_ST;
            uint32_t so = (uint32_t)(stn * G_STG) * 4;
            cp16(sA + so, Arow0 + nxt * BK);
            cp16(sA + so + 64 * G_APAD * 4, Arow1 + nxt * BK);
            cp16(sB + so, Bp0 + (size_t)nxt * BK * N);
            cp16(sB + so + 8 * G_BPAD * 4, Bp1 + (size_t)nxt * BK * N);
        }
        CP_COMMIT();

        const float* As = sm + st * G_STG;
        const float* Bs = As + G_AFL;

#pragma unroll
        for (int ks = 0; ks < 2; ks++) {
            int k0 = ks * 8;
            uint32_t af[4][4];
            uint32_t bf[4][2];
#pragma unroll
            for (int i = 0; i < 4; i++) {
                int r = warp_m * 64 + i * 16 + g;
                af[i][0] = __float_as_uint(As[r * G_APAD + k0 + tig]);
                af[i][1] = __float_as_uint(As[(r + 8) * G_APAD + k0 + tig]);
                af[i][2] = __float_as_uint(As[r * G_APAD + k0 + tig + 4]);
                af[i][3] = __float_as_uint(As[(r + 8) * G_APAD + k0 + tig + 4]);
            }
#pragma unroll
            for (int j = 0; j < 4; j++) {
                int cix = warp_n * 32 + j * 8 + g;
                bf[j][0] = __float_as_uint(Bs[(k0 + tig) * G_BPAD + cix]);
                bf[j][1] = __float_as_uint(Bs[(k0 + tig + 4) * G_BPAD + cix]);
            }
#pragma unroll
            for (int i = 0; i < 4; i++)
#pragma unroll
                for (int j = 0; j < 4; j++)
                    MMA_TF32(acc[i][j], af[i], bf[j]);
        }
        st = (st + 1 == G_ST) ? 0 : st + 1;
    }

#pragma unroll
    for (int i = 0; i < 4; i++) {
        int mbase = br * BM + warp_m * 64 + i * 16 + g;
#pragma unroll
        for (int half = 0; half < 2; half++) {
            int m = mbase + half * 8;
            if (m >= M) continue;
            int bb = m / NLOC;
            int row = bb * SEQ + g_idx[m];
            float* crow = C + (size_t)row * CDIM;
#pragma unroll
            for (int j = 0; j < 4; j++) {
                int n0 = bc * BN + warp_n * 32 + j * 8 + 2 * tig;
                crow[n0]     = acc[i][j][half * 2 + 0] + bias[n0];
                crow[n0 + 1] = acc[i][j][half * 2 + 1] + bias[n0 + 1];
            }
        }
    }
}

// ---------------- bf16 tensor-core flash attention per (b,h) --------------
// M=96 (78 valid), key tile 64, 8 warps 2x4; bf16 m16n8k16 for S and PV.
// Q/K rows are 64 bf16 = 32 u32 -> pitch 36 u32 (bank-clean: (4g+tig) mod 32).
#define AT_M   96
#define AT_KN  64
#define QK_PW  36                          // Qs/Ks/Ps row pitch in u32 words
// u32-unit offsets in dynamic smem
#define AOFF_Q   0                         // Qs bf16 [96][72]   -> 3456 u32
#define AOFF_KV  3456                      // Ks bf16 [64][72] (2304 u32) / Vs fp32 [64][65] (4160)
#define AOFF_S   (AOFF_KV + 4160)          // Ss fp32 [96][68]   -> 6528
#define AOFF_P   (AOFF_S + 6528)           // Ps bf16 [96][72]   -> 3456 u32
#define AOFF_M   (AOFF_P + 3456)
#define AOFF_L   (AOFF_M + AT_M)
#define AOFF_F   (AOFF_L + AT_M)
#define AT_SMEM_U32 (AOFF_F + AT_M)        // 17888 u32 = 71552 B

__global__ __launch_bounds__(256, 2) void attn_kernel()
{
    extern __shared__ float sm[];
    uint32_t* smu = (uint32_t*)sm;
    uint32_t* Qs_u = smu + AOFF_Q;     // pitch QK_PW u32
    uint32_t* Ks_u = smu + AOFF_KV;    // pitch QK_PW u32
    float*    Vs   = sm + AOFF_KV;     // pitch 65 fp32
    float*    Ss   = sm + AOFF_S;      // pitch 68 fp32
    uint32_t* Ps_u = smu + AOFF_P;     // pitch QK_PW u32
    float* s_m = sm + AOFF_M;
    float* s_l = sm + AOFF_L;
    float* s_f = sm + AOFF_F;

    int bh = blockIdx.x;
    int b = bh / NH, h = bh % NH;
    int t = threadIdx.x;
    int wid = t >> 5, lane = t & 31;
    int warp_m = wid & 1, warp_n = wid >> 1;   // 2 x 4
    int g = lane >> 2, tig = lane & 3;

    const float* qsrc = g_Q + (size_t)bh * NLOC * HD;
    const float* ksrc = g_K + (size_t)bh * SEQ * HD;
    const float* vsrc = g_V + (size_t)bh * SEQ * HD;

    // load Q as bf16, zero rows 78..95
    for (int l = t; l < AT_M * 16; l += 256) {
        int r = l >> 4, c4 = (l & 15) * 4;
        float4 v = (r < NLOC) ? *(const float4*)(qsrc + r * HD + c4)
                              : make_float4(0.f, 0.f, 0.f, 0.f);
        Qs_u[r * QK_PW + c4 / 2]     = packbf(v.x, v.y);
        Qs_u[r * QK_PW + c4 / 2 + 1] = packbf(v.z, v.w);
    }
    if (t < AT_M) { s_m[t] = -1e30f; s_l[t] = 0.f; }

    float acc_o[3][2][4];
#pragma unroll
    for (int i = 0; i < 3; i++)
#pragma unroll
        for (int j = 0; j < 2; j++)
#pragma unroll
            for (int c = 0; c < 4; c++) acc_o[i][j][c] = 0.f;

    const float scale = 0.125f;

    for (int n0 = 0; n0 < SEQ; n0 += AT_KN) {
        __syncthreads();   // protects Qs (1st iter), Ps/Vs reuse (later)

        // ---- load K tile bf16 [64][72]
        for (int l = t; l < AT_KN * 16; l += 256) {
            int kk = l >> 4, c4 = (l & 15) * 4;
            int src = n0 + kk; if (src > SEQ - 1) src = SEQ - 1;
            float4 v = *(const float4*)(ksrc + src * HD + c4);
            Ks_u[kk * QK_PW + c4 / 2]     = packbf(v.x, v.y);
            Ks_u[kk * QK_PW + c4 / 2 + 1] = packbf(v.z, v.w);
        }
        __syncthreads();

        // ---- S = Q K^T, bf16 m16n8k16, 4 k-steps
        float acc_s[3][2][4];
#pragma unroll
        for (int i = 0; i < 3; i++)
#pragma unroll
            for (int j = 0; j < 2; j++)
#pragma unroll
                for (int c = 0; c < 4; c++) acc_s[i][j][c] = 0.f;

#pragma unroll
        for (int ks = 0; ks < 4; ks++) {
            int kb = ks * 8;   // u32 words
            uint32_t af[3][4], bf[2][2];
#pragma unroll
            for (int i = 0; i < 3; i++) {
                int r = warp_m * 48 + i * 16 + g;
                af[i][0] = Qs_u[r * QK_PW + kb + tig];
                af[i][1] = Qs_u[(r + 8) * QK_PW + kb + tig];
                af[i][2] = Qs_u[r * QK_PW + kb + 4 + tig];
                af[i][3] = Qs_u[(r + 8) * QK_PW + kb + 4 + tig];
            }
#pragma unroll
            for (int j = 0; j < 2; j++) {
                int cix = warp_n * 16 + j * 8 + g;
                bf[j][0] = Ks_u[cix * QK_PW + kb + tig];
                bf[j][1] = Ks_u[cix * QK_PW + kb + 4 + tig];
            }
#pragma unroll
            for (int i = 0; i < 3; i++)
#pragma unroll
                for (int j = 0; j < 2; j++)
                    MMA_BF16(acc_s[i][j], af[i], bf[j]);
        }

        // ---- write S*scale (fp32) with key mask
#pragma unroll
        for (int i = 0; i < 3; i++) {
            int r0 = warp_m * 48 + i * 16 + g;
#pragma unroll
            for (int j = 0; j < 2; j++) {
                int c0 = warp_n * 16 + j * 8 + 2 * tig;
                bool v0 = (n0 + c0) < SEQ, v1 = (n0 + c0 + 1) < SEQ;
                Ss[r0 * 68 + c0]           = v0 ? acc_s[i][j][0] * scale : -1e30f;
                Ss[r0 * 68 + c0 + 1]       = v1 ? acc_s[i][j][1] * scale : -1e30f;
                Ss[(r0 + 8) * 68 + c0]     = v0 ? acc_s[i][j][2] * scale : -1e30f;
                Ss[(r0 + 8) * 68 + c0 + 1] = v1 ? acc_s[i][j][3] * scale : -1e30f;
            }
        }
        __syncthreads();

        // ---- V tile load fp32 (overwrites Ks) + row softmax -> Ps bf16
        {
            int d4 = (t & 15) * 4;
            int kk = t >> 4;
#pragma unroll
            for (int p = 0; p < 4; p++, kk += 16) {
                int src = n0 + kk; if (src > SEQ - 1) src = SEQ - 1;
                float4 v = *(const float4*)(vsrc + src * HD + d4);
                Vs[(d4 + 0) * 65 + kk] = v.x;
                Vs[(d4 + 1) * 65 + kk] = v.y;
                Vs[(d4 + 2) * 65 + kk] = v.z;
                Vs[(d4 + 3) * 65 + kk] = v.w;
            }
        }
        if (t < AT_M) {
            float* row = Ss + t * 68;
            uint32_t* prow = Ps_u + t * QK_PW;
            float mo = s_m[t], mx = mo;
#pragma unroll
            for (int c4 = 0; c4 < AT_KN; c4 += 4) {
                float4 v = *(float4*)(row + c4);
                mx = fmaxf(mx, fmaxf(fmaxf(v.x, v.y), fmaxf(v.z, v.w)));
            }
            float fac = __expf(mo - mx);
            s_f[t] = fac; s_m[t] = mx;
            float sum = 0.f;
#pragma unroll
            for (int c4 = 0; c4 < AT_KN; c4 += 4) {
                float4 v = *(float4*)(row + c4);
                v.x = __expf(v.x - mx); v.y = __expf(v.y - mx);
                v.z = __expf(v.z - mx); v.w = __expf(v.w - mx);
                sum += v.x + v.y + v.z + v.w;
                prow[c4 / 2]     = packbf(v.x, v.y);
                prow[c4 / 2 + 1] = packbf(v.z, v.w);
            }
            s_l[t] = s_l[t] * fac + sum;
        }
        __syncthreads();

        // ---- rescale O, then O += P V (bf16, 4 k-steps over 64 keys)
#pragma unroll
        for (int i = 0; i < 3; i++) {
            int r0 = warp_m * 48 + i * 16 + g;
            float f0 = s_f[r0], f1 = s_f[r0 + 8];
#pragma unroll
            for (int j = 0; j < 2; j++) {
                acc_o[i][j][0] *= f0; acc_o[i][j][1] *= f0;
                acc_o[i][j][2] *= f1; acc_o[i][j][3] *= f1;
            }
        }
#pragma unroll
        for (int ks = 0; ks < 4; ks++) {
            int kb = ks * 8;          // u32 words into P
            int kf = ks * 16;         // fp32 index into V rows
            uint32_t af[3][4], bf[2][2];
#pragma unroll
            for (int i = 0; i < 3; i++) {
                int r = warp_m * 48 + i * 16 + g;
                af[i][0] = Ps_u[r * QK_PW + kb + tig];
                af[i][1] = Ps_u[(r + 8) * QK_PW + kb + tig];
                af[i][2] = Ps_u[r * QK_PW + kb + 4 + tig];
                af[i][3] = Ps_u[(r + 8) * QK_PW + kb + 4 + tig];
            }
#pragma unroll
            for (int j = 0; j < 2; j++) {
                int cix = warp_n * 16 + j * 8 + g;   // output dim d
                const float* vr = Vs + cix * 65;
#pragma unroll
                for (int kh = 0; kh < 2; kh++) {
                    int k0 = kf + kh * 8 + 2 * tig;
                    bf[j][kh] = packbf(vr[k0], vr[k0 + 1]);
                }
            }
#pragma unroll
            for (int i = 0; i < 3; i++)
#pragma unroll
                for (int j = 0; j < 2; j++)
                    MMA_BF16(acc_o[i][j], af[i], bf[j]);
        }
    }
    __syncthreads();

    // ---- writeout: g_att[b*78 + r][h*64 + c] = O / l  (fp32)
#pragma unroll
    for (int i = 0; i < 3; i++) {
        int r0 = warp_m * 48 + i * 16 + g;
#pragma unroll
        for (int half = 0; half < 2; half++) {
            int r = r0 + half * 8;
            if (r >= NLOC) continue;
            float inv = 1.f / s_l[r];
            float* dst = g_att + ((size_t)(b * NLOC + r)) * CDIM + h * HD;
#pragma unroll
            for (int j = 0; j < 2; j++) {
                int c0 = warp_n * 16 + j * 8 + 2 * tig;
                float2 o;
                o.x = acc_o[i][j][half * 2 + 0] * inv;
                o.y = acc_o[i][j][half * 2 + 1] * inv;
                *(float2*)(dst + c0) = o;
            }
        }
    }
}

// ---------------- launch ---------------------------------------------------
extern "C" void kernel_launch(void* const* d_in, const int* in_sizes, int n_in,
                              void* d_out, int out_size)
{
    const float* x    = (const float*)d_in[0];
    const float* roll = (const float*)d_in[1];
    const float* Wq   = (const float*)d_in[2];
    const float* bq   = (const float*)d_in[3];
    const float* Wkv  = (const float*)d_in[4];
    const float* bkv  = (const float*)d_in[5];
    const float* Wp   = (const float*)d_in[6];
    const float* bp   = (const float*)d_in[7];
    float* out = (float*)d_out;

    size_t xbytes = (size_t)NB * SEQ * CDIM * sizeof(float);
    const int attn_smem = AT_SMEM_U32 * 4;

    static int s_attr_done = 0;
    if (!s_attr_done) {
        cudaFuncSetAttribute(attn_kernel,
                             cudaFuncAttributeMaxDynamicSharedMemorySize, attn_smem);
        cudaFuncSetAttribute(gemm_bf16<0>,
                             cudaFuncAttributeMaxDynamicSharedMemorySize, BF_SMEM_BYTES);
        cudaFuncSetAttribute(gemm_bf16<1>,
                             cudaFuncAttributeMaxDynamicSharedMemorySize, BF_SMEM_BYTES);
        cudaFuncSetAttribute(gemm_tf32_out,
                             cudaFuncAttributeMaxDynamicSharedMemorySize, G_SMEM_BYTES);
        s_attr_done = 1;
    }

    // resolve transposed-weight symbol addresses
    __nv_bfloat16 *wkv_bt, *wq_bt;
    cudaGetSymbolAddress((void**)&wkv_bt, g_Wkv_bt);
    cudaGetSymbolAddress((void**)&wq_bt,  g_Wq_bt);

    // pass-through copy (scattered rows overwritten at the end)
    cudaMemcpyAsync(out, x, xbytes, cudaMemcpyDeviceToDevice);

    // conversions
    conv_x_kernel<<<512, 256>>>(x);
    convt_kernel<<<dim3(2 * CDIM / 32, CDIM / 32), dim3(32, 8)>>>(Wkv, wkv_bt, CDIM, 2 * CDIM);
    convt_kernel<<<dim3(CDIM / 32, CDIM / 32), dim3(32, 8)>>>(Wq, wq_bt, CDIM, CDIM);

    // top-k indices per batch
    topk_kernel<<<NB, 256>>>(roll);

    // KV projection (bf16 + ldmatrix): [50240,768] @ [768,1536]
    {
        int M = NB * SEQ;
        dim3 grid((2 * CDIM) / 128, (M + 127) / 128);
        gemm_bf16<0><<<grid, 256, BF_SMEM_BYTES>>>(bkv);
    }
    // Q projection (bf16, gathered rows): [4992,768] @ [768,768]
    {
        int M = NB * NLOC;
        dim3 grid(CDIM / 128, (M + 127) / 128);
        gemm_bf16<1><<<grid, 256, BF_SMEM_BYTES>>>(bq);
    }
    // fused bf16 attention -> g_att
    attn_kernel<<<NB * NH, 256, attn_smem>>>();

    // output projection (tf32) + scatter into out
    {
        int M = NB * NLOC;
        dim3 grid(CDIM / 128, (M + 127) / 128);
        gemm_tf32_out<<<grid, 256, G_SMEM_BYTES>>>(Wp, bp, out);
    }
}

// round 16
// speedup vs baseline: 5.1772x; 1.2264x over previous
#include <cuda_runtime.h>
#include <cuda_bf16.h>
#include <cstdint>

// Problem constants
#define NB   64      // batch
#define SEQ  785     // tokens
#define SEQ_PAD 832  // padded key stride for V rows (16B-aligned cp.async chunks)
#define CDIM 768     // channels
#define NH   12      // heads
#define HD   64      // head dim
#define NLOC 78      // num_local = int(0.1 * 784)

// ---------------- device scratch (static, no allocations) ----------------
__device__ __nv_bfloat16 g_Kbf[(size_t)NB * NH * SEQ * HD];      // [b][h][n][d]
__device__ __nv_bfloat16 g_Vbf[(size_t)NB * NH * HD * SEQ_PAD];  // [b][h][d][n] transposed, zero-padded
__device__ __nv_bfloat16 g_Qbf[(size_t)NB * NH * NLOC * HD];     // [b][h][j][d]
__device__ float g_att[(size_t)NB * NLOC * CDIM];                // [b*78][768]
__device__ int   g_idx[NB * NLOC];                               // gathered token index (1..784)
__device__ __nv_bfloat16 g_x_bf[(size_t)NB * SEQ * CDIM];        // x in bf16
__device__ __nv_bfloat16 g_Wkv_bt[2 * CDIM * CDIM];              // Wkv^T [1536][768] bf16
__device__ __nv_bfloat16 g_Wq_bt[CDIM * CDIM];                   // Wq^T  [768][768] bf16

// ---------------- top-k by exact rank (matches jax.lax.top_k ties) -------
__global__ __launch_bounds__(1024) void topk_kernel(const float* __restrict__ roll)
{
    int b = blockIdx.x;
    __shared__ float v[SEQ - 1];  // 784
    const float* src = roll + (size_t)b * SEQ * SEQ + 1;  // row 0, cols 1..784
    for (int i = threadIdx.x; i < SEQ - 1; i += 1024) v[i] = src[i];
    __syncthreads();
    for (int i = threadIdx.x; i < SEQ - 1; i += 1024) {
        float vi = v[i];
        int rank = 0;
        for (int j = 0; j < SEQ - 1; j++) {
            float vj = v[j];
            rank += (vj > vi) || (vj == vi && j < i);
        }
        if (rank < NLOC) g_idx[b * NLOC + rank] = i + 1;
    }
}

// ---------------- fused: out = x (copy) ; g_x_bf = bf16(x) ----------------
__global__ __launch_bounds__(256) void copyconv_x_kernel(const float* __restrict__ src,
                                                         float* __restrict__ out)
{
    size_t n4 = (size_t)NB * SEQ * CDIM / 4;
    size_t stride = (size_t)gridDim.x * blockDim.x;
    for (size_t i = (size_t)blockIdx.x * blockDim.x + threadIdx.x; i < n4; i += stride) {
        float4 v = *(const float4*)(src + i * 4);
        *(float4*)(out + i * 4) = v;
        __nv_bfloat16 o[4];
        o[0] = __float2bfloat16_rn(v.x);
        o[1] = __float2bfloat16_rn(v.y);
        o[2] = __float2bfloat16_rn(v.z);
        o[3] = __float2bfloat16_rn(v.w);
        *(uint2*)(g_x_bf + i * 4) = *(uint2*)o;
    }
}

// ---------------- transpose+convert: src fp32 [R][C] -> dst bf16 [C][R] ---
__global__ void convt_kernel(const float* __restrict__ src,
                             __nv_bfloat16* __restrict__ dst, int R, int C)
{
    __shared__ float t[32][33];
    int c0 = blockIdx.x * 32, r0 = blockIdx.y * 32;
    int x = threadIdx.x, y = threadIdx.y;   // 32 x 8
    for (int i = y; i < 32; i += 8) t[i][x] = src[(size_t)(r0 + i) * C + c0 + x];
    __syncthreads();
    for (int i = y; i < 32; i += 8)
        dst[(size_t)(c0 + i) * R + r0 + x] = __float2bfloat16_rn(t[x][i]);
}

// ---------------- helpers --------------------------------------------------
__device__ __forceinline__ uint32_t packbf(float lo, float hi) {
    uint32_t u;
    asm("cvt.rn.bf16x2.f32 %0, %1, %2;" : "=r"(u) : "f"(hi), "f"(lo));
    return u;
}

#define MMA_TF32(C, A, B)                                                     \
    asm volatile(                                                             \
        "mma.sync.aligned.m16n8k8.row.col.f32.tf32.tf32.f32 "                 \
        "{%0,%1,%2,%3}, {%4,%5,%6,%7}, {%8,%9}, {%0,%1,%2,%3};"               \
        : "+f"((C)[0]), "+f"((C)[1]), "+f"((C)[2]), "+f"((C)[3])              \
        : "r"((A)[0]), "r"((A)[1]), "r"((A)[2]), "r"((A)[3]),                 \
          "r"((B)[0]), "r"((B)[1]))

#define MMA_BF16(C, A, B)                                                     \
    asm volatile(                                                             \
        "mma.sync.aligned.m16n8k16.row.col.f32.bf16.bf16.f32 "                \
        "{%0,%1,%2,%3}, {%4,%5,%6,%7}, {%8,%9}, {%0,%1,%2,%3};"               \
        : "+f"((C)[0]), "+f"((C)[1]), "+f"((C)[2]), "+f"((C)[3])              \
        : "r"((A)[0]), "r"((A)[1]), "r"((A)[2]), "r"((A)[3]),                 \
          "r"((B)[0]), "r"((B)[1]))

#define LDSM_X4(r, a)                                                         \
    asm volatile("ldmatrix.sync.aligned.m8n8.x4.shared.b16 {%0,%1,%2,%3}, [%4];" \
        : "=r"((r)[0]), "=r"((r)[1]), "=r"((r)[2]), "=r"((r)[3]) : "r"(a))

__device__ __forceinline__ void cp16(uint32_t s, const void* g) {
    asm volatile("cp.async.cg.shared.global [%0], [%1], 16;" :: "r"(s), "l"(g));
}
#define CP_COMMIT()  asm volatile("cp.async.commit_group;")
#define CP_WAIT(n)   asm volatile("cp.async.wait_group %0;" :: "n"(n))

// ---------------- unified bf16 GEMM, 128x128x32, ldmatrix, 3-stage --------
// MODE 0: A = g_x_bf direct, B = g_Wkv_bt, epilogue -> g_Kbf / g_Vbf (N=1536)
// MODE 1: A = g_x_bf gathered rows, B = g_Wq_bt, epilogue -> g_Qbf   (N=768)
#define BF_ROWB  80                               // bytes per smem row (32bf16+pad)
#define BF_AREA  (128 * BF_ROWB)                  // 10240 bytes
#define BF_STAGEB (2 * BF_AREA)                   // 20480 bytes per stage
#define BF_ST    3
#define BF_SMEM_BYTES (BF_ST * BF_STAGEB)         // 61440

template <int MODE>
__global__ __launch_bounds__(256, 2) void gemm_bf16(const float* __restrict__ bias)
{
    const int M = (MODE == 0) ? NB * SEQ : NB * NLOC;
    const int K = CDIM;
    const int BK = 32;
    extern __shared__ __nv_bfloat16 smb[];
    uint32_t smem_u32 = (uint32_t)__cvta_generic_to_shared(smb);

    int t = threadIdx.x;
    int wid = t >> 5, lane = t & 31;
    int warp_m = wid & 1, warp_n = wid >> 1;   // 2 x 4
    int g = lane >> 2, tig = lane & 3;
    int sel = lane >> 3, lrow = lane & 7;
    int bc = blockIdx.x, br = blockIdx.y;

    const __nv_bfloat16* Wsrc = (MODE == 0) ? g_Wkv_bt : g_Wq_bt;

    // loaders: 2 (row,chunk) tasks each for A and B
    const __nv_bfloat16* arow[2];
    const __nv_bfloat16* brow[2];
    uint32_t soff[2];
#pragma unroll
    for (int p = 0; p < 2; p++) {
        int task = p * 256 + t;
        int r = task >> 2, ch = task & 3;
        int am = br * 128 + r;
        int cm = am < M ? am : M - 1;
        if (MODE == 1) {
            int bb2 = cm / NLOC;
            arow[p] = g_x_bf + ((size_t)(bb2 * SEQ + g_idx[cm])) * K + ch * 8;
        } else {
            arow[p] = g_x_bf + (size_t)cm * K + ch * 8;
        }
        int bn = bc * 128 + r;
        brow[p] = Wsrc + (size_t)bn * K + ch * 8;
        soff[p] = (uint32_t)(r * BF_ROWB + ch * 16);
    }

    // prologue: stages 0,1
#pragma unroll
    for (int s = 0; s < 2; s++) {
        uint32_t sb = smem_u32 + s * BF_STAGEB;
#pragma unroll
        for (int p = 0; p < 2; p++) {
            cp16(sb + soff[p], arow[p] + s * BK);
            cp16(sb + BF_AREA + soff[p], brow[p] + s * BK);
        }
        CP_COMMIT();
    }

    float acc[4][4][4];
#pragma unroll
    for (int i = 0; i < 4; i++)
#pragma unroll
        for (int j = 0; j < 4; j++)
#pragma unroll
            for (int c = 0; c < 4; c++) acc[i][j][c] = 0.f;

    // per-thread ldmatrix base offsets (within stage)
    uint32_t a_off = (uint32_t)((warp_m * 64 + (sel & 1) * 8 + lrow) * BF_ROWB
                                + (sel >> 1) * 16);
    uint32_t b_off = (uint32_t)(BF_AREA
                                + (warp_n * 32 + (sel >> 1) * 8 + lrow) * BF_ROWB
                                + (sel & 1) * 16);

    const int nk = K / BK;   // 24
    int st = 0;
    for (int kt = 0; kt < nk; kt++) {
        CP_WAIT(1);
        __syncthreads();

        int nxt = kt + 2;
        if (nxt < nk) {
            uint32_t sb = smem_u32 + (nxt % BF_ST) * BF_STAGEB;
#pragma unroll
            for (int p = 0; p < 2; p++) {
                cp16(sb + soff[p], arow[p] + nxt * BK);
                cp16(sb + BF_AREA + soff[p], brow[p] + nxt * BK);
            }
        }
        CP_COMMIT();

        uint32_t sb = smem_u32 + st * BF_STAGEB;
        uint32_t ab = sb + a_off;
        uint32_t bb = sb + b_off;

#pragma unroll
        for (int ks = 0; ks < 2; ks++) {    // two k16 steps
            uint32_t af[4][4], bf[4][2];
#pragma unroll
            for (int i = 0; i < 4; i++)
                LDSM_X4(af[i], ab + i * (16 * BF_ROWB) + ks * 32);
#pragma unroll
            for (int jp = 0; jp < 2; jp++) {
                uint32_t bt[4];
                LDSM_X4(bt, bb + jp * (16 * BF_ROWB) + ks * 32);
                bf[2 * jp][0] = bt[0]; bf[2 * jp][1] = bt[1];
                bf[2 * jp + 1][0] = bt[2]; bf[2 * jp + 1][1] = bt[3];
            }
#pragma unroll
            for (int i = 0; i < 4; i++)
#pragma unroll
                for (int j = 0; j < 4; j++)
                    MMA_BF16(acc[i][j], af[i], bf[j]);
        }
        st = (st + 1 == BF_ST) ? 0 : st + 1;
    }

    // epilogue: bf16 outputs (K/Q packed u32; V transposed scalar)
#pragma unroll
    for (int i = 0; i < 4; i++) {
        int mbase = br * 128 + warp_m * 64 + i * 16 + g;
#pragma unroll
        for (int half = 0; half < 2; half++) {
            int m = mbase + half * 8;
            if (m >= M) continue;
            if (MODE == 0) {
                int bb2 = m / SEQ, nn = m % SEQ;
#pragma unroll
                for (int j = 0; j < 4; j++) {
                    int n0 = bc * 128 + warp_n * 32 + j * 8 + 2 * tig;
                    float v0 = acc[i][j][half * 2 + 0] + bias[n0];
                    float v1 = acc[i][j][half * 2 + 1] + bias[n0 + 1];
                    if (n0 < CDIM) {
                        int h = n0 >> 6, d = n0 & 63;   // d even
                        uint32_t* dst = (uint32_t*)g_Kbf
                            + (((size_t)bb2 * NH + h) * SEQ + nn) * (HD / 2) + d / 2;
                        *dst = packbf(v0, v1);
                    } else {
                        int nc = n0 - CDIM;
                        int h = nc >> 6, d = nc & 63;
                        __nv_bfloat16* dst = g_Vbf
                            + (((size_t)bb2 * NH + h) * HD + d) * SEQ_PAD + nn;
                        dst[0]       = __float2bfloat16_rn(v0);
                        dst[SEQ_PAD] = __float2bfloat16_rn(v1);
                    }
                }
            } else {
                int bb2 = m / NLOC, jj = m % NLOC;
#pragma unroll
                for (int j = 0; j < 4; j++) {
                    int n0 = bc * 128 + warp_n * 32 + j * 8 + 2 * tig;
                    float v0 = acc[i][j][half * 2 + 0] + bias[n0];
                    float v1 = acc[i][j][half * 2 + 1] + bias[n0 + 1];
                    int h = n0 >> 6, d = n0 & 63;
                    uint32_t* dst = (uint32_t*)g_Qbf
                        + (((size_t)bb2 * NH + h) * NLOC + jj) * (HD / 2) + d / 2;
                    *dst = packbf(v0, v1);
                }
            }
        }
    }
}

// ---------------- TF32 GEMM (out projection only), 128x128x16 -------------
#define G_APAD 20
#define G_BPAD 136
#define G_AFL  (128 * G_APAD)
#define G_BFL  (16 * G_BPAD)
#define G_STG  (G_AFL + G_BFL)
#define G_ST   3
#define G_SMEM_BYTES (G_ST * G_STG * 4)

__global__ __launch_bounds__(256, 2) void gemm_tf32_out(
    const float* __restrict__ B, const float* __restrict__ bias,
    float* __restrict__ C)
{
    const int M = NB * NLOC, N = CDIM, K = CDIM;
    const int BM = 128, BN = 128, BK = 16;
    extern __shared__ float sm[];
    uint32_t smem_u32 = (uint32_t)__cvta_generic_to_shared(sm);

    int tid = threadIdx.x;
    int wid = tid >> 5, lane = tid & 31;
    int warp_m = wid & 1, warp_n = wid >> 1;
    int g = lane >> 2, tig = lane & 3;

    int bc = blockIdx.x, br = blockIdx.y;

    const float* Ap = (const float*)g_att;

    int ar  = tid >> 2;
    int acl = (tid & 3) * 4;
    int am0 = br * BM + ar;
    int am1 = am0 + 64;
    int cm0 = am0 < M ? am0 : M - 1;
    int cm1 = am1 < M ? am1 : M - 1;
    const float* Arow0 = Ap + (size_t)cm0 * K + acl;
    const float* Arow1 = Ap + (size_t)cm1 * K + acl;

    int brw = tid >> 5;
    int bcl = (tid & 31) * 4;
    const float* Bp0 = B + (size_t)brw * N + bc * BN + bcl;
    const float* Bp1 = Bp0 + (size_t)8 * N;

    uint32_t sA = smem_u32 + (uint32_t)(ar * G_APAD + acl) * 4;
    uint32_t sB = smem_u32 + (uint32_t)(G_AFL + brw * G_BPAD + bcl) * 4;

    int nk = K / BK;

#pragma unroll
    for (int p = 0; p < G_ST - 1; p++) {
        uint32_t so = (uint32_t)(p * G_STG) * 4;
        cp16(sA + so, Arow0 + p * BK);
        cp16(sA + so + 64 * G_APAD * 4, Arow1 + p * BK);
        cp16(sB + so, Bp0 + (size_t)p * BK * N);
        cp16(sB + so + 8 * G_BPAD * 4, Bp1 + (size_t)p * BK * N);
        CP_COMMIT();
    }

    float acc[4][4][4];
#pragma unroll
    for (int i = 0; i < 4; i++)
#pragma unroll
        for (int j = 0; j < 4; j++)
#pragma unroll
            for (int c = 0; c < 4; c++) acc[i][j][c] = 0.f;

    int st = 0;
    for (int kt = 0; kt < nk; kt++) {
        CP_WAIT(G_ST - 2);
        __syncthreads();

        int nxt = kt + G_ST - 1;
        if (nxt < nk) {
            int stn = nxt % G_ST;
            uint32_t so = (uint32_t)(stn * G_STG) * 4;
            cp16(sA + so, Arow0 + nxt * BK);
            cp16(sA + so + 64 * G_APAD * 4, Arow1 + nxt * BK);
            cp16(sB + so, Bp0 + (size_t)nxt * BK * N);
            cp16(sB + so + 8 * G_BPAD * 4, Bp1 + (size_t)nxt * BK * N);
        }
        CP_COMMIT();

        const float* As = sm + st * G_STG;
        const float* Bs = As + G_AFL;

#pragma unroll
        for (int ks = 0; ks < 2; ks++) {
            int k0 = ks * 8;
            uint32_t af[4][4];
            uint32_t bf[4][2];
#pragma unroll
            for (int i = 0; i < 4; i++) {
                int r = warp_m * 64 + i * 16 + g;
                af[i][0] = __float_as_uint(As[r * G_APAD + k0 + tig]);
                af[i][1] = __float_as_uint(As[(r + 8) * G_APAD + k0 + tig]);
                af[i][2] = __float_as_uint(As[r * G_APAD + k0 + tig + 4]);
                af[i][3] = __float_as_uint(As[(r + 8) * G_APAD + k0 + tig + 4]);
            }
#pragma unroll
            for (int j = 0; j < 4; j++) {
                int cix = warp_n * 32 + j * 8 + g;
                bf[j][0] = __float_as_uint(Bs[(k0 + tig) * G_BPAD + cix]);
                bf[j][1] = __float_as_uint(Bs[(k0 + tig + 4) * G_BPAD + cix]);
            }
#pragma unroll
            for (int i = 0; i < 4; i++)
#pragma unroll
                for (int j = 0; j < 4; j++)
                    MMA_TF32(acc[i][j], af[i], bf[j]);
        }
        st = (st + 1 == G_ST) ? 0 : st + 1;
    }

#pragma unroll
    for (int i = 0; i < 4; i++) {
        int mbase = br * BM + warp_m * 64 + i * 16 + g;
#pragma unroll
        for (int half = 0; half < 2; half++) {
            int m = mbase + half * 8;
            if (m >= M) continue;
            int bb = m / NLOC;
            int row = bb * SEQ + g_idx[m];
            float* crow = C + (size_t)row * CDIM;
#pragma unroll
            for (int j = 0; j < 4; j++) {
                int n0 = bc * BN + warp_n * 32 + j * 8 + 2 * tig;
                crow[n0]     = acc[i][j][half * 2 + 0] + bias[n0];
                crow[n0 + 1] = acc[i][j][half * 2 + 1] + bias[n0 + 1];
            }
        }
    }
}

// ---------------- bf16 tensor-core flash attention per (b,h) --------------
// M=96 (78 valid), key tile 64, 8 warps 2x4; bf16 m16n8k16 for S and PV.
// Q/K/V tiles are raw bf16 from gmem via cp.async (no conversions in-loop).
#define AT_M   96
#define AT_KN  64
#define QK_PW  36                          // row pitch in u32 words (32 data + 4 pad)
// u32-unit offsets in dynamic smem
#define AOFF_Q   0                         // Qs bf16 [96][72]   -> 3456 u32
#define AOFF_K   3456                      // Ks bf16 [64][72]   -> 2304 u32
#define AOFF_V   5760                      // Vs bf16 [64 d][72] -> 2304 u32
#define AOFF_S   8064                      // Ss fp32 [96][68]   -> 6528
#define AOFF_P   (AOFF_S + 6528)           // Ps bf16 [96][72]   -> 3456 u32
#define AOFF_M   (AOFF_P + 3456)
#define AOFF_L   (AOFF_M + AT_M)
#define AOFF_F   (AOFF_L + AT_M)
#define AT_SMEM_U32 (AOFF_F + AT_M)        // 18336 u32 = 73344 B

__global__ __launch_bounds__(256, 2) void attn_kernel()
{
    extern __shared__ float sm[];
    uint32_t* smu = (uint32_t*)sm;
    uint32_t* Qs_u = smu + AOFF_Q;     // pitch QK_PW
    uint32_t* Ks_u = smu + AOFF_K;     // pitch QK_PW
    uint32_t* Vs_u = smu + AOFF_V;     // pitch QK_PW, rows = d
    float*    Ss   = sm + AOFF_S;      // pitch 68 fp32
    uint32_t* Ps_u = smu + AOFF_P;     // pitch QK_PW
    float* s_m = sm + AOFF_M;
    float* s_l = sm + AOFF_L;
    float* s_f = sm + AOFF_F;

    uint32_t smem_base = (uint32_t)__cvta_generic_to_shared(sm);
    uint32_t kbase = smem_base + AOFF_K * 4;
    uint32_t vbase = smem_base + AOFF_V * 4;

    int bh = blockIdx.x;
    int b = bh / NH, h = bh % NH;
    int t = threadIdx.x;
    int wid = t >> 5, lane = t & 31;
    int warp_m = wid & 1, warp_n = wid >> 1;   // 2 x 4
    int g = lane >> 2, tig = lane & 3;

    const __nv_bfloat16* qsrc = g_Qbf + (size_t)bh * NLOC * HD;
    const __nv_bfloat16* ksrc = g_Kbf + (size_t)bh * SEQ * HD;
    const __nv_bfloat16* vsrc = g_Vbf + (size_t)bh * HD * SEQ_PAD;

    // load Q (raw bf16), zero rows 78..95 ; 96 rows x 8 16B-chunks
    for (int l = t; l < AT_M * 8; l += 256) {
        int r = l >> 3, ch = l & 7;
        uint4 v = make_uint4(0, 0, 0, 0);
        if (r < NLOC) v = *(const uint4*)(qsrc + r * HD + ch * 8);
        *(uint4*)&Qs_u[r * QK_PW + ch * 4] = v;
    }
    if (t < AT_M) { s_m[t] = -1e30f; s_l[t] = 0.f; }

    float acc_o[3][2][4];
#pragma unroll
    for (int i = 0; i < 3; i++)
#pragma unroll
        for (int j = 0; j < 2; j++)
#pragma unroll
            for (int c = 0; c < 4; c++) acc_o[i][j][c] = 0.f;

    const float scale = 0.125f;

    for (int n0 = 0; n0 < SEQ; n0 += AT_KN) {
        __syncthreads();   // Qs ready (1st iter); Ks/Vs/Ps free (later iters)

        // ---- cp.async K tile [64 keys][64 d] and V tile [64 d][64 keys]
        for (int l = t; l < AT_KN * 8; l += 256) {
            int r = l >> 3, ch = l & 7;
            int src = n0 + r; if (src > SEQ - 1) src = SEQ - 1;
            cp16(kbase + (uint32_t)(r * QK_PW * 4 + ch * 16), ksrc + src * HD + ch * 8);
            cp16(vbase + (uint32_t)(r * QK_PW * 4 + ch * 16),
                 vsrc + r * SEQ_PAD + n0 + ch * 8);   // padded rows: always in-bounds, pad=0
        }
        CP_COMMIT();
        CP_WAIT(0);
        __syncthreads();

        // ---- S = Q K^T, bf16 m16n8k16, 4 k-steps
        float acc_s[3][2][4];
#pragma unroll
        for (int i = 0; i < 3; i++)
#pragma unroll
            for (int j = 0; j < 2; j++)
#pragma unroll
                for (int c = 0; c < 4; c++) acc_s[i][j][c] = 0.f;

#pragma unroll
        for (int ks = 0; ks < 4; ks++) {
            int kb = ks * 8;   // u32 words
            uint32_t af[3][4], bf[2][2];
#pragma unroll
            for (int i = 0; i < 3; i++) {
                int r = warp_m * 48 + i * 16 + g;
                af[i][0] = Qs_u[r * QK_PW + kb + tig];
                af[i][1] = Qs_u[(r + 8) * QK_PW + kb + tig];
                af[i][2] = Qs_u[r * QK_PW + kb + 4 + tig];
                af[i][3] = Qs_u[(r + 8) * QK_PW + kb + 4 + tig];
            }
#pragma unroll
            for (int j = 0; j < 2; j++) {
                int cix = warp_n * 16 + j * 8 + g;
                bf[j][0] = Ks_u[cix * QK_PW + kb + tig];
                bf[j][1] = Ks_u[cix * QK_PW + kb + 4 + tig];
            }
#pragma unroll
            for (int i = 0; i < 3; i++)
#pragma unroll
                for (int j = 0; j < 2; j++)
                    MMA_BF16(acc_s[i][j], af[i], bf[j]);
        }

        // ---- write S*scale (fp32) with key mask
#pragma unroll
        for (int i = 0; i < 3; i++) {
            int r0 = warp_m * 48 + i * 16 + g;
#pragma unroll
            for (int j = 0; j < 2; j++) {
                int c0 = warp_n * 16 + j * 8 + 2 * tig;
                bool v0 = (n0 + c0) < SEQ, v1 = (n0 + c0 + 1) < SEQ;
                Ss[r0 * 68 + c0]           = v0 ? acc_s[i][j][0] * scale : -1e30f;
                Ss[r0 * 68 + c0 + 1]       = v1 ? acc_s[i][j][1] * scale : -1e30f;
                Ss[(r0 + 8) * 68 + c0]     = v0 ? acc_s[i][j][2] * scale : -1e30f;
                Ss[(r0 + 8) * 68 + c0 + 1] = v1 ? acc_s[i][j][3] * scale : -1e30f;
            }
        }
        __syncthreads();

        // ---- row softmax -> Ps bf16
        if (t < AT_M) {
            float* row = Ss + t * 68;
            uint32_t* prow = Ps_u + t * QK_PW;
            float mo = s_m[t], mx = mo;
#pragma unroll
            for (int c4 = 0; c4 < AT_KN; c4 += 4) {
                float4 v = *(float4*)(row + c4);
                mx = fmaxf(mx, fmaxf(fmaxf(v.x, v.y), fmaxf(v.z, v.w)));
            }
            float fac = __expf(mo - mx);
            s_f[t] = fac; s_m[t] = mx;
            float sum = 0.f;
#pragma unroll
            for (int c4 = 0; c4 < AT_KN; c4 += 4) {
                float4 v = *(float4*)(row + c4);
                v.x = __expf(v.x - mx); v.y = __expf(v.y - mx);
                v.z = __expf(v.z - mx); v.w = __expf(v.w - mx);
                sum += v.x + v.y + v.z + v.w;
                prow[c4 / 2]     = packbf(v.x, v.y);
                prow[c4 / 2 + 1] = packbf(v.z, v.w);
            }
            s_l[t] = s_l[t] * fac + sum;
        }
        __syncthreads();

        // ---- rescale O, then O += P V (bf16, 4 k-steps over 64 keys)
#pragma unroll
        for (int i = 0; i < 3; i++) {
            int r0 = warp_m * 48 + i * 16 + g;
            float f0 = s_f[r0], f1 = s_f[r0 + 8];
#pragma unroll
            for (int j = 0; j < 2; j++) {
                acc_o[i][j][0] *= f0; acc_o[i][j][1] *= f0;
                acc_o[i][j][2] *= f1; acc_o[i][j][3] *= f1;
            }
        }
#pragma unroll
        for (int ks = 0; ks < 4; ks++) {
            int kb = ks * 8;          // u32 words (keys pair index)
            uint32_t af[3][4], bf[2][2];
#pragma unroll
            for (int i = 0; i < 3; i++) {
                int r = warp_m * 48 + i * 16 + g;
                af[i][0] = Ps_u[r * QK_PW + kb + tig];
                af[i][1] = Ps_u[(r + 8) * QK_PW + kb + tig];
                af[i][2] = Ps_u[r * QK_PW + kb + 4 + tig];
                af[i][3] = Ps_u[(r + 8) * QK_PW + kb + 4 + tig];
            }
#pragma unroll
            for (int j = 0; j < 2; j++) {
                int cix = warp_n * 16 + j * 8 + g;   // output dim d = Vs row
#pragma unroll
                for (int kh = 0; kh < 2; kh++)
                    bf[j][kh] = Vs_u[cix * QK_PW + kb + kh * 4 + tig];
            }
#pragma unroll
            for (int i = 0; i < 3; i++)
#pragma unroll
                for (int j = 0; j < 2; j++)
                    MMA_BF16(acc_o[i][j], af[i], bf[j]);
        }
    }
    __syncthreads();

    // ---- writeout: g_att[b*78 + r][h*64 + c] = O / l  (fp32)
#pragma unroll
    for (int i = 0; i < 3; i++) {
        int r0 = warp_m * 48 + i * 16 + g;
#pragma unroll
        for (int half = 0; half < 2; half++) {
            int r = r0 + half * 8;
            if (r >= NLOC) continue;
            float inv = 1.f / s_l[r];
            float* dst = g_att + ((size_t)(b * NLOC + r)) * CDIM + h * HD;
#pragma unroll
            for (int j = 0; j < 2; j++) {
                int c0 = warp_n * 16 + j * 8 + 2 * tig;
                float2 o;
                o.x = acc_o[i][j][half * 2 + 0] * inv;
                o.y = acc_o[i][j][half * 2 + 1] * inv;
                *(float2*)(dst + c0) = o;
            }
        }
    }
}

// ---------------- launch ---------------------------------------------------
extern "C" void kernel_launch(void* const* d_in, const int* in_sizes, int n_in,
                              void* d_out, int out_size)
{
    const float* x    = (const float*)d_in[0];
    const float* roll = (const float*)d_in[1];
    const float* Wq   = (const float*)d_in[2];
    const float* bq   = (const float*)d_in[3];
    const float* Wkv  = (const float*)d_in[4];
    const float* bkv  = (const float*)d_in[5];
    const float* Wp   = (const float*)d_in[6];
    const float* bp   = (const float*)d_in[7];
    float* out = (float*)d_out;

    const int attn_smem = AT_SMEM_U32 * 4;

    static int s_attr_done = 0;
    if (!s_attr_done) {
        cudaFuncSetAttribute(attn_kernel,
                             cudaFuncAttributeMaxDynamicSharedMemorySize, attn_smem);
        cudaFuncSetAttribute(gemm_bf16<0>,
                             cudaFuncAttributeMaxDynamicSharedMemorySize, BF_SMEM_BYTES);
        cudaFuncSetAttribute(gemm_bf16<1>,
                             cudaFuncAttributeMaxDynamicSharedMemorySize, BF_SMEM_BYTES);
        cudaFuncSetAttribute(gemm_tf32_out,
                             cudaFuncAttributeMaxDynamicSharedMemorySize, G_SMEM_BYTES);
        s_attr_done = 1;
    }

    // resolve transposed-weight symbol addresses
    __nv_bfloat16 *wkv_bt, *wq_bt;
    cudaGetSymbolAddress((void**)&wkv_bt, g_Wkv_bt);
    cudaGetSymbolAddress((void**)&wq_bt,  g_Wq_bt);

    // fused pass-through copy + x->bf16 conversion
    copyconv_x_kernel<<<1024, 256>>>(x, out);

    // weight conversions
    convt_kernel<<<dim3(2 * CDIM / 32, CDIM / 32), dim3(32, 8)>>>(Wkv, wkv_bt, CDIM, 2 * CDIM);
    convt_kernel<<<dim3(CDIM / 32, CDIM / 32), dim3(32, 8)>>>(Wq, wq_bt, CDIM, CDIM);

    // top-k indices per batch
    topk_kernel<<<NB, 1024>>>(roll);

    // KV projection (bf16 + ldmatrix): [50240,768] @ [768,1536] -> g_Kbf/g_Vbf
    {
        int M = NB * SEQ;
        dim3 grid((2 * CDIM) / 128, (M + 127) / 128);
        gemm_bf16<0><<<grid, 256, BF_SMEM_BYTES>>>(bkv);
    }
    // Q projection (bf16, gathered rows): [4992,768] @ [768,768] -> g_Qbf
    {
        int M = NB * NLOC;
        dim3 grid(CDIM / 128, (M + 127) / 128);
        gemm_bf16<1><<<grid, 256, BF_SMEM_BYTES>>>(bq);
    }
    // fused bf16 attention -> g_att
    attn_kernel<<<NB * NH, 256, attn_smem>>>();

    // output projection (tf32) + scatter into out
    {
        int M = NB * NLOC;
        dim3 grid(CDIM / 128, (M + 127) / 128);
        gemm_tf32_out<<<grid, 256, G_SMEM_BYTES>>>(Wp, bp, out);
    }
}